// round 4
// baseline (speedup 1.0000x reference)
#include <cuda_runtime.h>
#include <mma.h>
#include <cstdint>

using namespace nvcuda;

// Problem constants (fixed by the reference)
constexpr int B   = 256;
constexpr int T   = 256;
constexpr int D   = 72;
constexpr int HID = 512;
constexpr int H   = 1024;
constexpr int H3  = 3 * H;
constexpr int P   = 10;       // to_predict
constexpr int BT  = B * T;    // 65536

// ----------------------------------------------------------------------------
// Device scratch
// ----------------------------------------------------------------------------
__device__ float g_buf1  [(size_t)BT * HID];
__device__ float g_latent[(size_t)BT * H];
__device__ float g_xp    [(size_t)BT * H3];
__device__ float g_eout  [(size_t)BT * H];
__device__ float g_hb0   [B * H];
__device__ float g_hb1   [B * H];
__device__ float g_logits[BT];
__device__ float g_wts   [BT];
__device__ float g_hs    [B * H];
__device__ float g_hs2   [B * H];
__device__ float g_p0    [B * D];
__device__ float g_d1    [B * HID];
__device__ float g_dinp  [B * H];
__device__ float g_gi    [B * H3];
__device__ float g_l1    [B * HID];

// ----------------------------------------------------------------------------
// Pipelined tf32 WMMA GEMM v2 (UNCHANGED from round 3 — ~118 TF/s measured)
// C[M,N] = act(A[M,K] * W[N,K]^T + bias); tile 128x128x32, double-buffered.
// ----------------------------------------------------------------------------
#define BM 128
#define BN 128
#define BK 32
constexpr int GLDS = BK + 4;
constexpr int GBUF = (BM + BN) * GLDS;
constexpr int GM_SMEM_BYTES = 2 * GBUF * 4;

__device__ __forceinline__ void gm_load_tiles(
    const float* __restrict__ A, int lda,
    const float* __restrict__ W, int K,
    int bm, int bn, int kk, int tid,
    float4 ra[4], float4 rb[4])
{
#pragma unroll
    for (int i = 0; i < 4; i++) {
        int idx = tid + i * 256;
        int r   = idx >> 3;
        int c4  = (idx & 7) * 4;
        int gk  = kk + c4;
        const float* srcA = A + (size_t)(bm + r) * lda + gk;
        const float* srcB = W + (size_t)(bn + r) * K + gk;
        if (gk + 4 <= K) {
            ra[i] = *reinterpret_cast<const float4*>(srcA);
            rb[i] = *reinterpret_cast<const float4*>(srcB);
        } else {
            ra[i].x = (gk + 0 < K) ? srcA[0] : 0.f;
            ra[i].y = (gk + 1 < K) ? srcA[1] : 0.f;
            ra[i].z = (gk + 2 < K) ? srcA[2] : 0.f;
            ra[i].w = (gk + 3 < K) ? srcA[3] : 0.f;
            rb[i].x = (gk + 0 < K) ? srcB[0] : 0.f;
            rb[i].y = (gk + 1 < K) ? srcB[1] : 0.f;
            rb[i].z = (gk + 2 < K) ? srcB[2] : 0.f;
            rb[i].w = (gk + 3 < K) ? srcB[3] : 0.f;
        }
    }
}

__device__ __forceinline__ void gm_store_tiles(
    float* __restrict__ As, float* __restrict__ Bs, int tid,
    const float4 ra[4], const float4 rb[4])
{
#pragma unroll
    for (int i = 0; i < 4; i++) {
        int idx = tid + i * 256;
        int r   = idx >> 3;
        int c4  = (idx & 7) * 4;
        float* da = As + r * GLDS + c4;
        da[0] = wmma::__float_to_tf32(ra[i].x);
        da[1] = wmma::__float_to_tf32(ra[i].y);
        da[2] = wmma::__float_to_tf32(ra[i].z);
        da[3] = wmma::__float_to_tf32(ra[i].w);
        float* db = Bs + r * GLDS + c4;
        db[0] = wmma::__float_to_tf32(rb[i].x);
        db[1] = wmma::__float_to_tf32(rb[i].y);
        db[2] = wmma::__float_to_tf32(rb[i].z);
        db[3] = wmma::__float_to_tf32(rb[i].w);
    }
}

__global__ void __launch_bounds__(256, 1)
gemm_tf32_v2(const float* __restrict__ A, int lda,
             const float* __restrict__ W,
             const float* __restrict__ bias,
             float* __restrict__ C, int ldc,
             int M, int N, int K, int act)
{
    extern __shared__ float sm[];
    float* Abuf[2] = { sm,               sm + GBUF };
    float* Bbuf[2] = { sm + BM * GLDS,   sm + GBUF + BM * GLDS };
    float* Cs = sm;

    const int bm  = blockIdx.y * BM;
    const int bn  = blockIdx.x * BN;
    const int tid = threadIdx.x;
    const int w   = tid >> 5;
    const int wm  = w & 3;
    const int wn  = w >> 2;

    wmma::fragment<wmma::accumulator, 16, 16, 8, float> c[2][4];
#pragma unroll
    for (int i = 0; i < 2; i++)
#pragma unroll
        for (int j = 0; j < 4; j++)
            wmma::fill_fragment(c[i][j], 0.0f);

    const int niter = (K + BK - 1) / BK;
    float4 ra[4], rb[4];

    gm_load_tiles(A, lda, W, K, bm, bn, 0, tid, ra, rb);
    gm_store_tiles(Abuf[0], Bbuf[0], tid, ra, rb);
    __syncthreads();

    for (int it = 0; it < niter; it++) {
        if (it + 1 < niter)
            gm_load_tiles(A, lda, W, K, bm, bn, (it + 1) * BK, tid, ra, rb);

        const float* As = Abuf[it & 1];
        const float* Bs = Bbuf[it & 1];
#pragma unroll
        for (int ks = 0; ks < 4; ks++) {
            wmma::fragment<wmma::matrix_a, 16, 16, 8, wmma::precision::tf32, wmma::row_major> af[2];
            wmma::fragment<wmma::matrix_b, 16, 16, 8, wmma::precision::tf32, wmma::col_major> bf[4];
#pragma unroll
            for (int i = 0; i < 2; i++)
                wmma::load_matrix_sync(af[i], As + (wm * 32 + i * 16) * GLDS + ks * 8, GLDS);
#pragma unroll
            for (int j = 0; j < 4; j++)
                wmma::load_matrix_sync(bf[j], Bs + (wn * 64 + j * 16) * GLDS + ks * 8, GLDS);
#pragma unroll
            for (int i = 0; i < 2; i++)
#pragma unroll
                for (int j = 0; j < 4; j++)
                    wmma::mma_sync(c[i][j], af[i], bf[j], c[i][j]);
        }

        if (it + 1 < niter)
            gm_store_tiles(Abuf[(it + 1) & 1], Bbuf[(it + 1) & 1], tid, ra, rb);
        __syncthreads();
    }

#pragma unroll
    for (int i = 0; i < 2; i++)
#pragma unroll
        for (int j = 0; j < 4; j++)
            wmma::store_matrix_sync(Cs + (wm * 32 + i * 16) * (BN + 4) + wn * 64 + j * 16,
                                    c[i][j], BN + 4, wmma::mem_row_major);
    __syncthreads();

#pragma unroll
    for (int i = 0; i < 16; i++) {
        int idx4 = tid + i * 256;
        int r    = idx4 >> 5;
        int c4   = (idx4 & 31) * 4;
        float4 v = *reinterpret_cast<const float4*>(Cs + r * (BN + 4) + c4);
        if (bias) {
            float4 bv = *reinterpret_cast<const float4*>(bias + bn + c4);
            v.x += bv.x; v.y += bv.y; v.z += bv.z; v.w += bv.w;
        }
        if (act == 1) {
            v.x = fmaxf(v.x, 0.f); v.y = fmaxf(v.y, 0.f);
            v.z = fmaxf(v.z, 0.f); v.w = fmaxf(v.w, 0.f);
        }
        *reinterpret_cast<float4*>(C + (size_t)(bm + r) * ldc + bn + c4) = v;
    }
}

// ----------------------------------------------------------------------------
// Fused single GRU step (per-launch; replaces persistent loop + grid barrier).
// Grid = 128 CTAs = 2 b-tiles (128 rows) x 64 n-tiles (16 h-cols x 3 gates).
// Weights (48x1024, tf32) in smem; h tile streamed via double-buffered
// 16-wide K chunks (one __syncthreads per chunk, loads overlap MMAs).
// ----------------------------------------------------------------------------
constexpr int S_LDW     = 1028;                 // weight smem ld (pad 4)
constexpr int S_WFLOATS = 48 * S_LDW;           // 49344
constexpr int S_LDA     = 20;                   // A smem ld (16 + pad 4)
constexpr int S_ABUF    = 128 * S_LDA;          // 2560 floats per buffer
constexpr int S_GFLOATS = 3 * 128 * S_LDA;      // 7680 (gate staging, aliases A)
constexpr int S_SMEM_BYTES = (S_WFLOATS + S_GFLOATS) * 4;   // 228096

__device__ __forceinline__ float sigf(float x) { return 1.f / (1.f + expf(-x)); }

__global__ void __launch_bounds__(256, 1)
gru_step(const float* __restrict__ whh, const float* __restrict__ bhh,
         const float* __restrict__ gi, size_t gi_bstride,
         const float* __restrict__ hread, float* __restrict__ hwrite,
         float* __restrict__ eout_t, size_t eout_bstride)
{
    extern __shared__ float smem[];
    float* Wsm   = smem;
    float* Abuf0 = smem + S_WFLOATS;
    float* Abuf1 = Abuf0 + S_ABUF;
    float* Gsm   = Abuf0;              // aliases A buffers (used post-loop)

    const int tid = threadIdx.x;
    const int w   = tid >> 5;
    const int nt  = blockIdx.x & 63;
    const int bt  = blockIdx.x >> 6;
    const int b0  = bt * 128;
    const int n0  = nt * 16;

    // ---- preload weight slab: 48 rows (3 gates x 16 n-cols) x 1024, tf32 ----
    for (int i = tid; i < 48 * 256; i += 256) {
        int r  = i >> 8;
        int c4 = (i & 255) * 4;
        int g  = r >> 4;
        int nr = r & 15;
        const float4 v = *reinterpret_cast<const float4*>(
            whh + (size_t)(g * H + n0 + nr) * H + c4);
        float* dst = Wsm + r * S_LDW + c4;
        dst[0] = wmma::__float_to_tf32(v.x);
        dst[1] = wmma::__float_to_tf32(v.y);
        dst[2] = wmma::__float_to_tf32(v.z);
        dst[3] = wmma::__float_to_tf32(v.w);
    }

    // ---- prologue: h chunk 0 -> Abuf0 ----
    float4 st[2];
#pragma unroll
    for (int i = 0; i < 2; i++) {
        int idx = tid + i * 256;
        int r   = idx >> 2;
        int c4  = (idx & 3) * 4;
        st[i] = *reinterpret_cast<const float4*>(hread + (size_t)(b0 + r) * H + c4);
    }
#pragma unroll
    for (int i = 0; i < 2; i++) {
        int idx = tid + i * 256;
        int r   = idx >> 2;
        int c4  = (idx & 3) * 4;
        float* d = Abuf0 + r * S_LDA + c4;
        d[0] = wmma::__float_to_tf32(st[i].x);
        d[1] = wmma::__float_to_tf32(st[i].y);
        d[2] = wmma::__float_to_tf32(st[i].z);
        d[3] = wmma::__float_to_tf32(st[i].w);
    }
    __syncthreads();   // weights + chunk 0 visible

    wmma::fragment<wmma::accumulator, 16, 16, 8, float> acc[3];
#pragma unroll
    for (int g = 0; g < 3; g++) wmma::fill_fragment(acc[g], 0.0f);

    // ---- main loop: 64 chunks of 16 K, double-buffered ----
    for (int c = 0; c < 64; c++) {
        const int kk = c * 16;
        if (c < 63) {
#pragma unroll
            for (int i = 0; i < 2; i++) {
                int idx = tid + i * 256;
                int r   = idx >> 2;
                int c4  = (idx & 3) * 4;
                st[i] = *reinterpret_cast<const float4*>(
                    hread + (size_t)(b0 + r) * H + kk + 16 + c4);
            }
        }
        const float* As = (c & 1) ? Abuf1 : Abuf0;
#pragma unroll
        for (int ks = 0; ks < 2; ks++) {
            wmma::fragment<wmma::matrix_a, 16, 16, 8, wmma::precision::tf32, wmma::row_major> a;
            wmma::load_matrix_sync(a, As + (w * 16) * S_LDA + ks * 8, S_LDA);
#pragma unroll
            for (int g = 0; g < 3; g++) {
                wmma::fragment<wmma::matrix_b, 16, 16, 8, wmma::precision::tf32, wmma::col_major> b;
                wmma::load_matrix_sync(b, Wsm + (g * 16) * S_LDW + kk + ks * 8, S_LDW);
                wmma::mma_sync(acc[g], a, b, acc[g]);
            }
        }
        if (c < 63) {
            float* Ad = (c & 1) ? Abuf0 : Abuf1;
#pragma unroll
            for (int i = 0; i < 2; i++) {
                int idx = tid + i * 256;
                int r   = idx >> 2;
                int c4  = (idx & 3) * 4;
                float* d = Ad + r * S_LDA + c4;
                d[0] = wmma::__float_to_tf32(st[i].x);
                d[1] = wmma::__float_to_tf32(st[i].y);
                d[2] = wmma::__float_to_tf32(st[i].z);
                d[3] = wmma::__float_to_tf32(st[i].w);
            }
        }
        __syncthreads();
    }

    // ---- epilogue: stage gates, fused GRU math ----
#pragma unroll
    for (int g = 0; g < 3; g++)
        wmma::store_matrix_sync(Gsm + (g * 128 + w * 16) * S_LDA,
                                acc[g], S_LDA, wmma::mem_row_major);
    __syncthreads();

#pragma unroll
    for (int i = 0; i < 8; i++) {
        int e  = tid + i * 256;
        int bl = e >> 4;
        int nl = e & 15;
        int b  = b0 + bl;
        int nc = n0 + nl;
        float hr = Gsm[(0 * 128 + bl) * S_LDA + nl] + bhh[nc];
        float hz = Gsm[(1 * 128 + bl) * S_LDA + nl] + bhh[H + nc];
        float hn = Gsm[(2 * 128 + bl) * S_LDA + nl] + bhh[2 * H + nc];
        const float* gib = gi + (size_t)b * gi_bstride;
        float ir = gib[nc], iz = gib[H + nc], in_ = gib[2 * H + nc];
        float r  = sigf(ir + hr);
        float z  = sigf(iz + hz);
        float nn = tanhf(in_ + r * hn);
        float hv = hread[(size_t)b * H + nc];
        float hnew = (1.f - z) * nn + z * hv;
        hwrite[(size_t)b * H + nc] = hnew;
        if (eout_t) eout_t[(size_t)b * eout_bstride + nc] = hnew;
    }
}

// ----------------------------------------------------------------------------
// Small kernels (unchanged)
// ----------------------------------------------------------------------------
__global__ void logits_kernel(const float* __restrict__ s1,
                              const float* __restrict__ w2,
                              const float* __restrict__ b2,
                              float* __restrict__ logits)
{
    int row  = blockIdx.x * 8 + (threadIdx.x >> 5);
    int lane = threadIdx.x & 31;
    const float* src = s1 + (size_t)row * HID;
    float acc = 0.f;
    for (int k = lane; k < HID; k += 32) acc += src[k] * w2[k];
#pragma unroll
    for (int o = 16; o > 0; o >>= 1) acc += __shfl_xor_sync(0xffffffffu, acc, o);
    if (lane == 0) logits[row] = acc + b2[0];
}

__global__ void softmax_kernel(const float* __restrict__ logits,
                               float* __restrict__ wts)
{
    __shared__ float sdata[T];
    int b = blockIdx.x, t = threadIdx.x;
    float v = logits[b * T + t];
    sdata[t] = v;
    __syncthreads();
    for (int s = T / 2; s > 0; s >>= 1) {
        if (t < s) sdata[t] = fmaxf(sdata[t], sdata[t + s]);
        __syncthreads();
    }
    float mx = sdata[0];
    __syncthreads();
    float e = expf(v - mx);
    sdata[t] = e;
    __syncthreads();
    for (int s = T / 2; s > 0; s >>= 1) {
        if (t < s) sdata[t] += sdata[t + s];
        __syncthreads();
    }
    wts[b * T + t] = e / sdata[0];
}

__global__ void pool_kernel(const float* __restrict__ eout,
                            const float* __restrict__ wts,
                            float* __restrict__ hs,
                            float* __restrict__ rep_out)
{
    __shared__ float w[T];
    int b = blockIdx.x, tid = threadIdx.x;
    w[tid] = wts[b * T + tid];
    __syncthreads();
    for (int h0 = tid; h0 < H; h0 += blockDim.x) {
        const float* base = eout + (size_t)b * T * H + h0;
        float acc = 0.f;
#pragma unroll 4
        for (int t = 0; t < T; t++) acc += w[t] * base[(size_t)t * H];
        hs[b * H + h0] = acc;
        if (rep_out) rep_out[b * H + h0] = acc;
    }
}

__global__ void gather_last(const float* __restrict__ x, float* __restrict__ p0)
{
    int idx = blockIdx.x * blockDim.x + threadIdx.x;
    if (idx >= B * D) return;
    int b = idx / D, dd = idx % D;
    p0[idx] = x[((size_t)b * T + (T - 1)) * D + dd];
}

__global__ void pred_kernel(const float* __restrict__ l1,
                            const float* __restrict__ w,
                            const float* __restrict__ bias,
                            float* __restrict__ out, int ldc)
{
    __shared__ float row[HID];
    int m = blockIdx.x;
    for (int k = threadIdx.x; k < HID; k += blockDim.x)
        row[k] = l1[(size_t)m * HID + k];
    __syncthreads();
    int n = threadIdx.x;
    if (n < D) {
        const float* wr = w + (size_t)n * HID;
        float acc = bias[n];
        for (int k = 0; k < HID; k++) acc += row[k] * wr[k];
        out[(size_t)m * ldc + n] = acc;
    }
}

// ----------------------------------------------------------------------------
// Host driver
// ----------------------------------------------------------------------------
static inline void launch_gemm(const float* A, int lda, const float* W,
                               const float* bias, float* C, int ldc,
                               int M, int N, int K, int act)
{
    dim3 grid(N / BN, M / BM);
    gemm_tf32_v2<<<grid, 256, GM_SMEM_BYTES>>>(A, lda, W, bias, C, ldc, M, N, K, act);
}

extern "C" void kernel_launch(void* const* d_in, const int* in_sizes, int n_in,
                              void* d_out, int out_size)
{
    const float* x       = (const float*)d_in[0];
    const float* p2l_w1  = (const float*)d_in[2];
    const float* p2l_b1  = (const float*)d_in[3];
    const float* p2l_w2  = (const float*)d_in[4];
    const float* p2l_b2  = (const float*)d_in[5];
    const float* enc_wih = (const float*)d_in[6];
    const float* enc_whh = (const float*)d_in[7];
    const float* enc_bih = (const float*)d_in[8];
    const float* enc_bhh = (const float*)d_in[9];
    const float* dec_wih = (const float*)d_in[10];
    const float* dec_whh = (const float*)d_in[11];
    const float* dec_bih = (const float*)d_in[12];
    const float* dec_bhh = (const float*)d_in[13];
    const float* l2p_w1  = (const float*)d_in[14];
    const float* l2p_b1  = (const float*)d_in[15];
    const float* l2p_w2  = (const float*)d_in[16];
    const float* l2p_b2  = (const float*)d_in[17];
    const float* l2s_w1  = (const float*)d_in[18];
    const float* l2s_b1  = (const float*)d_in[19];
    const float* l2s_w2  = (const float*)d_in[20];
    const float* l2s_b2  = (const float*)d_in[21];

    float* out = (float*)d_out;
    const int PREDS = B * P * D;
    float* rep_out = (out_size >= PREDS + B * H) ? (out + PREDS) : nullptr;

    float *p_buf1, *p_latent, *p_xp, *p_eout, *p_hb0, *p_hb1, *p_logits,
          *p_wts, *p_hs, *p_hs2, *p_p0, *p_d1, *p_dinp, *p_gi, *p_l1;
    void* tmp;
#define SYM(dst, sym) cudaGetSymbolAddress(&tmp, sym); dst = (decltype(dst))tmp;
    SYM(p_buf1, g_buf1)   SYM(p_latent, g_latent) SYM(p_xp, g_xp)
    SYM(p_eout, g_eout)   SYM(p_hb0, g_hb0)       SYM(p_hb1, g_hb1)
    SYM(p_logits, g_logits) SYM(p_wts, g_wts)     SYM(p_hs, g_hs)
    SYM(p_hs2, g_hs2)     SYM(p_p0, g_p0)         SYM(p_d1, g_d1)
    SYM(p_dinp, g_dinp)   SYM(p_gi, g_gi)         SYM(p_l1, g_l1)
#undef SYM

    cudaFuncSetAttribute(gru_step, cudaFuncAttributeMaxDynamicSharedMemorySize,
                         S_SMEM_BYTES);
    cudaFuncSetAttribute(gemm_tf32_v2, cudaFuncAttributeMaxDynamicSharedMemorySize,
                         GM_SMEM_BYTES);

    // ---- par2lat(x) ----
    launch_gemm(x, D, p2l_w1, p2l_b1, p_buf1, HID, BT, HID, D, 1);
    launch_gemm(p_buf1, HID, p2l_w2, p2l_b2, p_latent, H, BT, H, HID, 1);

    // ---- xp = latent @ enc_wih^T + enc_bih ----
    launch_gemm(p_latent, H, enc_wih, enc_bih, p_xp, H3, BT, H3, H, 0);

    // ---- encoder recurrence: one fused launch per step ----
    cudaMemsetAsync(p_hb0, 0, (size_t)B * H * sizeof(float));
    {
        float* hr = p_hb0;
        float* hw = p_hb1;
        for (int t = 0; t < T; t++) {
            gru_step<<<128, 256, S_SMEM_BYTES>>>(
                enc_whh, enc_bhh,
                p_xp + (size_t)t * H3, (size_t)T * H3,
                hr, hw,
                p_eout + (size_t)t * H, (size_t)T * H);
            float* t2 = hr; hr = hw; hw = t2;
        }
    }

    // ---- attention pooling ----
    launch_gemm(p_eout, H, l2s_w1, l2s_b1, p_buf1, HID, BT, HID, H, 1);
    logits_kernel<<<BT / 8, 256>>>(p_buf1, l2s_w2, l2s_b2, p_logits);
    softmax_kernel<<<B, T>>>(p_logits, p_wts);
    pool_kernel<<<B, 256>>>(p_eout, p_wts, p_hs, rep_out);

    // ---- autoregressive decode ----
    gather_last<<<(B * D + 255) / 256, 256>>>(x, p_p0);
    float* hs_read  = p_hs;
    float* hs_write = p_hs2;
    for (int s = 0; s < P; s++) {
        const float* pin = (s == 0) ? p_p0 : (out + (size_t)(s - 1) * D);
        int plda = (s == 0) ? D : (P * D);
        launch_gemm(pin, plda, p2l_w1, p2l_b1, p_d1, HID, B, HID, D, 1);
        launch_gemm(p_d1, HID, p2l_w2, p2l_b2, p_dinp, H, B, H, HID, 1);
        launch_gemm(p_dinp, H, dec_wih, dec_bih, p_gi, H3, B, H3, H, 0);
        gru_step<<<128, 256, S_SMEM_BYTES>>>(
            dec_whh, dec_bhh, p_gi, (size_t)H3,
            hs_read, hs_write, nullptr, 0);
        launch_gemm(hs_write, H, l2p_w1, l2p_b1, p_l1, HID, B, HID, H, 1);
        pred_kernel<<<B, 128>>>(p_l1, l2p_w2, l2p_b2,
                                out + (size_t)s * D, P * D);
        float* t2 = hs_read; hs_read = hs_write; hs_write = t2;
    }
}

// round 5
// speedup vs baseline: 1.0231x; 1.0231x over previous
#include <cuda_runtime.h>
#include <mma.h>
#include <cstdint>

using namespace nvcuda;

// Problem constants (fixed by the reference)
constexpr int B   = 256;
constexpr int T   = 256;
constexpr int D   = 72;
constexpr int HID = 512;
constexpr int H   = 1024;
constexpr int H3  = 3 * H;
constexpr int P   = 10;       // to_predict
constexpr int BT  = B * T;    // 65536

// ----------------------------------------------------------------------------
// Device scratch
// ----------------------------------------------------------------------------
__device__ float g_buf1  [(size_t)BT * HID];
__device__ float g_latent[(size_t)BT * H];
__device__ float g_xp    [(size_t)BT * H3];
__device__ float g_eout  [(size_t)BT * H];
__device__ float g_hb0   [B * H];
__device__ float g_hb1   [B * H];
__device__ float g_logits[BT];
__device__ float g_wts   [BT];
__device__ float g_hs    [B * H];
__device__ float g_hs2   [B * H];
__device__ float g_p0    [B * D];
__device__ float g_d1    [B * HID];
__device__ float g_dinp  [B * H];
__device__ float g_gi    [B * H3];
__device__ float g_l1    [B * HID];

// ----------------------------------------------------------------------------
// Pipelined tf32 WMMA GEMM v2 (UNCHANGED — ~118 TF/s measured)
// ----------------------------------------------------------------------------
#define BM 128
#define BN 128
#define BK 32
constexpr int GLDS = BK + 4;
constexpr int GBUF = (BM + BN) * GLDS;
constexpr int GM_SMEM_BYTES = 2 * GBUF * 4;

__device__ __forceinline__ void gm_load_tiles(
    const float* __restrict__ A, int lda,
    const float* __restrict__ W, int K,
    int bm, int bn, int kk, int tid,
    float4 ra[4], float4 rb[4])
{
#pragma unroll
    for (int i = 0; i < 4; i++) {
        int idx = tid + i * 256;
        int r   = idx >> 3;
        int c4  = (idx & 7) * 4;
        int gk  = kk + c4;
        const float* srcA = A + (size_t)(bm + r) * lda + gk;
        const float* srcB = W + (size_t)(bn + r) * K + gk;
        if (gk + 4 <= K) {
            ra[i] = *reinterpret_cast<const float4*>(srcA);
            rb[i] = *reinterpret_cast<const float4*>(srcB);
        } else {
            ra[i].x = (gk + 0 < K) ? srcA[0] : 0.f;
            ra[i].y = (gk + 1 < K) ? srcA[1] : 0.f;
            ra[i].z = (gk + 2 < K) ? srcA[2] : 0.f;
            ra[i].w = (gk + 3 < K) ? srcA[3] : 0.f;
            rb[i].x = (gk + 0 < K) ? srcB[0] : 0.f;
            rb[i].y = (gk + 1 < K) ? srcB[1] : 0.f;
            rb[i].z = (gk + 2 < K) ? srcB[2] : 0.f;
            rb[i].w = (gk + 3 < K) ? srcB[3] : 0.f;
        }
    }
}

__device__ __forceinline__ void gm_store_tiles(
    float* __restrict__ As, float* __restrict__ Bs, int tid,
    const float4 ra[4], const float4 rb[4])
{
#pragma unroll
    for (int i = 0; i < 4; i++) {
        int idx = tid + i * 256;
        int r   = idx >> 3;
        int c4  = (idx & 7) * 4;
        float* da = As + r * GLDS + c4;
        da[0] = wmma::__float_to_tf32(ra[i].x);
        da[1] = wmma::__float_to_tf32(ra[i].y);
        da[2] = wmma::__float_to_tf32(ra[i].z);
        da[3] = wmma::__float_to_tf32(ra[i].w);
        float* db = Bs + r * GLDS + c4;
        db[0] = wmma::__float_to_tf32(rb[i].x);
        db[1] = wmma::__float_to_tf32(rb[i].y);
        db[2] = wmma::__float_to_tf32(rb[i].z);
        db[3] = wmma::__float_to_tf32(rb[i].w);
    }
}

__global__ void __launch_bounds__(256, 1)
gemm_tf32_v2(const float* __restrict__ A, int lda,
             const float* __restrict__ W,
             const float* __restrict__ bias,
             float* __restrict__ C, int ldc,
             int M, int N, int K, int act)
{
    extern __shared__ float sm[];
    float* Abuf[2] = { sm,               sm + GBUF };
    float* Bbuf[2] = { sm + BM * GLDS,   sm + GBUF + BM * GLDS };
    float* Cs = sm;

    const int bm  = blockIdx.y * BM;
    const int bn  = blockIdx.x * BN;
    const int tid = threadIdx.x;
    const int w   = tid >> 5;
    const int wm  = w & 3;
    const int wn  = w >> 2;

    wmma::fragment<wmma::accumulator, 16, 16, 8, float> c[2][4];
#pragma unroll
    for (int i = 0; i < 2; i++)
#pragma unroll
        for (int j = 0; j < 4; j++)
            wmma::fill_fragment(c[i][j], 0.0f);

    const int niter = (K + BK - 1) / BK;
    float4 ra[4], rb[4];

    gm_load_tiles(A, lda, W, K, bm, bn, 0, tid, ra, rb);
    gm_store_tiles(Abuf[0], Bbuf[0], tid, ra, rb);
    __syncthreads();

    for (int it = 0; it < niter; it++) {
        if (it + 1 < niter)
            gm_load_tiles(A, lda, W, K, bm, bn, (it + 1) * BK, tid, ra, rb);

        const float* As = Abuf[it & 1];
        const float* Bs = Bbuf[it & 1];
#pragma unroll
        for (int ks = 0; ks < 4; ks++) {
            wmma::fragment<wmma::matrix_a, 16, 16, 8, wmma::precision::tf32, wmma::row_major> af[2];
            wmma::fragment<wmma::matrix_b, 16, 16, 8, wmma::precision::tf32, wmma::col_major> bf[4];
#pragma unroll
            for (int i = 0; i < 2; i++)
                wmma::load_matrix_sync(af[i], As + (wm * 32 + i * 16) * GLDS + ks * 8, GLDS);
#pragma unroll
            for (int j = 0; j < 4; j++)
                wmma::load_matrix_sync(bf[j], Bs + (wn * 64 + j * 16) * GLDS + ks * 8, GLDS);
#pragma unroll
            for (int i = 0; i < 2; i++)
#pragma unroll
                for (int j = 0; j < 4; j++)
                    wmma::mma_sync(c[i][j], af[i], bf[j], c[i][j]);
        }

        if (it + 1 < niter)
            gm_store_tiles(Abuf[(it + 1) & 1], Bbuf[(it + 1) & 1], tid, ra, rb);
        __syncthreads();
    }

#pragma unroll
    for (int i = 0; i < 2; i++)
#pragma unroll
        for (int j = 0; j < 4; j++)
            wmma::store_matrix_sync(Cs + (wm * 32 + i * 16) * (BN + 4) + wn * 64 + j * 16,
                                    c[i][j], BN + 4, wmma::mem_row_major);
    __syncthreads();

#pragma unroll
    for (int i = 0; i < 16; i++) {
        int idx4 = tid + i * 256;
        int r    = idx4 >> 5;
        int c4   = (idx4 & 31) * 4;
        float4 v = *reinterpret_cast<const float4*>(Cs + r * (BN + 4) + c4);
        if (bias) {
            float4 bv = *reinterpret_cast<const float4*>(bias + bn + c4);
            v.x += bv.x; v.y += bv.y; v.z += bv.z; v.w += bv.w;
        }
        if (act == 1) {
            v.x = fmaxf(v.x, 0.f); v.y = fmaxf(v.y, 0.f);
            v.z = fmaxf(v.z, 0.f); v.w = fmaxf(v.w, 0.f);
        }
        *reinterpret_cast<float4*>(C + (size_t)(bm + r) * ldc + bn + c4) = v;
    }
}

// ----------------------------------------------------------------------------
// Fused single GRU step — EXACT round-2 step body (64-wide K chunks, 16 iters;
// measured 11.6us as the decode instance), stripped of the persistent loop and
// grid barrier. Grid = 128 CTAs = 2 b-tiles x 64 n-tiles (16 h-cols x 3 gates).
// ----------------------------------------------------------------------------
constexpr int RC_BTILE  = 128;
constexpr int RC_NCOLS  = 16;
constexpr int RC_WROWS  = 48;
constexpr int RC_KCH    = 64;
constexpr int RC_LDW    = 1028;
constexpr int RC_LDA    = 68;
constexpr int RC_LDG    = 20;
constexpr int RC_WFLOATS = RC_WROWS * RC_LDW;
constexpr int RC_AFLOATS = RC_BTILE * RC_LDA;
constexpr int RC_SMEM_BYTES = (RC_WFLOATS + RC_AFLOATS) * 4;   // 232192

__device__ __forceinline__ float sigf(float x) { return 1.f / (1.f + expf(-x)); }

__global__ void __launch_bounds__(256, 1)
gru_step(const float* __restrict__ whh, const float* __restrict__ bhh,
         const float* __restrict__ gi, size_t gi_bstride,
         const float* __restrict__ hread, float* __restrict__ hwrite,
         float* __restrict__ eout_t, size_t eout_bstride)
{
    extern __shared__ float smem[];
    float* Wsm = smem;
    float* Asm = smem + RC_WFLOATS;
    float* Gsm = Asm;

    const int tid = threadIdx.x;
    const int w   = tid >> 5;
    const int nt  = blockIdx.x & 63;
    const int bt  = blockIdx.x >> 6;
    const int b0  = bt * RC_BTILE;
    const int n0  = nt * RC_NCOLS;

    // ---- preload weight slab (48 x 1024, tf32) ----
    for (int i = tid; i < RC_WROWS * (H / 4); i += 256) {
        int r  = i >> 8;
        int c4 = (i & 255) * 4;
        int g  = r >> 4;
        int nr = r & 15;
        const float4 v = *reinterpret_cast<const float4*>(
            whh + (size_t)(g * H + n0 + nr) * H + c4);
        float* dst = Wsm + r * RC_LDW + c4;
        dst[0] = wmma::__float_to_tf32(v.x);
        dst[1] = wmma::__float_to_tf32(v.y);
        dst[2] = wmma::__float_to_tf32(v.z);
        dst[3] = wmma::__float_to_tf32(v.w);
    }

    wmma::fragment<wmma::accumulator, 16, 16, 8, float> acc[3];
#pragma unroll
    for (int g = 0; g < 3; g++) wmma::fill_fragment(acc[g], 0.0f);

    for (int kk = 0; kk < H; kk += RC_KCH) {
        __syncthreads();
#pragma unroll
        for (int i = 0; i < 8; i++) {
            int idx = tid + i * 256;
            int r   = idx >> 4;
            int c4  = (idx & 15) * 4;
            const float4 v = *reinterpret_cast<const float4*>(
                hread + (size_t)(b0 + r) * H + kk + c4);
            float* dst = Asm + r * RC_LDA + c4;
            dst[0] = wmma::__float_to_tf32(v.x);
            dst[1] = wmma::__float_to_tf32(v.y);
            dst[2] = wmma::__float_to_tf32(v.z);
            dst[3] = wmma::__float_to_tf32(v.w);
        }
        __syncthreads();

#pragma unroll
        for (int ks = 0; ks < RC_KCH / 8; ks++) {
            wmma::fragment<wmma::matrix_a, 16, 16, 8, wmma::precision::tf32, wmma::row_major> a;
            wmma::load_matrix_sync(a, Asm + (w * 16) * RC_LDA + ks * 8, RC_LDA);
#pragma unroll
            for (int g = 0; g < 3; g++) {
                wmma::fragment<wmma::matrix_b, 16, 16, 8, wmma::precision::tf32, wmma::col_major> b;
                wmma::load_matrix_sync(b, Wsm + (g * 16) * RC_LDW + kk + ks * 8, RC_LDW);
                wmma::mma_sync(acc[g], a, b, acc[g]);
            }
        }
    }

    // ---- epilogue: gates in smem, fused GRU math ----
    __syncthreads();
#pragma unroll
    for (int g = 0; g < 3; g++)
        wmma::store_matrix_sync(Gsm + (g * RC_BTILE + w * 16) * RC_LDG,
                                acc[g], RC_LDG, wmma::mem_row_major);
    __syncthreads();

#pragma unroll
    for (int i = 0; i < 8; i++) {
        int e  = tid + i * 256;
        int bl = e >> 4;
        int nl = e & 15;
        int b  = b0 + bl;
        int nc = n0 + nl;
        float hr = Gsm[(0 * RC_BTILE + bl) * RC_LDG + nl] + bhh[nc];
        float hz = Gsm[(1 * RC_BTILE + bl) * RC_LDG + nl] + bhh[H + nc];
        float hn = Gsm[(2 * RC_BTILE + bl) * RC_LDG + nl] + bhh[2 * H + nc];
        const float* gib = gi + (size_t)b * gi_bstride;
        float ir = gib[nc], iz = gib[H + nc], in_ = gib[2 * H + nc];
        float r  = sigf(ir + hr);
        float z  = sigf(iz + hz);
        float nn = tanhf(in_ + r * hn);
        float hv = hread[(size_t)b * H + nc];
        float hnew = (1.f - z) * nn + z * hv;
        hwrite[(size_t)b * H + nc] = hnew;
        if (eout_t) eout_t[(size_t)b * eout_bstride + nc] = hnew;
    }
}

// ----------------------------------------------------------------------------
// Small kernels (unchanged)
// ----------------------------------------------------------------------------
__global__ void logits_kernel(const float* __restrict__ s1,
                              const float* __restrict__ w2,
                              const float* __restrict__ b2,
                              float* __restrict__ logits)
{
    int row  = blockIdx.x * 8 + (threadIdx.x >> 5);
    int lane = threadIdx.x & 31;
    const float* src = s1 + (size_t)row * HID;
    float acc = 0.f;
    for (int k = lane; k < HID; k += 32) acc += src[k] * w2[k];
#pragma unroll
    for (int o = 16; o > 0; o >>= 1) acc += __shfl_xor_sync(0xffffffffu, acc, o);
    if (lane == 0) logits[row] = acc + b2[0];
}

__global__ void softmax_kernel(const float* __restrict__ logits,
                               float* __restrict__ wts)
{
    __shared__ float sdata[T];
    int b = blockIdx.x, t = threadIdx.x;
    float v = logits[b * T + t];
    sdata[t] = v;
    __syncthreads();
    for (int s = T / 2; s > 0; s >>= 1) {
        if (t < s) sdata[t] = fmaxf(sdata[t], sdata[t + s]);
        __syncthreads();
    }
    float mx = sdata[0];
    __syncthreads();
    float e = expf(v - mx);
    sdata[t] = e;
    __syncthreads();
    for (int s = T / 2; s > 0; s >>= 1) {
        if (t < s) sdata[t] += sdata[t + s];
        __syncthreads();
    }
    wts[b * T + t] = e / sdata[0];
}

__global__ void pool_kernel(const float* __restrict__ eout,
                            const float* __restrict__ wts,
                            float* __restrict__ hs,
                            float* __restrict__ rep_out)
{
    __shared__ float w[T];
    int b = blockIdx.x, tid = threadIdx.x;
    w[tid] = wts[b * T + tid];
    __syncthreads();
    for (int h0 = tid; h0 < H; h0 += blockDim.x) {
        const float* base = eout + (size_t)b * T * H + h0;
        float acc = 0.f;
#pragma unroll 4
        for (int t = 0; t < T; t++) acc += w[t] * base[(size_t)t * H];
        hs[b * H + h0] = acc;
        if (rep_out) rep_out[b * H + h0] = acc;
    }
}

__global__ void gather_last(const float* __restrict__ x, float* __restrict__ p0)
{
    int idx = blockIdx.x * blockDim.x + threadIdx.x;
    if (idx >= B * D) return;
    int b = idx / D, dd = idx % D;
    p0[idx] = x[((size_t)b * T + (T - 1)) * D + dd];
}

__global__ void pred_kernel(const float* __restrict__ l1,
                            const float* __restrict__ w,
                            const float* __restrict__ bias,
                            float* __restrict__ out, int ldc)
{
    __shared__ float row[HID];
    int m = blockIdx.x;
    for (int k = threadIdx.x; k < HID; k += blockDim.x)
        row[k] = l1[(size_t)m * HID + k];
    __syncthreads();
    int n = threadIdx.x;
    if (n < D) {
        const float* wr = w + (size_t)n * HID;
        float acc = bias[n];
        for (int k = 0; k < HID; k++) acc += row[k] * wr[k];
        out[(size_t)m * ldc + n] = acc;
    }
}

// ----------------------------------------------------------------------------
// Host driver
// ----------------------------------------------------------------------------
static inline void launch_gemm(const float* A, int lda, const float* W,
                               const float* bias, float* C, int ldc,
                               int M, int N, int K, int act)
{
    dim3 grid(N / BN, M / BM);
    gemm_tf32_v2<<<grid, 256, GM_SMEM_BYTES>>>(A, lda, W, bias, C, ldc, M, N, K, act);
}

extern "C" void kernel_launch(void* const* d_in, const int* in_sizes, int n_in,
                              void* d_out, int out_size)
{
    const float* x       = (const float*)d_in[0];
    const float* p2l_w1  = (const float*)d_in[2];
    const float* p2l_b1  = (const float*)d_in[3];
    const float* p2l_w2  = (const float*)d_in[4];
    const float* p2l_b2  = (const float*)d_in[5];
    const float* enc_wih = (const float*)d_in[6];
    const float* enc_whh = (const float*)d_in[7];
    const float* enc_bih = (const float*)d_in[8];
    const float* enc_bhh = (const float*)d_in[9];
    const float* dec_wih = (const float*)d_in[10];
    const float* dec_whh = (const float*)d_in[11];
    const float* dec_bih = (const float*)d_in[12];
    const float* dec_bhh = (const float*)d_in[13];
    const float* l2p_w1  = (const float*)d_in[14];
    const float* l2p_b1  = (const float*)d_in[15];
    const float* l2p_w2  = (const float*)d_in[16];
    const float* l2p_b2  = (const float*)d_in[17];
    const float* l2s_w1  = (const float*)d_in[18];
    const float* l2s_b1  = (const float*)d_in[19];
    const float* l2s_w2  = (const float*)d_in[20];
    const float* l2s_b2  = (const float*)d_in[21];

    float* out = (float*)d_out;
    const int PREDS = B * P * D;
    float* rep_out = (out_size >= PREDS + B * H) ? (out + PREDS) : nullptr;

    float *p_buf1, *p_latent, *p_xp, *p_eout, *p_hb0, *p_hb1, *p_logits,
          *p_wts, *p_hs, *p_hs2, *p_p0, *p_d1, *p_dinp, *p_gi, *p_l1;
    void* tmp;
#define SYM(dst, sym) cudaGetSymbolAddress(&tmp, sym); dst = (decltype(dst))tmp;
    SYM(p_buf1, g_buf1)   SYM(p_latent, g_latent) SYM(p_xp, g_xp)
    SYM(p_eout, g_eout)   SYM(p_hb0, g_hb0)       SYM(p_hb1, g_hb1)
    SYM(p_logits, g_logits) SYM(p_wts, g_wts)     SYM(p_hs, g_hs)
    SYM(p_hs2, g_hs2)     SYM(p_p0, g_p0)         SYM(p_d1, g_d1)
    SYM(p_dinp, g_dinp)   SYM(p_gi, g_gi)         SYM(p_l1, g_l1)
#undef SYM

    cudaFuncSetAttribute(gru_step, cudaFuncAttributeMaxDynamicSharedMemorySize,
                         RC_SMEM_BYTES);
    cudaFuncSetAttribute(gemm_tf32_v2, cudaFuncAttributeMaxDynamicSharedMemorySize,
                         GM_SMEM_BYTES);

    // ---- par2lat(x) ----
    launch_gemm(x, D, p2l_w1, p2l_b1, p_buf1, HID, BT, HID, D, 1);
    launch_gemm(p_buf1, HID, p2l_w2, p2l_b2, p_latent, H, BT, H, HID, 1);

    // ---- xp = latent @ enc_wih^T + enc_bih ----
    launch_gemm(p_latent, H, enc_wih, enc_bih, p_xp, H3, BT, H3, H, 0);

    // ---- encoder recurrence: one fused launch per step (round-2 step body) ----
    cudaMemsetAsync(p_hb0, 0, (size_t)B * H * sizeof(float));
    {
        float* hr = p_hb0;
        float* hw = p_hb1;
        for (int t = 0; t < T; t++) {
            gru_step<<<128, 256, RC_SMEM_BYTES>>>(
                enc_whh, enc_bhh,
                p_xp + (size_t)t * H3, (size_t)T * H3,
                hr, hw,
                p_eout + (size_t)t * H, (size_t)T * H);
            float* t2 = hr; hr = hw; hw = t2;
        }
    }

    // ---- attention pooling ----
    launch_gemm(p_eout, H, l2s_w1, l2s_b1, p_buf1, HID, BT, HID, H, 1);
    logits_kernel<<<BT / 8, 256>>>(p_buf1, l2s_w2, l2s_b2, p_logits);
    softmax_kernel<<<B, T>>>(p_logits, p_wts);
    pool_kernel<<<B, 256>>>(p_eout, p_wts, p_hs, rep_out);

    // ---- autoregressive decode ----
    gather_last<<<(B * D + 255) / 256, 256>>>(x, p_p0);
    float* hs_read  = p_hs;
    float* hs_write = p_hs2;
    for (int s = 0; s < P; s++) {
        const float* pin = (s == 0) ? p_p0 : (out + (size_t)(s - 1) * D);
        int plda = (s == 0) ? D : (P * D);
        launch_gemm(pin, plda, p2l_w1, p2l_b1, p_d1, HID, B, HID, D, 1);
        launch_gemm(p_d1, HID, p2l_w2, p2l_b2, p_dinp, H, B, H, HID, 1);
        launch_gemm(p_dinp, H, dec_wih, dec_bih, p_gi, H3, B, H3, H, 0);
        gru_step<<<128, 256, RC_SMEM_BYTES>>>(
            dec_whh, dec_bhh, p_gi, (size_t)H3,
            hs_read, hs_write, nullptr, 0);
        launch_gemm(hs_write, H, l2p_w1, l2p_b1, p_l1, HID, B, HID, H, 1);
        pred_kernel<<<B, 128>>>(p_l1, l2p_w2, l2p_b2,
                                out + (size_t)s * D, P * D);
        float* t2 = hs_read; hs_read = hs_write; hs_write = t2;
    }
}

// round 6
// speedup vs baseline: 1.0251x; 1.0020x over previous
#include <cuda_runtime.h>
#include <mma.h>
#include <cstdint>

using namespace nvcuda;

// Problem constants (fixed by the reference)
constexpr int B   = 256;
constexpr int T   = 256;
constexpr int D   = 72;
constexpr int HID = 512;
constexpr int H   = 1024;
constexpr int H3  = 3 * H;
constexpr int P   = 10;       // to_predict
constexpr int BT  = B * T;    // 65536

// ----------------------------------------------------------------------------
// Device scratch
// ----------------------------------------------------------------------------
__device__ float g_buf1  [(size_t)BT * HID];
__device__ float g_latent[(size_t)BT * H];
__device__ float g_xp    [(size_t)BT * H3];   // [T, B, 3H] (t-major!)
__device__ float g_eout  [(size_t)BT * H];    // [T, B, H]  (t-major!)
__device__ float g_hb0   [B * H];
__device__ float g_hb1   [B * H];
__device__ float g_logits[BT];                // index t*B + b
__device__ float g_wts   [BT];                // index t*B + b
__device__ float g_hs    [B * H];
__device__ float g_hs2   [B * H];
__device__ float g_p0    [B * D];
__device__ float g_d1    [B * HID];
__device__ float g_dinp  [B * H];
__device__ float g_gi    [B * H3];
__device__ float g_l1    [B * HID];

// ----------------------------------------------------------------------------
// Pipelined tf32 WMMA GEMM v2 (+ optional (b,t)->(t,b) output row permute).
// C[M,N] = act(A[M,K] * W[N,K]^T + bias). With permute_bt, output row for
// input row r (= b*256 + t) is t*256 + b — an 8-bit halves swap. Row data
// stays contiguous, so stores remain fully coalesced.
// ----------------------------------------------------------------------------
#define BM 128
#define BN 128
#define BK 32
constexpr int GLDS = BK + 4;
constexpr int GBUF = (BM + BN) * GLDS;
constexpr int GM_SMEM_BYTES = 2 * GBUF * 4;

__device__ __forceinline__ void gm_load_tiles(
    const float* __restrict__ A, int lda,
    const float* __restrict__ W, int K,
    int bm, int bn, int kk, int tid,
    float4 ra[4], float4 rb[4])
{
#pragma unroll
    for (int i = 0; i < 4; i++) {
        int idx = tid + i * 256;
        int r   = idx >> 3;
        int c4  = (idx & 7) * 4;
        int gk  = kk + c4;
        const float* srcA = A + (size_t)(bm + r) * lda + gk;
        const float* srcB = W + (size_t)(bn + r) * K + gk;
        if (gk + 4 <= K) {
            ra[i] = *reinterpret_cast<const float4*>(srcA);
            rb[i] = *reinterpret_cast<const float4*>(srcB);
        } else {
            ra[i].x = (gk + 0 < K) ? srcA[0] : 0.f;
            ra[i].y = (gk + 1 < K) ? srcA[1] : 0.f;
            ra[i].z = (gk + 2 < K) ? srcA[2] : 0.f;
            ra[i].w = (gk + 3 < K) ? srcA[3] : 0.f;
            rb[i].x = (gk + 0 < K) ? srcB[0] : 0.f;
            rb[i].y = (gk + 1 < K) ? srcB[1] : 0.f;
            rb[i].z = (gk + 2 < K) ? srcB[2] : 0.f;
            rb[i].w = (gk + 3 < K) ? srcB[3] : 0.f;
        }
    }
}

__device__ __forceinline__ void gm_store_tiles(
    float* __restrict__ As, float* __restrict__ Bs, int tid,
    const float4 ra[4], const float4 rb[4])
{
#pragma unroll
    for (int i = 0; i < 4; i++) {
        int idx = tid + i * 256;
        int r   = idx >> 3;
        int c4  = (idx & 7) * 4;
        float* da = As + r * GLDS + c4;
        da[0] = wmma::__float_to_tf32(ra[i].x);
        da[1] = wmma::__float_to_tf32(ra[i].y);
        da[2] = wmma::__float_to_tf32(ra[i].z);
        da[3] = wmma::__float_to_tf32(ra[i].w);
        float* db = Bs + r * GLDS + c4;
        db[0] = wmma::__float_to_tf32(rb[i].x);
        db[1] = wmma::__float_to_tf32(rb[i].y);
        db[2] = wmma::__float_to_tf32(rb[i].z);
        db[3] = wmma::__float_to_tf32(rb[i].w);
    }
}

__global__ void __launch_bounds__(256, 1)
gemm_tf32_v2(const float* __restrict__ A, int lda,
             const float* __restrict__ W,
             const float* __restrict__ bias,
             float* __restrict__ C, int ldc,
             int M, int N, int K, int act, int permute_bt)
{
    extern __shared__ float sm[];
    float* Abuf[2] = { sm,               sm + GBUF };
    float* Bbuf[2] = { sm + BM * GLDS,   sm + GBUF + BM * GLDS };
    float* Cs = sm;

    const int bm  = blockIdx.y * BM;
    const int bn  = blockIdx.x * BN;
    const int tid = threadIdx.x;
    const int w   = tid >> 5;
    const int wm  = w & 3;
    const int wn  = w >> 2;

    wmma::fragment<wmma::accumulator, 16, 16, 8, float> c[2][4];
#pragma unroll
    for (int i = 0; i < 2; i++)
#pragma unroll
        for (int j = 0; j < 4; j++)
            wmma::fill_fragment(c[i][j], 0.0f);

    const int niter = (K + BK - 1) / BK;
    float4 ra[4], rb[4];

    gm_load_tiles(A, lda, W, K, bm, bn, 0, tid, ra, rb);
    gm_store_tiles(Abuf[0], Bbuf[0], tid, ra, rb);
    __syncthreads();

    for (int it = 0; it < niter; it++) {
        if (it + 1 < niter)
            gm_load_tiles(A, lda, W, K, bm, bn, (it + 1) * BK, tid, ra, rb);

        const float* As = Abuf[it & 1];
        const float* Bs = Bbuf[it & 1];
#pragma unroll
        for (int ks = 0; ks < 4; ks++) {
            wmma::fragment<wmma::matrix_a, 16, 16, 8, wmma::precision::tf32, wmma::row_major> af[2];
            wmma::fragment<wmma::matrix_b, 16, 16, 8, wmma::precision::tf32, wmma::col_major> bf[4];
#pragma unroll
            for (int i = 0; i < 2; i++)
                wmma::load_matrix_sync(af[i], As + (wm * 32 + i * 16) * GLDS + ks * 8, GLDS);
#pragma unroll
            for (int j = 0; j < 4; j++)
                wmma::load_matrix_sync(bf[j], Bs + (wn * 64 + j * 16) * GLDS + ks * 8, GLDS);
#pragma unroll
            for (int i = 0; i < 2; i++)
#pragma unroll
                for (int j = 0; j < 4; j++)
                    wmma::mma_sync(c[i][j], af[i], bf[j], c[i][j]);
        }

        if (it + 1 < niter)
            gm_store_tiles(Abuf[(it + 1) & 1], Bbuf[(it + 1) & 1], tid, ra, rb);
        __syncthreads();
    }

#pragma unroll
    for (int i = 0; i < 2; i++)
#pragma unroll
        for (int j = 0; j < 4; j++)
            wmma::store_matrix_sync(Cs + (wm * 32 + i * 16) * (BN + 4) + wn * 64 + j * 16,
                                    c[i][j], BN + 4, wmma::mem_row_major);
    __syncthreads();

#pragma unroll
    for (int i = 0; i < 16; i++) {
        int idx4 = tid + i * 256;
        int r    = idx4 >> 5;
        int c4   = (idx4 & 31) * 4;
        float4 v = *reinterpret_cast<const float4*>(Cs + r * (BN + 4) + c4);
        if (bias) {
            float4 bv = *reinterpret_cast<const float4*>(bias + bn + c4);
            v.x += bv.x; v.y += bv.y; v.z += bv.z; v.w += bv.w;
        }
        if (act == 1) {
            v.x = fmaxf(v.x, 0.f); v.y = fmaxf(v.y, 0.f);
            v.z = fmaxf(v.z, 0.f); v.w = fmaxf(v.w, 0.f);
        }
        int gr   = bm + r;
        int orow = permute_bt ? (((gr & 255) << 8) | (gr >> 8)) : gr;
        *reinterpret_cast<float4*>(C + (size_t)orow * ldc + bn + c4) = v;
    }
}

// ----------------------------------------------------------------------------
// Fused single GRU step (round-2 body). With t-major xp/eout, gi and eout
// accesses are contiguous slabs — the access pattern of the 11.6us decode
// instance. Grid = 128 CTAs = 2 b-tiles x 64 n-tiles.
// ----------------------------------------------------------------------------
constexpr int RC_BTILE  = 128;
constexpr int RC_NCOLS  = 16;
constexpr int RC_WROWS  = 48;
constexpr int RC_KCH    = 64;
constexpr int RC_LDW    = 1028;
constexpr int RC_LDA    = 68;
constexpr int RC_LDG    = 20;
constexpr int RC_WFLOATS = RC_WROWS * RC_LDW;
constexpr int RC_AFLOATS = RC_BTILE * RC_LDA;
constexpr int RC_SMEM_BYTES = (RC_WFLOATS + RC_AFLOATS) * 4;   // 232192

__device__ __forceinline__ float sigf(float x) { return 1.f / (1.f + expf(-x)); }

__global__ void __launch_bounds__(256, 1)
gru_step(const float* __restrict__ whh, const float* __restrict__ bhh,
         const float* __restrict__ gi, size_t gi_bstride,
         const float* __restrict__ hread, float* __restrict__ hwrite,
         float* __restrict__ eout_t, size_t eout_bstride)
{
    extern __shared__ float smem[];
    float* Wsm = smem;
    float* Asm = smem + RC_WFLOATS;
    float* Gsm = Asm;

    const int tid = threadIdx.x;
    const int w   = tid >> 5;
    const int nt  = blockIdx.x & 63;
    const int bt  = blockIdx.x >> 6;
    const int b0  = bt * RC_BTILE;
    const int n0  = nt * RC_NCOLS;

    // ---- preload weight slab (48 x 1024, tf32) ----
    for (int i = tid; i < RC_WROWS * (H / 4); i += 256) {
        int r  = i >> 8;
        int c4 = (i & 255) * 4;
        int g  = r >> 4;
        int nr = r & 15;
        const float4 v = *reinterpret_cast<const float4*>(
            whh + (size_t)(g * H + n0 + nr) * H + c4);
        float* dst = Wsm + r * RC_LDW + c4;
        dst[0] = wmma::__float_to_tf32(v.x);
        dst[1] = wmma::__float_to_tf32(v.y);
        dst[2] = wmma::__float_to_tf32(v.z);
        dst[3] = wmma::__float_to_tf32(v.w);
    }

    wmma::fragment<wmma::accumulator, 16, 16, 8, float> acc[3];
#pragma unroll
    for (int g = 0; g < 3; g++) wmma::fill_fragment(acc[g], 0.0f);

    for (int kk = 0; kk < H; kk += RC_KCH) {
        __syncthreads();
#pragma unroll
        for (int i = 0; i < 8; i++) {
            int idx = tid + i * 256;
            int r   = idx >> 4;
            int c4  = (idx & 15) * 4;
            const float4 v = *reinterpret_cast<const float4*>(
                hread + (size_t)(b0 + r) * H + kk + c4);
            float* dst = Asm + r * RC_LDA + c4;
            dst[0] = wmma::__float_to_tf32(v.x);
            dst[1] = wmma::__float_to_tf32(v.y);
            dst[2] = wmma::__float_to_tf32(v.z);
            dst[3] = wmma::__float_to_tf32(v.w);
        }
        __syncthreads();

#pragma unroll
        for (int ks = 0; ks < RC_KCH / 8; ks++) {
            wmma::fragment<wmma::matrix_a, 16, 16, 8, wmma::precision::tf32, wmma::row_major> a;
            wmma::load_matrix_sync(a, Asm + (w * 16) * RC_LDA + ks * 8, RC_LDA);
#pragma unroll
            for (int g = 0; g < 3; g++) {
                wmma::fragment<wmma::matrix_b, 16, 16, 8, wmma::precision::tf32, wmma::col_major> b;
                wmma::load_matrix_sync(b, Wsm + (g * 16) * RC_LDW + kk + ks * 8, RC_LDW);
                wmma::mma_sync(acc[g], a, b, acc[g]);
            }
        }
    }

    // ---- epilogue: gates in smem, fused GRU math ----
    __syncthreads();
#pragma unroll
    for (int g = 0; g < 3; g++)
        wmma::store_matrix_sync(Gsm + (g * RC_BTILE + w * 16) * RC_LDG,
                                acc[g], RC_LDG, wmma::mem_row_major);
    __syncthreads();

#pragma unroll
    for (int i = 0; i < 8; i++) {
        int e  = tid + i * 256;
        int bl = e >> 4;
        int nl = e & 15;
        int b  = b0 + bl;
        int nc = n0 + nl;
        float hr = Gsm[(0 * RC_BTILE + bl) * RC_LDG + nl] + bhh[nc];
        float hz = Gsm[(1 * RC_BTILE + bl) * RC_LDG + nl] + bhh[H + nc];
        float hn = Gsm[(2 * RC_BTILE + bl) * RC_LDG + nl] + bhh[2 * H + nc];
        const float* gib = gi + (size_t)b * gi_bstride;
        float ir = gib[nc], iz = gib[H + nc], in_ = gib[2 * H + nc];
        float r  = sigf(ir + hr);
        float z  = sigf(iz + hz);
        float nn = tanhf(in_ + r * hn);
        float hv = hread[(size_t)b * H + nc];
        float hnew = (1.f - z) * nn + z * hv;
        hwrite[(size_t)b * H + nc] = hnew;
        if (eout_t) eout_t[(size_t)b * eout_bstride + nc] = hnew;
    }
}

// ----------------------------------------------------------------------------
// Small kernels (indices adapted for t-major logits/wts/eout)
// ----------------------------------------------------------------------------
__global__ void logits_kernel(const float* __restrict__ s1,
                              const float* __restrict__ w2,
                              const float* __restrict__ b2,
                              float* __restrict__ logits)
{
    int row  = blockIdx.x * 8 + (threadIdx.x >> 5);
    int lane = threadIdx.x & 31;
    const float* src = s1 + (size_t)row * HID;
    float acc = 0.f;
    for (int k = lane; k < HID; k += 32) acc += src[k] * w2[k];
#pragma unroll
    for (int o = 16; o > 0; o >>= 1) acc += __shfl_xor_sync(0xffffffffu, acc, o);
    if (lane == 0) logits[row] = acc + b2[0];
}

// logits/wts are indexed [t*B + b]; one block per b, threads over t.
__global__ void softmax_kernel(const float* __restrict__ logits,
                               float* __restrict__ wts)
{
    __shared__ float sdata[T];
    int b = blockIdx.x, t = threadIdx.x;
    float v = logits[t * B + b];
    sdata[t] = v;
    __syncthreads();
    for (int s = T / 2; s > 0; s >>= 1) {
        if (t < s) sdata[t] = fmaxf(sdata[t], sdata[t + s]);
        __syncthreads();
    }
    float mx = sdata[0];
    __syncthreads();
    float e = expf(v - mx);
    sdata[t] = e;
    __syncthreads();
    for (int s = T / 2; s > 0; s >>= 1) {
        if (t < s) sdata[t] += sdata[t + s];
        __syncthreads();
    }
    wts[t * B + b] = e / sdata[0];
}

// eout is [T, B, H]; Rep[b,h] = sum_t wts[t*B+b] * eout[t,b,h]
__global__ void pool_kernel(const float* __restrict__ eout,
                            const float* __restrict__ wts,
                            float* __restrict__ hs,
                            float* __restrict__ rep_out)
{
    __shared__ float w[T];
    int b = blockIdx.x, tid = threadIdx.x;
    w[tid] = wts[tid * B + b];
    __syncthreads();
    for (int h0 = tid; h0 < H; h0 += blockDim.x) {
        const float* base = eout + (size_t)b * H + h0;
        float acc = 0.f;
#pragma unroll 4
        for (int t = 0; t < T; t++) acc += w[t] * base[(size_t)t * B * H];
        hs[b * H + h0] = acc;
        if (rep_out) rep_out[b * H + h0] = acc;
    }
}

__global__ void gather_last(const float* __restrict__ x, float* __restrict__ p0)
{
    int idx = blockIdx.x * blockDim.x + threadIdx.x;
    if (idx >= B * D) return;
    int b = idx / D, dd = idx % D;
    p0[idx] = x[((size_t)b * T + (T - 1)) * D + dd];
}

__global__ void pred_kernel(const float* __restrict__ l1,
                            const float* __restrict__ w,
                            const float* __restrict__ bias,
                            float* __restrict__ out, int ldc)
{
    __shared__ float row[HID];
    int m = blockIdx.x;
    for (int k = threadIdx.x; k < HID; k += blockDim.x)
        row[k] = l1[(size_t)m * HID + k];
    __syncthreads();
    int n = threadIdx.x;
    if (n < D) {
        const float* wr = w + (size_t)n * HID;
        float acc = bias[n];
        for (int k = 0; k < HID; k++) acc += row[k] * wr[k];
        out[(size_t)m * ldc + n] = acc;
    }
}

// ----------------------------------------------------------------------------
// Host driver
// ----------------------------------------------------------------------------
static inline void launch_gemm(const float* A, int lda, const float* W,
                               const float* bias, float* C, int ldc,
                               int M, int N, int K, int act, int permute_bt = 0)
{
    dim3 grid(N / BN, M / BM);
    gemm_tf32_v2<<<grid, 256, GM_SMEM_BYTES>>>(A, lda, W, bias, C, ldc, M, N, K,
                                               act, permute_bt);
}

extern "C" void kernel_launch(void* const* d_in, const int* in_sizes, int n_in,
                              void* d_out, int out_size)
{
    const float* x       = (const float*)d_in[0];
    const float* p2l_w1  = (const float*)d_in[2];
    const float* p2l_b1  = (const float*)d_in[3];
    const float* p2l_w2  = (const float*)d_in[4];
    const float* p2l_b2  = (const float*)d_in[5];
    const float* enc_wih = (const float*)d_in[6];
    const float* enc_whh = (const float*)d_in[7];
    const float* enc_bih = (const float*)d_in[8];
    const float* enc_bhh = (const float*)d_in[9];
    const float* dec_wih = (const float*)d_in[10];
    const float* dec_whh = (const float*)d_in[11];
    const float* dec_bih = (const float*)d_in[12];
    const float* dec_bhh = (const float*)d_in[13];
    const float* l2p_w1  = (const float*)d_in[14];
    const float* l2p_b1  = (const float*)d_in[15];
    const float* l2p_w2  = (const float*)d_in[16];
    const float* l2p_b2  = (const float*)d_in[17];
    const float* l2s_w1  = (const float*)d_in[18];
    const float* l2s_b1  = (const float*)d_in[19];
    const float* l2s_w2  = (const float*)d_in[20];
    const float* l2s_b2  = (const float*)d_in[21];

    float* out = (float*)d_out;
    const int PREDS = B * P * D;
    float* rep_out = (out_size >= PREDS + B * H) ? (out + PREDS) : nullptr;

    float *p_buf1, *p_latent, *p_xp, *p_eout, *p_hb0, *p_hb1, *p_logits,
          *p_wts, *p_hs, *p_hs2, *p_p0, *p_d1, *p_dinp, *p_gi, *p_l1;
    void* tmp;
#define SYM(dst, sym) cudaGetSymbolAddress(&tmp, sym); dst = (decltype(dst))tmp;
    SYM(p_buf1, g_buf1)   SYM(p_latent, g_latent) SYM(p_xp, g_xp)
    SYM(p_eout, g_eout)   SYM(p_hb0, g_hb0)       SYM(p_hb1, g_hb1)
    SYM(p_logits, g_logits) SYM(p_wts, g_wts)     SYM(p_hs, g_hs)
    SYM(p_hs2, g_hs2)     SYM(p_p0, g_p0)         SYM(p_d1, g_d1)
    SYM(p_dinp, g_dinp)   SYM(p_gi, g_gi)         SYM(p_l1, g_l1)
#undef SYM

    cudaFuncSetAttribute(gru_step, cudaFuncAttributeMaxDynamicSharedMemorySize,
                         RC_SMEM_BYTES);
    cudaFuncSetAttribute(gemm_tf32_v2, cudaFuncAttributeMaxDynamicSharedMemorySize,
                         GM_SMEM_BYTES);

    // ---- par2lat(x) ----
    launch_gemm(x, D, p2l_w1, p2l_b1, p_buf1, HID, BT, HID, D, 1);
    launch_gemm(p_buf1, HID, p2l_w2, p2l_b2, p_latent, H, BT, H, HID, 1);

    // ---- xp = latent @ enc_wih^T + enc_bih, stored t-major [T, B, 3H] ----
    launch_gemm(p_latent, H, enc_wih, enc_bih, p_xp, H3, BT, H3, H, 0, 1);

    // ---- encoder recurrence: one fused launch per step ----
    cudaMemsetAsync(p_hb0, 0, (size_t)B * H * sizeof(float));
    {
        float* hr = p_hb0;
        float* hw = p_hb1;
        for (int t = 0; t < T; t++) {
            gru_step<<<128, 256, RC_SMEM_BYTES>>>(
                enc_whh, enc_bhh,
                p_xp + (size_t)t * B * H3, (size_t)H3,
                hr, hw,
                p_eout + (size_t)t * B * H, (size_t)H);
            float* t2 = hr; hr = hw; hw = t2;
        }
    }

    // ---- attention pooling (rows in (t,b) order) ----
    launch_gemm(p_eout, H, l2s_w1, l2s_b1, p_buf1, HID, BT, HID, H, 1);
    logits_kernel<<<BT / 8, 256>>>(p_buf1, l2s_w2, l2s_b2, p_logits);
    softmax_kernel<<<B, T>>>(p_logits, p_wts);
    pool_kernel<<<B, 256>>>(p_eout, p_wts, p_hs, rep_out);

    // ---- autoregressive decode ----
    gather_last<<<(B * D + 255) / 256, 256>>>(x, p_p0);
    float* hs_read  = p_hs;
    float* hs_write = p_hs2;
    for (int s = 0; s < P; s++) {
        const float* pin = (s == 0) ? p_p0 : (out + (size_t)(s - 1) * D);
        int plda = (s == 0) ? D : (P * D);
        launch_gemm(pin, plda, p2l_w1, p2l_b1, p_d1, HID, B, HID, D, 1);
        launch_gemm(p_d1, HID, p2l_w2, p2l_b2, p_dinp, H, B, H, HID, 1);
        launch_gemm(p_dinp, H, dec_wih, dec_bih, p_gi, H3, B, H3, H, 0);
        gru_step<<<128, 256, RC_SMEM_BYTES>>>(
            dec_whh, dec_bhh, p_gi, (size_t)H3,
            hs_read, hs_write, nullptr, 0);
        launch_gemm(hs_write, H, l2p_w1, l2p_b1, p_l1, HID, B, HID, H, 1);
        pred_kernel<<<B, 128>>>(p_l1, l2p_w2, l2p_b2,
                                out + (size_t)s * D, P * D);
        float* t2 = hs_read; hs_read = hs_write; hs_write = t2;
    }
}

// round 7
// speedup vs baseline: 1.1134x; 1.0861x over previous
#include <cuda_runtime.h>
#include <mma.h>
#include <cstdint>

using namespace nvcuda;

// Problem constants (fixed by the reference)
constexpr int B   = 256;
constexpr int T   = 256;
constexpr int D   = 72;
constexpr int HID = 512;
constexpr int H   = 1024;
constexpr int H3  = 3 * H;
constexpr int P   = 10;       // to_predict
constexpr int BT  = B * T;    // 65536

// ----------------------------------------------------------------------------
// Device scratch
// ----------------------------------------------------------------------------
__device__ float g_buf1  [(size_t)BT * HID];
__device__ float g_latent[(size_t)BT * H];
__device__ float g_xp    [(size_t)BT * H3];   // [T, B, 3H] (t-major)
__device__ float g_eout  [(size_t)BT * H];    // [T, B, H]  (t-major)
__device__ float g_hb0   [B * H];
__device__ float g_hb1   [B * H];
__device__ float g_logits[BT];                // index t*B + b
__device__ float g_wts   [BT];                // index t*B + b
__device__ float g_hs    [B * H];
__device__ float g_hs2   [B * H];
__device__ float g_p0    [B * D];
__device__ float g_d1    [B * HID];
__device__ float g_dinp  [B * H];
__device__ float g_gi    [B * H3];
__device__ float g_l1    [B * HID];

// ----------------------------------------------------------------------------
// Pipelined tf32 WMMA GEMM v2 (+ optional (b,t)->(t,b) output row permute).
// UNCHANGED (proven).
// ----------------------------------------------------------------------------
#define BM 128
#define BN 128
#define BK 32
constexpr int GLDS = BK + 4;
constexpr int GBUF = (BM + BN) * GLDS;
constexpr int GM_SMEM_BYTES = 2 * GBUF * 4;

__device__ __forceinline__ void gm_load_tiles(
    const float* __restrict__ A, int lda,
    const float* __restrict__ W, int K,
    int bm, int bn, int kk, int tid,
    float4 ra[4], float4 rb[4])
{
#pragma unroll
    for (int i = 0; i < 4; i++) {
        int idx = tid + i * 256;
        int r   = idx >> 3;
        int c4  = (idx & 7) * 4;
        int gk  = kk + c4;
        const float* srcA = A + (size_t)(bm + r) * lda + gk;
        const float* srcB = W + (size_t)(bn + r) * K + gk;
        if (gk + 4 <= K) {
            ra[i] = *reinterpret_cast<const float4*>(srcA);
            rb[i] = *reinterpret_cast<const float4*>(srcB);
        } else {
            ra[i].x = (gk + 0 < K) ? srcA[0] : 0.f;
            ra[i].y = (gk + 1 < K) ? srcA[1] : 0.f;
            ra[i].z = (gk + 2 < K) ? srcA[2] : 0.f;
            ra[i].w = (gk + 3 < K) ? srcA[3] : 0.f;
            rb[i].x = (gk + 0 < K) ? srcB[0] : 0.f;
            rb[i].y = (gk + 1 < K) ? srcB[1] : 0.f;
            rb[i].z = (gk + 2 < K) ? srcB[2] : 0.f;
            rb[i].w = (gk + 3 < K) ? srcB[3] : 0.f;
        }
    }
}

__device__ __forceinline__ void gm_store_tiles(
    float* __restrict__ As, float* __restrict__ Bs, int tid,
    const float4 ra[4], const float4 rb[4])
{
#pragma unroll
    for (int i = 0; i < 4; i++) {
        int idx = tid + i * 256;
        int r   = idx >> 3;
        int c4  = (idx & 7) * 4;
        float* da = As + r * GLDS + c4;
        da[0] = wmma::__float_to_tf32(ra[i].x);
        da[1] = wmma::__float_to_tf32(ra[i].y);
        da[2] = wmma::__float_to_tf32(ra[i].z);
        da[3] = wmma::__float_to_tf32(ra[i].w);
        float* db = Bs + r * GLDS + c4;
        db[0] = wmma::__float_to_tf32(rb[i].x);
        db[1] = wmma::__float_to_tf32(rb[i].y);
        db[2] = wmma::__float_to_tf32(rb[i].z);
        db[3] = wmma::__float_to_tf32(rb[i].w);
    }
}

__global__ void __launch_bounds__(256, 1)
gemm_tf32_v2(const float* __restrict__ A, int lda,
             const float* __restrict__ W,
             const float* __restrict__ bias,
             float* __restrict__ C, int ldc,
             int M, int N, int K, int act, int permute_bt)
{
    extern __shared__ float sm[];
    float* Abuf[2] = { sm,               sm + GBUF };
    float* Bbuf[2] = { sm + BM * GLDS,   sm + GBUF + BM * GLDS };
    float* Cs = sm;

    const int bm  = blockIdx.y * BM;
    const int bn  = blockIdx.x * BN;
    const int tid = threadIdx.x;
    const int w   = tid >> 5;
    const int wm  = w & 3;
    const int wn  = w >> 2;

    wmma::fragment<wmma::accumulator, 16, 16, 8, float> c[2][4];
#pragma unroll
    for (int i = 0; i < 2; i++)
#pragma unroll
        for (int j = 0; j < 4; j++)
            wmma::fill_fragment(c[i][j], 0.0f);

    const int niter = (K + BK - 1) / BK;
    float4 ra[4], rb[4];

    gm_load_tiles(A, lda, W, K, bm, bn, 0, tid, ra, rb);
    gm_store_tiles(Abuf[0], Bbuf[0], tid, ra, rb);
    __syncthreads();

    for (int it = 0; it < niter; it++) {
        if (it + 1 < niter)
            gm_load_tiles(A, lda, W, K, bm, bn, (it + 1) * BK, tid, ra, rb);

        const float* As = Abuf[it & 1];
        const float* Bs = Bbuf[it & 1];
#pragma unroll
        for (int ks = 0; ks < 4; ks++) {
            wmma::fragment<wmma::matrix_a, 16, 16, 8, wmma::precision::tf32, wmma::row_major> af[2];
            wmma::fragment<wmma::matrix_b, 16, 16, 8, wmma::precision::tf32, wmma::col_major> bf[4];
#pragma unroll
            for (int i = 0; i < 2; i++)
                wmma::load_matrix_sync(af[i], As + (wm * 32 + i * 16) * GLDS + ks * 8, GLDS);
#pragma unroll
            for (int j = 0; j < 4; j++)
                wmma::load_matrix_sync(bf[j], Bs + (wn * 64 + j * 16) * GLDS + ks * 8, GLDS);
#pragma unroll
            for (int i = 0; i < 2; i++)
#pragma unroll
                for (int j = 0; j < 4; j++)
                    wmma::mma_sync(c[i][j], af[i], bf[j], c[i][j]);
        }

        if (it + 1 < niter)
            gm_store_tiles(Abuf[(it + 1) & 1], Bbuf[(it + 1) & 1], tid, ra, rb);
        __syncthreads();
    }

#pragma unroll
    for (int i = 0; i < 2; i++)
#pragma unroll
        for (int j = 0; j < 4; j++)
            wmma::store_matrix_sync(Cs + (wm * 32 + i * 16) * (BN + 4) + wn * 64 + j * 16,
                                    c[i][j], BN + 4, wmma::mem_row_major);
    __syncthreads();

#pragma unroll
    for (int i = 0; i < 16; i++) {
        int idx4 = tid + i * 256;
        int r    = idx4 >> 5;
        int c4   = (idx4 & 31) * 4;
        float4 v = *reinterpret_cast<const float4*>(Cs + r * (BN + 4) + c4);
        if (bias) {
            float4 bv = *reinterpret_cast<const float4*>(bias + bn + c4);
            v.x += bv.x; v.y += bv.y; v.z += bv.z; v.w += bv.w;
        }
        if (act == 1) {
            v.x = fmaxf(v.x, 0.f); v.y = fmaxf(v.y, 0.f);
            v.z = fmaxf(v.z, 0.f); v.w = fmaxf(v.w, 0.f);
        }
        int gr   = bm + r;
        int orow = permute_bt ? (((gr & 255) << 8) | (gr >> 8)) : gr;
        *reinterpret_cast<float4*>(C + (size_t)orow * ldc + bn + c4) = v;
    }
}

// ----------------------------------------------------------------------------
// Fused single GRU step v3: 512 threads, warp-group K-split.
// Grid = 128 CTAs = 2 b-tiles x 64 n-tiles. Warps 0-7 accumulate K[0:512),
// warps 8-15 K[512:1024), each group over 32 chunks of 16 K with register
// prefetch; partials combined via smem fragment-add. Weight slab 48x1024
// (tf32) shared by both groups in smem.
// ----------------------------------------------------------------------------
constexpr int RC_LDW     = 1028;
constexpr int RC_WFLOATS = 48 * RC_LDW;          // 49344 floats (197376 B)
constexpr int RC_LDA     = 20;
constexpr int RC_ABUF    = 128 * RC_LDA;         // 2560 floats per group buffer
constexpr int RC_GFLOATS = 3 * 128 * RC_LDA;     // 7680 floats (gate staging)
constexpr int RC_SMEM_BYTES = (RC_WFLOATS + RC_GFLOATS) * 4;  // 228096 B

__device__ __forceinline__ float sigf(float x) { return 1.f / (1.f + expf(-x)); }

__global__ void __launch_bounds__(512, 1)
gru_step(const float* __restrict__ whh, const float* __restrict__ bhh,
         const float* __restrict__ gi, size_t gi_bstride,
         const float* __restrict__ hread, float* __restrict__ hwrite,
         float* __restrict__ eout_t, size_t eout_bstride)
{
    extern __shared__ float smem[];
    float* Wsm  = smem;
    float* Aall = smem + RC_WFLOATS;   // 7680 floats; group bufs at 0 / RC_ABUF
    float* Gsm  = Aall;                // gate staging aliases A region

    const int tid = threadIdx.x;
    const int w   = tid >> 5;          // 0..15
    const int grp = w >> 3;            // 0 | 1  (K half)
    const int wm  = w & 7;             // m-fragment 0..7 (16 rows each)
    const int gt  = tid & 255;         // thread index within group
    const int nt  = blockIdx.x & 63;
    const int bt  = blockIdx.x >> 6;
    const int b0  = bt * 128;
    const int n0  = nt * 16;
    const int kbase = grp * 512;

    float* Ag = Aall + grp * RC_ABUF;

    // ---- preload weight slab (48 x 1024, tf32), all 512 threads ----
    for (int i = tid; i < 48 * 256; i += 512) {
        int r  = i >> 8;
        int c4 = (i & 255) * 4;
        int g  = r >> 4;
        int nr = r & 15;
        const float4 v = *reinterpret_cast<const float4*>(
            whh + (size_t)(g * H + n0 + nr) * H + c4);
        float* dst = Wsm + r * RC_LDW + c4;
        dst[0] = wmma::__float_to_tf32(v.x);
        dst[1] = wmma::__float_to_tf32(v.y);
        dst[2] = wmma::__float_to_tf32(v.z);
        dst[3] = wmma::__float_to_tf32(v.w);
    }

    // ---- prologue: chunk 0 of this group's K half ----
    float4 pf[2];
#pragma unroll
    for (int i = 0; i < 2; i++) {
        int idx = gt + i * 256;
        int r   = idx >> 2;
        int c4  = (idx & 3) * 4;
        pf[i] = *reinterpret_cast<const float4*>(
            hread + (size_t)(b0 + r) * H + kbase + c4);
    }
#pragma unroll
    for (int i = 0; i < 2; i++) {
        int idx = gt + i * 256;
        int r   = idx >> 2;
        int c4  = (idx & 3) * 4;
        float* d = Ag + r * RC_LDA + c4;
        d[0] = wmma::__float_to_tf32(pf[i].x);
        d[1] = wmma::__float_to_tf32(pf[i].y);
        d[2] = wmma::__float_to_tf32(pf[i].z);
        d[3] = wmma::__float_to_tf32(pf[i].w);
    }
    __syncthreads();

    wmma::fragment<wmma::accumulator, 16, 16, 8, float> acc[3];
#pragma unroll
    for (int g = 0; g < 3; g++) wmma::fill_fragment(acc[g], 0.0f);

    // ---- main loop: 32 chunks of 16 K per group, register prefetch ----
    for (int c = 0; c < 32; c++) {
        const int kk = kbase + c * 16;
        if (c < 31) {
#pragma unroll
            for (int i = 0; i < 2; i++) {
                int idx = gt + i * 256;
                int r   = idx >> 2;
                int c4  = (idx & 3) * 4;
                pf[i] = *reinterpret_cast<const float4*>(
                    hread + (size_t)(b0 + r) * H + kk + 16 + c4);
            }
        }
#pragma unroll
        for (int ks = 0; ks < 2; ks++) {
            wmma::fragment<wmma::matrix_a, 16, 16, 8, wmma::precision::tf32, wmma::row_major> a;
            wmma::load_matrix_sync(a, Ag + (wm * 16) * RC_LDA + ks * 8, RC_LDA);
#pragma unroll
            for (int g = 0; g < 3; g++) {
                wmma::fragment<wmma::matrix_b, 16, 16, 8, wmma::precision::tf32, wmma::col_major> b;
                wmma::load_matrix_sync(b, Wsm + (g * 16) * RC_LDW + kk + ks * 8, RC_LDW);
                wmma::mma_sync(acc[g], a, b, acc[g]);
            }
        }
        __syncthreads();
        if (c < 31) {
#pragma unroll
            for (int i = 0; i < 2; i++) {
                int idx = gt + i * 256;
                int r   = idx >> 2;
                int c4  = (idx & 3) * 4;
                float* d = Ag + r * RC_LDA + c4;
                d[0] = wmma::__float_to_tf32(pf[i].x);
                d[1] = wmma::__float_to_tf32(pf[i].y);
                d[2] = wmma::__float_to_tf32(pf[i].z);
                d[3] = wmma::__float_to_tf32(pf[i].w);
            }
        }
        __syncthreads();
    }

    // ---- combine K halves: group1 stores, group0 adds ----
    if (grp == 1) {
#pragma unroll
        for (int g = 0; g < 3; g++)
            wmma::store_matrix_sync(Gsm + (g * 128 + wm * 16) * RC_LDA,
                                    acc[g], RC_LDA, wmma::mem_row_major);
    }
    __syncthreads();
    if (grp == 0) {
#pragma unroll
        for (int g = 0; g < 3; g++) {
            wmma::fragment<wmma::accumulator, 16, 16, 8, float> tmp;
            wmma::load_matrix_sync(tmp, Gsm + (g * 128 + wm * 16) * RC_LDA,
                                   RC_LDA, wmma::mem_row_major);
#pragma unroll
            for (int e = 0; e < tmp.num_elements; e++)
                acc[g].x[e] += tmp.x[e];
        }
    }
    __syncthreads();
    if (grp == 0) {
#pragma unroll
        for (int g = 0; g < 3; g++)
            wmma::store_matrix_sync(Gsm + (g * 128 + wm * 16) * RC_LDA,
                                    acc[g], RC_LDA, wmma::mem_row_major);
    }
    __syncthreads();

    // ---- fused gate math: 128 b-rows x 16 n-cols, 512 threads x 4 ----
#pragma unroll
    for (int i = 0; i < 4; i++) {
        int e  = tid + i * 512;
        int bl = e >> 4;
        int nl = e & 15;
        int b  = b0 + bl;
        int nc = n0 + nl;
        float hr = Gsm[(0 * 128 + bl) * RC_LDA + nl] + bhh[nc];
        float hz = Gsm[(1 * 128 + bl) * RC_LDA + nl] + bhh[H + nc];
        float hn = Gsm[(2 * 128 + bl) * RC_LDA + nl] + bhh[2 * H + nc];
        const float* gib = gi + (size_t)b * gi_bstride;
        float ir = gib[nc], iz = gib[H + nc], in_ = gib[2 * H + nc];
        float r  = sigf(ir + hr);
        float z  = sigf(iz + hz);
        float nn = tanhf(in_ + r * hn);
        float hv = hread[(size_t)b * H + nc];
        float hnew = (1.f - z) * nn + z * hv;
        hwrite[(size_t)b * H + nc] = hnew;
        if (eout_t) eout_t[(size_t)b * eout_bstride + nc] = hnew;
    }
}

// ----------------------------------------------------------------------------
// Small kernels (t-major indices; unchanged from round 6)
// ----------------------------------------------------------------------------
__global__ void logits_kernel(const float* __restrict__ s1,
                              const float* __restrict__ w2,
                              const float* __restrict__ b2,
                              float* __restrict__ logits)
{
    int row  = blockIdx.x * 8 + (threadIdx.x >> 5);
    int lane = threadIdx.x & 31;
    const float* src = s1 + (size_t)row * HID;
    float acc = 0.f;
    for (int k = lane; k < HID; k += 32) acc += src[k] * w2[k];
#pragma unroll
    for (int o = 16; o > 0; o >>= 1) acc += __shfl_xor_sync(0xffffffffu, acc, o);
    if (lane == 0) logits[row] = acc + b2[0];
}

__global__ void softmax_kernel(const float* __restrict__ logits,
                               float* __restrict__ wts)
{
    __shared__ float sdata[T];
    int b = blockIdx.x, t = threadIdx.x;
    float v = logits[t * B + b];
    sdata[t] = v;
    __syncthreads();
    for (int s = T / 2; s > 0; s >>= 1) {
        if (t < s) sdata[t] = fmaxf(sdata[t], sdata[t + s]);
        __syncthreads();
    }
    float mx = sdata[0];
    __syncthreads();
    float e = expf(v - mx);
    sdata[t] = e;
    __syncthreads();
    for (int s = T / 2; s > 0; s >>= 1) {
        if (t < s) sdata[t] += sdata[t + s];
        __syncthreads();
    }
    wts[t * B + b] = e / sdata[0];
}

__global__ void pool_kernel(const float* __restrict__ eout,
                            const float* __restrict__ wts,
                            float* __restrict__ hs,
                            float* __restrict__ rep_out)
{
    __shared__ float w[T];
    int b = blockIdx.x, tid = threadIdx.x;
    w[tid] = wts[tid * B + b];
    __syncthreads();
    for (int h0 = tid; h0 < H; h0 += blockDim.x) {
        const float* base = eout + (size_t)b * H + h0;
        float acc = 0.f;
#pragma unroll 4
        for (int t = 0; t < T; t++) acc += w[t] * base[(size_t)t * B * H];
        hs[b * H + h0] = acc;
        if (rep_out) rep_out[b * H + h0] = acc;
    }
}

__global__ void gather_last(const float* __restrict__ x, float* __restrict__ p0)
{
    int idx = blockIdx.x * blockDim.x + threadIdx.x;
    if (idx >= B * D) return;
    int b = idx / D, dd = idx % D;
    p0[idx] = x[((size_t)b * T + (T - 1)) * D + dd];
}

__global__ void pred_kernel(const float* __restrict__ l1,
                            const float* __restrict__ w,
                            const float* __restrict__ bias,
                            float* __restrict__ out, int ldc)
{
    __shared__ float row[HID];
    int m = blockIdx.x;
    for (int k = threadIdx.x; k < HID; k += blockDim.x)
        row[k] = l1[(size_t)m * HID + k];
    __syncthreads();
    int n = threadIdx.x;
    if (n < D) {
        const float* wr = w + (size_t)n * HID;
        float acc = bias[n];
        for (int k = 0; k < HID; k++) acc += row[k] * wr[k];
        out[(size_t)m * ldc + n] = acc;
    }
}

// ----------------------------------------------------------------------------
// Host driver
// ----------------------------------------------------------------------------
static inline void launch_gemm(const float* A, int lda, const float* W,
                               const float* bias, float* C, int ldc,
                               int M, int N, int K, int act, int permute_bt = 0)
{
    dim3 grid(N / BN, M / BM);
    gemm_tf32_v2<<<grid, 256, GM_SMEM_BYTES>>>(A, lda, W, bias, C, ldc, M, N, K,
                                               act, permute_bt);
}

extern "C" void kernel_launch(void* const* d_in, const int* in_sizes, int n_in,
                              void* d_out, int out_size)
{
    const float* x       = (const float*)d_in[0];
    const float* p2l_w1  = (const float*)d_in[2];
    const float* p2l_b1  = (const float*)d_in[3];
    const float* p2l_w2  = (const float*)d_in[4];
    const float* p2l_b2  = (const float*)d_in[5];
    const float* enc_wih = (const float*)d_in[6];
    const float* enc_whh = (const float*)d_in[7];
    const float* enc_bih = (const float*)d_in[8];
    const float* enc_bhh = (const float*)d_in[9];
    const float* dec_wih = (const float*)d_in[10];
    const float* dec_whh = (const float*)d_in[11];
    const float* dec_bih = (const float*)d_in[12];
    const float* dec_bhh = (const float*)d_in[13];
    const float* l2p_w1  = (const float*)d_in[14];
    const float* l2p_b1  = (const float*)d_in[15];
    const float* l2p_w2  = (const float*)d_in[16];
    const float* l2p_b2  = (const float*)d_in[17];
    const float* l2s_w1  = (const float*)d_in[18];
    const float* l2s_b1  = (const float*)d_in[19];
    const float* l2s_w2  = (const float*)d_in[20];
    const float* l2s_b2  = (const float*)d_in[21];

    float* out = (float*)d_out;
    const int PREDS = B * P * D;
    float* rep_out = (out_size >= PREDS + B * H) ? (out + PREDS) : nullptr;

    float *p_buf1, *p_latent, *p_xp, *p_eout, *p_hb0, *p_hb1, *p_logits,
          *p_wts, *p_hs, *p_hs2, *p_p0, *p_d1, *p_dinp, *p_gi, *p_l1;
    void* tmp;
#define SYM(dst, sym) cudaGetSymbolAddress(&tmp, sym); dst = (decltype(dst))tmp;
    SYM(p_buf1, g_buf1)   SYM(p_latent, g_latent) SYM(p_xp, g_xp)
    SYM(p_eout, g_eout)   SYM(p_hb0, g_hb0)       SYM(p_hb1, g_hb1)
    SYM(p_logits, g_logits) SYM(p_wts, g_wts)     SYM(p_hs, g_hs)
    SYM(p_hs2, g_hs2)     SYM(p_p0, g_p0)         SYM(p_d1, g_d1)
    SYM(p_dinp, g_dinp)   SYM(p_gi, g_gi)         SYM(p_l1, g_l1)
#undef SYM

    cudaFuncSetAttribute(gru_step, cudaFuncAttributeMaxDynamicSharedMemorySize,
                         RC_SMEM_BYTES);
    cudaFuncSetAttribute(gemm_tf32_v2, cudaFuncAttributeMaxDynamicSharedMemorySize,
                         GM_SMEM_BYTES);

    // ---- par2lat(x) ----
    launch_gemm(x, D, p2l_w1, p2l_b1, p_buf1, HID, BT, HID, D, 1);
    launch_gemm(p_buf1, HID, p2l_w2, p2l_b2, p_latent, H, BT, H, HID, 1);

    // ---- xp = latent @ enc_wih^T + enc_bih, stored t-major [T, B, 3H] ----
    launch_gemm(p_latent, H, enc_wih, enc_bih, p_xp, H3, BT, H3, H, 0, 1);

    // ---- encoder recurrence: one fused launch per step ----
    cudaMemsetAsync(p_hb0, 0, (size_t)B * H * sizeof(float));
    {
        float* hr = p_hb0;
        float* hw = p_hb1;
        for (int t = 0; t < T; t++) {
            gru_step<<<128, 512, RC_SMEM_BYTES>>>(
                enc_whh, enc_bhh,
                p_xp + (size_t)t * B * H3, (size_t)H3,
                hr, hw,
                p_eout + (size_t)t * B * H, (size_t)H);
            float* t2 = hr; hr = hw; hw = t2;
        }
    }

    // ---- attention pooling (rows in (t,b) order) ----
    launch_gemm(p_eout, H, l2s_w1, l2s_b1, p_buf1, HID, BT, HID, H, 1);
    logits_kernel<<<BT / 8, 256>>>(p_buf1, l2s_w2, l2s_b2, p_logits);
    softmax_kernel<<<B, T>>>(p_logits, p_wts);
    pool_kernel<<<B, 256>>>(p_eout, p_wts, p_hs, rep_out);

    // ---- autoregressive decode ----
    gather_last<<<(B * D + 255) / 256, 256>>>(x, p_p0);
    float* hs_read  = p_hs;
    float* hs_write = p_hs2;
    for (int s = 0; s < P; s++) {
        const float* pin = (s == 0) ? p_p0 : (out + (size_t)(s - 1) * D);
        int plda = (s == 0) ? D : (P * D);
        launch_gemm(pin, plda, p2l_w1, p2l_b1, p_d1, HID, B, HID, D, 1);
        launch_gemm(p_d1, HID, p2l_w2, p2l_b2, p_dinp, H, B, H, HID, 1);
        launch_gemm(p_dinp, H, dec_wih, dec_bih, p_gi, H3, B, H3, H, 0);
        gru_step<<<128, 512, RC_SMEM_BYTES>>>(
            dec_whh, dec_bhh, p_gi, (size_t)H3,
            hs_read, hs_write, nullptr, 0);
        launch_gemm(hs_write, H, l2p_w1, l2p_b1, p_l1, HID, B, HID, H, 1);
        pred_kernel<<<B, 128>>>(p_l1, l2p_w2, l2p_b2,
                                out + (size_t)s * D, P * D);
        float* t2 = hs_read; hs_read = hs_write; hs_write = t2;
    }
}

// round 8
// speedup vs baseline: 1.2431x; 1.1164x over previous
#include <cuda_runtime.h>
#include <mma.h>
#include <cstdint>

using namespace nvcuda;

// Problem constants (fixed by the reference)
constexpr int B   = 256;
constexpr int T   = 256;
constexpr int D   = 72;
constexpr int HID = 512;
constexpr int H   = 1024;
constexpr int H3  = 3 * H;
constexpr int P   = 10;       // to_predict
constexpr int BT  = B * T;    // 65536

// ----------------------------------------------------------------------------
// Device scratch
// ----------------------------------------------------------------------------
__device__ float g_buf1  [(size_t)BT * HID];
__device__ float g_latent[(size_t)BT * H];
__device__ float g_xp    [(size_t)BT * H3];   // [T, B, 3H] (t-major)
__device__ float g_eout  [(size_t)BT * H];    // [T, B, H]  (t-major)
__device__ float g_hb0   [B * H];
__device__ float g_hb1   [B * H];
__device__ float g_logits[BT];                // index t*B + b
__device__ float g_wts   [BT];                // index t*B + b
__device__ float g_hs    [B * H];
__device__ float g_hs2   [B * H];
__device__ float g_p0    [B * D];
__device__ float g_d1    [B * HID];
__device__ float g_dinp  [B * H];
__device__ float g_gi    [B * H3];
__device__ float g_l1    [B * HID];

// ----------------------------------------------------------------------------
// Pipelined tf32 WMMA GEMM v2 (+ optional (b,t)->(t,b) output row permute).
// UNCHANGED (proven, ~118 TF/s).
// ----------------------------------------------------------------------------
#define BM 128
#define BN 128
#define BK 32
constexpr int GLDS = BK + 4;
constexpr int GBUF = (BM + BN) * GLDS;
constexpr int GM_SMEM_BYTES = 2 * GBUF * 4;

__device__ __forceinline__ void gm_load_tiles(
    const float* __restrict__ A, int lda,
    const float* __restrict__ W, int K,
    int bm, int bn, int kk, int tid,
    float4 ra[4], float4 rb[4])
{
#pragma unroll
    for (int i = 0; i < 4; i++) {
        int idx = tid + i * 256;
        int r   = idx >> 3;
        int c4  = (idx & 7) * 4;
        int gk  = kk + c4;
        const float* srcA = A + (size_t)(bm + r) * lda + gk;
        const float* srcB = W + (size_t)(bn + r) * K + gk;
        if (gk + 4 <= K) {
            ra[i] = *reinterpret_cast<const float4*>(srcA);
            rb[i] = *reinterpret_cast<const float4*>(srcB);
        } else {
            ra[i].x = (gk + 0 < K) ? srcA[0] : 0.f;
            ra[i].y = (gk + 1 < K) ? srcA[1] : 0.f;
            ra[i].z = (gk + 2 < K) ? srcA[2] : 0.f;
            ra[i].w = (gk + 3 < K) ? srcA[3] : 0.f;
            rb[i].x = (gk + 0 < K) ? srcB[0] : 0.f;
            rb[i].y = (gk + 1 < K) ? srcB[1] : 0.f;
            rb[i].z = (gk + 2 < K) ? srcB[2] : 0.f;
            rb[i].w = (gk + 3 < K) ? srcB[3] : 0.f;
        }
    }
}

__device__ __forceinline__ void gm_store_tiles(
    float* __restrict__ As, float* __restrict__ Bs, int tid,
    const float4 ra[4], const float4 rb[4])
{
#pragma unroll
    for (int i = 0; i < 4; i++) {
        int idx = tid + i * 256;
        int r   = idx >> 3;
        int c4  = (idx & 7) * 4;
        float* da = As + r * GLDS + c4;
        da[0] = wmma::__float_to_tf32(ra[i].x);
        da[1] = wmma::__float_to_tf32(ra[i].y);
        da[2] = wmma::__float_to_tf32(ra[i].z);
        da[3] = wmma::__float_to_tf32(ra[i].w);
        float* db = Bs + r * GLDS + c4;
        db[0] = wmma::__float_to_tf32(rb[i].x);
        db[1] = wmma::__float_to_tf32(rb[i].y);
        db[2] = wmma::__float_to_tf32(rb[i].z);
        db[3] = wmma::__float_to_tf32(rb[i].w);
    }
}

__global__ void __launch_bounds__(256, 1)
gemm_tf32_v2(const float* __restrict__ A, int lda,
             const float* __restrict__ W,
             const float* __restrict__ bias,
             float* __restrict__ C, int ldc,
             int M, int N, int K, int act, int permute_bt)
{
    extern __shared__ float sm[];
    float* Abuf[2] = { sm,               sm + GBUF };
    float* Bbuf[2] = { sm + BM * GLDS,   sm + GBUF + BM * GLDS };
    float* Cs = sm;

    const int bm  = blockIdx.y * BM;
    const int bn  = blockIdx.x * BN;
    const int tid = threadIdx.x;
    const int w   = tid >> 5;
    const int wm  = w & 3;
    const int wn  = w >> 2;

    wmma::fragment<wmma::accumulator, 16, 16, 8, float> c[2][4];
#pragma unroll
    for (int i = 0; i < 2; i++)
#pragma unroll
        for (int j = 0; j < 4; j++)
            wmma::fill_fragment(c[i][j], 0.0f);

    const int niter = (K + BK - 1) / BK;
    float4 ra[4], rb[4];

    gm_load_tiles(A, lda, W, K, bm, bn, 0, tid, ra, rb);
    gm_store_tiles(Abuf[0], Bbuf[0], tid, ra, rb);
    __syncthreads();

    for (int it = 0; it < niter; it++) {
        if (it + 1 < niter)
            gm_load_tiles(A, lda, W, K, bm, bn, (it + 1) * BK, tid, ra, rb);

        const float* As = Abuf[it & 1];
        const float* Bs = Bbuf[it & 1];
#pragma unroll
        for (int ks = 0; ks < 4; ks++) {
            wmma::fragment<wmma::matrix_a, 16, 16, 8, wmma::precision::tf32, wmma::row_major> af[2];
            wmma::fragment<wmma::matrix_b, 16, 16, 8, wmma::precision::tf32, wmma::col_major> bf[4];
#pragma unroll
            for (int i = 0; i < 2; i++)
                wmma::load_matrix_sync(af[i], As + (wm * 32 + i * 16) * GLDS + ks * 8, GLDS);
#pragma unroll
            for (int j = 0; j < 4; j++)
                wmma::load_matrix_sync(bf[j], Bs + (wn * 64 + j * 16) * GLDS + ks * 8, GLDS);
#pragma unroll
            for (int i = 0; i < 2; i++)
#pragma unroll
                for (int j = 0; j < 4; j++)
                    wmma::mma_sync(c[i][j], af[i], bf[j], c[i][j]);
        }

        if (it + 1 < niter)
            gm_store_tiles(Abuf[(it + 1) & 1], Bbuf[(it + 1) & 1], tid, ra, rb);
        __syncthreads();
    }

#pragma unroll
    for (int i = 0; i < 2; i++)
#pragma unroll
        for (int j = 0; j < 4; j++)
            wmma::store_matrix_sync(Cs + (wm * 32 + i * 16) * (BN + 4) + wn * 64 + j * 16,
                                    c[i][j], BN + 4, wmma::mem_row_major);
    __syncthreads();

#pragma unroll
    for (int i = 0; i < 16; i++) {
        int idx4 = tid + i * 256;
        int r    = idx4 >> 5;
        int c4   = (idx4 & 31) * 4;
        float4 v = *reinterpret_cast<const float4*>(Cs + r * (BN + 4) + c4);
        if (bias) {
            float4 bv = *reinterpret_cast<const float4*>(bias + bn + c4);
            v.x += bv.x; v.y += bv.y; v.z += bv.z; v.w += bv.w;
        }
        if (act == 1) {
            v.x = fmaxf(v.x, 0.f); v.y = fmaxf(v.y, 0.f);
            v.z = fmaxf(v.z, 0.f); v.w = fmaxf(v.w, 0.f);
        }
        int gr   = bm + r;
        int orow = permute_bt ? (((gr & 255) << 8) | (gr >> 8)) : gr;
        *reinterpret_cast<float4*>(C + (size_t)orow * ldc + bn + c4) = v;
    }
}

// ----------------------------------------------------------------------------
// Fused single GRU step v4: raw PTX mma.m16n8k8.tf32, barrier-free main loop.
// Grid = 128 CTAs = 2 b-tiles x 64 n-tiles (16 h-cols x 3 gates).
// 512 threads = 16 warps = 4 K-groups (K=256 each) x 4 m-warps (m32 each).
// A (h) loads: global -> registers (documented mma fragment layout).
// B (weights): resident tf32 slab in smem, per-lane LDS (conflict-free).
// K-group partials combined via sequential smem add-passes (deterministic).
// ----------------------------------------------------------------------------
constexpr int RC_LDW     = 1028;
constexpr int RC_WFLOATS = 48 * RC_LDW;          // 49344 floats
constexpr int RC_LDA     = 20;                   // gate staging ld
constexpr int RC_GFLOATS = 3 * 128 * RC_LDA;     // 7680 floats
constexpr int RC_SMEM_BYTES = (RC_WFLOATS + RC_GFLOATS) * 4;  // 228096 B

__device__ __forceinline__ float sigf(float x) { return 1.f / (1.f + expf(-x)); }

__device__ __forceinline__ uint32_t f2tf32(float x) {
    uint32_t r;
    asm("cvt.rna.tf32.f32 %0, %1;" : "=r"(r) : "f"(x));
    return r;
}

__device__ __forceinline__ void mma_tf32(float d[4], const uint32_t a[4],
                                         uint32_t b0, uint32_t b1) {
    asm volatile(
        "mma.sync.aligned.m16n8k8.row.col.f32.tf32.tf32.f32 "
        "{%0,%1,%2,%3}, {%4,%5,%6,%7}, {%8,%9}, {%0,%1,%2,%3};"
        : "+f"(d[0]), "+f"(d[1]), "+f"(d[2]), "+f"(d[3])
        : "r"(a[0]), "r"(a[1]), "r"(a[2]), "r"(a[3]), "r"(b0), "r"(b1));
}

__global__ void __launch_bounds__(512, 1)
gru_step(const float* __restrict__ whh, const float* __restrict__ bhh,
         const float* __restrict__ gi, size_t gi_bstride,
         const float* __restrict__ hread, float* __restrict__ hwrite,
         float* __restrict__ eout_t, size_t eout_bstride)
{
    extern __shared__ float smem[];
    float* Wsm = smem;                 // [48][1028] tf32
    float* Gsm = smem + RC_WFLOATS;    // [3][128][20] gate staging

    const int tid  = threadIdx.x;
    const int lane = tid & 31;
    const int w    = tid >> 5;         // 0..15
    const int grp  = w >> 2;           // K group 0..3
    const int wm   = w & 3;            // m32 tile 0..3
    const int nt   = blockIdx.x & 63;
    const int bt   = blockIdx.x >> 6;
    const int b0   = bt * 128;
    const int n0   = nt * 16;
    const int kb   = grp * 256;

    // ---- preload weight slab (48 x 1024, tf32), all 512 threads ----
    for (int i = tid; i < 48 * 256; i += 512) {
        int r  = i >> 8;
        int c4 = (i & 255) * 4;
        int g  = r >> 4;
        int nr = r & 15;
        const float4 v = *reinterpret_cast<const float4*>(
            whh + (size_t)(g * H + n0 + nr) * H + c4);
        float* dst = Wsm + r * RC_LDW + c4;
        dst[0] = __uint_as_float(f2tf32(v.x));
        dst[1] = __uint_as_float(f2tf32(v.y));
        dst[2] = __uint_as_float(f2tf32(v.z));
        dst[3] = __uint_as_float(f2tf32(v.w));
    }
    __syncthreads();

    // ---- barrier-free main loop: 32 k8-steps over this group's K range ----
    // A fragment layout (m16n8k8.tf32): a0:(r,c)=(q,t) a1:(q+8,t) a2:(q,t+4)
    // a3:(q+8,t+4) with q=lane>>2, t=lane&3. Two m16 halves (mh) per warp.
    const int q = lane >> 2;
    const int t = lane & 3;
    const float* hbase = hread + (size_t)(b0 + wm * 32 + q) * H + kb + t;

    float acc[2][3][2][4];
#pragma unroll
    for (int mh = 0; mh < 2; mh++)
#pragma unroll
        for (int g = 0; g < 3; g++)
#pragma unroll
            for (int nj = 0; nj < 2; nj++)
#pragma unroll
                for (int e = 0; e < 4; e++) acc[mh][g][nj][e] = 0.f;

    float pf[2][4];
#pragma unroll
    for (int mh = 0; mh < 2; mh++) {
        const float* p = hbase + (size_t)mh * 16 * H;
        pf[mh][0] = p[0];
        pf[mh][1] = p[8 * H];
        pf[mh][2] = p[4];
        pf[mh][3] = p[8 * H + 4];
    }

    for (int c = 0; c < 32; c++) {
        uint32_t A[2][4];
#pragma unroll
        for (int mh = 0; mh < 2; mh++)
#pragma unroll
            for (int i = 0; i < 4; i++)
                A[mh][i] = f2tf32(pf[mh][i]);

        if (c < 31) {
#pragma unroll
            for (int mh = 0; mh < 2; mh++) {
                const float* p = hbase + (size_t)mh * 16 * H + (c + 1) * 8;
                pf[mh][0] = p[0];
                pf[mh][1] = p[8 * H];
                pf[mh][2] = p[4];
                pf[mh][3] = p[8 * H + 4];
            }
        }

        const int kk = kb + c * 8;
        // B fragment (col): b0:(k,n)=(t,q) b1:(t+4,q); W stored [n][k] in smem.
#pragma unroll
        for (int g = 0; g < 3; g++) {
#pragma unroll
            for (int nj = 0; nj < 2; nj++) {
                const float* wp = Wsm + (g * 16 + nj * 8 + q) * RC_LDW + kk + t;
                uint32_t b0r = __float_as_uint(wp[0]);
                uint32_t b1r = __float_as_uint(wp[4]);
                mma_tf32(acc[0][g][nj], A[0], b0r, b1r);
                mma_tf32(acc[1][g][nj], A[1], b0r, b1r);
            }
        }
    }

    // ---- combine K-group partials (deterministic sequential passes) ----
    // C layout: c0:(q, 2t) c1:(q, 2t+1) c2:(q+8, 2t) c3:(q+8, 2t+1)
    const int ccol = 2 * t;
#pragma unroll
    for (int pass = 3; pass >= 0; pass--) {
        if (grp == pass) {
#pragma unroll
            for (int mh = 0; mh < 2; mh++)
#pragma unroll
                for (int g = 0; g < 3; g++)
#pragma unroll
                    for (int nj = 0; nj < 2; nj++) {
                        int row = wm * 32 + mh * 16 + q;
                        float* b0p = Gsm + (g * 128 + row) * RC_LDA + nj * 8 + ccol;
                        float* b1p = Gsm + (g * 128 + row + 8) * RC_LDA + nj * 8 + ccol;
                        if (pass == 3) {
                            b0p[0] = acc[mh][g][nj][0];
                            b0p[1] = acc[mh][g][nj][1];
                            b1p[0] = acc[mh][g][nj][2];
                            b1p[1] = acc[mh][g][nj][3];
                        } else {
                            b0p[0] += acc[mh][g][nj][0];
                            b0p[1] += acc[mh][g][nj][1];
                            b1p[0] += acc[mh][g][nj][2];
                            b1p[1] += acc[mh][g][nj][3];
                        }
                    }
        }
        __syncthreads();
    }

    // ---- fused gate math: 128 b-rows x 16 n-cols, 4 elems per thread ----
#pragma unroll
    for (int i = 0; i < 4; i++) {
        int e  = tid + i * 512;
        int bl = e >> 4;
        int nl = e & 15;
        int b  = b0 + bl;
        int nc = n0 + nl;
        float hr = Gsm[(0 * 128 + bl) * RC_LDA + nl] + bhh[nc];
        float hz = Gsm[(1 * 128 + bl) * RC_LDA + nl] + bhh[H + nc];
        float hn = Gsm[(2 * 128 + bl) * RC_LDA + nl] + bhh[2 * H + nc];
        const float* gib = gi + (size_t)b * gi_bstride;
        float ir = gib[nc], iz = gib[H + nc], in_ = gib[2 * H + nc];
        float r  = sigf(ir + hr);
        float z  = sigf(iz + hz);
        float nn = tanhf(in_ + r * hn);
        float hv = hread[(size_t)b * H + nc];
        float hnew = (1.f - z) * nn + z * hv;
        hwrite[(size_t)b * H + nc] = hnew;
        if (eout_t) eout_t[(size_t)b * eout_bstride + nc] = hnew;
    }
}

// ----------------------------------------------------------------------------
// Small kernels (t-major indices; unchanged)
// ----------------------------------------------------------------------------
__global__ void logits_kernel(const float* __restrict__ s1,
                              const float* __restrict__ w2,
                              const float* __restrict__ b2,
                              float* __restrict__ logits)
{
    int row  = blockIdx.x * 8 + (threadIdx.x >> 5);
    int lane = threadIdx.x & 31;
    const float* src = s1 + (size_t)row * HID;
    float acc = 0.f;
    for (int k = lane; k < HID; k += 32) acc += src[k] * w2[k];
#pragma unroll
    for (int o = 16; o > 0; o >>= 1) acc += __shfl_xor_sync(0xffffffffu, acc, o);
    if (lane == 0) logits[row] = acc + b2[0];
}

__global__ void softmax_kernel(const float* __restrict__ logits,
                               float* __restrict__ wts)
{
    __shared__ float sdata[T];
    int b = blockIdx.x, t = threadIdx.x;
    float v = logits[t * B + b];
    sdata[t] = v;
    __syncthreads();
    for (int s = T / 2; s > 0; s >>= 1) {
        if (t < s) sdata[t] = fmaxf(sdata[t], sdata[t + s]);
        __syncthreads();
    }
    float mx = sdata[0];
    __syncthreads();
    float e = expf(v - mx);
    sdata[t] = e;
    __syncthreads();
    for (int s = T / 2; s > 0; s >>= 1) {
        if (t < s) sdata[t] += sdata[t + s];
        __syncthreads();
    }
    wts[t * B + b] = e / sdata[0];
}

__global__ void pool_kernel(const float* __restrict__ eout,
                            const float* __restrict__ wts,
                            float* __restrict__ hs,
                            float* __restrict__ rep_out)
{
    __shared__ float w[T];
    int b = blockIdx.x, tid = threadIdx.x;
    w[tid] = wts[tid * B + b];
    __syncthreads();
    for (int h0 = tid; h0 < H; h0 += blockDim.x) {
        const float* base = eout + (size_t)b * H + h0;
        float acc = 0.f;
#pragma unroll 4
        for (int t = 0; t < T; t++) acc += w[t] * base[(size_t)t * B * H];
        hs[b * H + h0] = acc;
        if (rep_out) rep_out[b * H + h0] = acc;
    }
}

__global__ void gather_last(const float* __restrict__ x, float* __restrict__ p0)
{
    int idx = blockIdx.x * blockDim.x + threadIdx.x;
    if (idx >= B * D) return;
    int b = idx / D, dd = idx % D;
    p0[idx] = x[((size_t)b * T + (T - 1)) * D + dd];
}

__global__ void pred_kernel(const float* __restrict__ l1,
                            const float* __restrict__ w,
                            const float* __restrict__ bias,
                            float* __restrict__ out, int ldc)
{
    __shared__ float row[HID];
    int m = blockIdx.x;
    for (int k = threadIdx.x; k < HID; k += blockDim.x)
        row[k] = l1[(size_t)m * HID + k];
    __syncthreads();
    int n = threadIdx.x;
    if (n < D) {
        const float* wr = w + (size_t)n * HID;
        float acc = bias[n];
        for (int k = 0; k < HID; k++) acc += row[k] * wr[k];
        out[(size_t)m * ldc + n] = acc;
    }
}

// ----------------------------------------------------------------------------
// Host driver
// ----------------------------------------------------------------------------
static inline void launch_gemm(const float* A, int lda, const float* W,
                               const float* bias, float* C, int ldc,
                               int M, int N, int K, int act, int permute_bt = 0)
{
    dim3 grid(N / BN, M / BM);
    gemm_tf32_v2<<<grid, 256, GM_SMEM_BYTES>>>(A, lda, W, bias, C, ldc, M, N, K,
                                               act, permute_bt);
}

extern "C" void kernel_launch(void* const* d_in, const int* in_sizes, int n_in,
                              void* d_out, int out_size)
{
    const float* x       = (const float*)d_in[0];
    const float* p2l_w1  = (const float*)d_in[2];
    const float* p2l_b1  = (const float*)d_in[3];
    const float* p2l_w2  = (const float*)d_in[4];
    const float* p2l_b2  = (const float*)d_in[5];
    const float* enc_wih = (const float*)d_in[6];
    const float* enc_whh = (const float*)d_in[7];
    const float* enc_bih = (const float*)d_in[8];
    const float* enc_bhh = (const float*)d_in[9];
    const float* dec_wih = (const float*)d_in[10];
    const float* dec_whh = (const float*)d_in[11];
    const float* dec_bih = (const float*)d_in[12];
    const float* dec_bhh = (const float*)d_in[13];
    const float* l2p_w1  = (const float*)d_in[14];
    const float* l2p_b1  = (const float*)d_in[15];
    const float* l2p_w2  = (const float*)d_in[16];
    const float* l2p_b2  = (const float*)d_in[17];
    const float* l2s_w1  = (const float*)d_in[18];
    const float* l2s_b1  = (const float*)d_in[19];
    const float* l2s_w2  = (const float*)d_in[20];
    const float* l2s_b2  = (const float*)d_in[21];

    float* out = (float*)d_out;
    const int PREDS = B * P * D;
    float* rep_out = (out_size >= PREDS + B * H) ? (out + PREDS) : nullptr;

    float *p_buf1, *p_latent, *p_xp, *p_eout, *p_hb0, *p_hb1, *p_logits,
          *p_wts, *p_hs, *p_hs2, *p_p0, *p_d1, *p_dinp, *p_gi, *p_l1;
    void* tmp;
#define SYM(dst, sym) cudaGetSymbolAddress(&tmp, sym); dst = (decltype(dst))tmp;
    SYM(p_buf1, g_buf1)   SYM(p_latent, g_latent) SYM(p_xp, g_xp)
    SYM(p_eout, g_eout)   SYM(p_hb0, g_hb0)       SYM(p_hb1, g_hb1)
    SYM(p_logits, g_logits) SYM(p_wts, g_wts)     SYM(p_hs, g_hs)
    SYM(p_hs2, g_hs2)     SYM(p_p0, g_p0)         SYM(p_d1, g_d1)
    SYM(p_dinp, g_dinp)   SYM(p_gi, g_gi)         SYM(p_l1, g_l1)
#undef SYM

    cudaFuncSetAttribute(gru_step, cudaFuncAttributeMaxDynamicSharedMemorySize,
                         RC_SMEM_BYTES);
    cudaFuncSetAttribute(gemm_tf32_v2, cudaFuncAttributeMaxDynamicSharedMemorySize,
                         GM_SMEM_BYTES);

    // ---- par2lat(x) ----
    launch_gemm(x, D, p2l_w1, p2l_b1, p_buf1, HID, BT, HID, D, 1);
    launch_gemm(p_buf1, HID, p2l_w2, p2l_b2, p_latent, H, BT, H, HID, 1);

    // ---- xp = latent @ enc_wih^T + enc_bih, stored t-major [T, B, 3H] ----
    launch_gemm(p_latent, H, enc_wih, enc_bih, p_xp, H3, BT, H3, H, 0, 1);

    // ---- encoder recurrence: one fused launch per step ----
    cudaMemsetAsync(p_hb0, 0, (size_t)B * H * sizeof(float));
    {
        float* hr = p_hb0;
        float* hw = p_hb1;
        for (int t = 0; t < T; t++) {
            gru_step<<<128, 512, RC_SMEM_BYTES>>>(
                enc_whh, enc_bhh,
                p_xp + (size_t)t * B * H3, (size_t)H3,
                hr, hw,
                p_eout + (size_t)t * B * H, (size_t)H);
            float* t2 = hr; hr = hw; hw = t2;
        }
    }

    // ---- attention pooling (rows in (t,b) order) ----
    launch_gemm(p_eout, H, l2s_w1, l2s_b1, p_buf1, HID, BT, HID, H, 1);
    logits_kernel<<<BT / 8, 256>>>(p_buf1, l2s_w2, l2s_b2, p_logits);
    softmax_kernel<<<B, T>>>(p_logits, p_wts);
    pool_kernel<<<B, 256>>>(p_eout, p_wts, p_hs, rep_out);

    // ---- autoregressive decode ----
    gather_last<<<(B * D + 255) / 256, 256>>>(x, p_p0);
    float* hs_read  = p_hs;
    float* hs_write = p_hs2;
    for (int s = 0; s < P; s++) {
        const float* pin = (s == 0) ? p_p0 : (out + (size_t)(s - 1) * D);
        int plda = (s == 0) ? D : (P * D);
        launch_gemm(pin, plda, p2l_w1, p2l_b1, p_d1, HID, B, HID, D, 1);
        launch_gemm(p_d1, HID, p2l_w2, p2l_b2, p_dinp, H, B, H, HID, 1);
        launch_gemm(p_dinp, H, dec_wih, dec_bih, p_gi, H3, B, H3, H, 0);
        gru_step<<<128, 512, RC_SMEM_BYTES>>>(
            dec_whh, dec_bhh, p_gi, (size_t)H3,
            hs_read, hs_write, nullptr, 0);
        launch_gemm(hs_write, H, l2p_w1, l2p_b1, p_l1, HID, B, HID, H, 1);
        pred_kernel<<<B, 128>>>(p_l1, l2p_w2, l2p_b2,
                                out + (size_t)s * D, P * D);
        float* t2 = hs_read; hs_read = hs_write; hs_write = t2;
    }
}

// round 9
// speedup vs baseline: 1.4118x; 1.1358x over previous
#include <cuda_runtime.h>
#include <mma.h>
#include <cstdint>

using namespace nvcuda;

// Problem constants (fixed by the reference)
constexpr int B   = 256;
constexpr int T   = 256;
constexpr int D   = 72;
constexpr int HID = 512;
constexpr int H   = 1024;
constexpr int H3  = 3 * H;
constexpr int P   = 10;       // to_predict
constexpr int BT  = B * T;    // 65536

// ----------------------------------------------------------------------------
// Device scratch
// ----------------------------------------------------------------------------
__device__ float g_buf1  [(size_t)BT * HID];
__device__ float g_latent[(size_t)BT * H];
__device__ float g_xp    [(size_t)BT * H3];   // [T, B, 3H] (t-major)
__device__ float g_eout  [(size_t)BT * H];    // [T, B, H]  (t-major)
__device__ float g_hb0   [B * H];             // hT layout [H][B]
__device__ float g_hb1   [B * H];             // hT layout [H][B]
__device__ float g_logits[BT];                // index t*B + b
__device__ float g_wts   [BT];                // index t*B + b
__device__ float g_hs    [B * H];             // hT layout (decode ping)
__device__ float g_hs2   [B * H];             // hT layout (decode pong)
__device__ float g_hrow  [B * H];             // row-major h for decode l2p GEMM
__device__ float g_p0    [B * D];
__device__ float g_d1    [B * HID];
__device__ float g_dinp  [B * H];
__device__ float g_gi    [B * H3];
__device__ float g_l1    [B * HID];
// Pre-swizzled (fragment-order, tf32) weight slabs: 64 n-tiles x 49152 floats
constexpr int WSW_TILE = 128 * 6 * 64;        // 49152
__device__ float g_wsw_enc[(size_t)64 * WSW_TILE];
__device__ float g_wsw_dec[(size_t)64 * WSW_TILE];

// ----------------------------------------------------------------------------
// Pipelined tf32 WMMA GEMM v2 (+ optional (b,t)->(t,b) output row permute).
// UNCHANGED (proven, ~118 TF/s).
// ----------------------------------------------------------------------------
#define BM 128
#define BN 128
#define BK 32
constexpr int GLDS = BK + 4;
constexpr int GBUF = (BM + BN) * GLDS;
constexpr int GM_SMEM_BYTES = 2 * GBUF * 4;

__device__ __forceinline__ void gm_load_tiles(
    const float* __restrict__ A, int lda,
    const float* __restrict__ W, int K,
    int bm, int bn, int kk, int tid,
    float4 ra[4], float4 rb[4])
{
#pragma unroll
    for (int i = 0; i < 4; i++) {
        int idx = tid + i * 256;
        int r   = idx >> 3;
        int c4  = (idx & 7) * 4;
        int gk  = kk + c4;
        const float* srcA = A + (size_t)(bm + r) * lda + gk;
        const float* srcB = W + (size_t)(bn + r) * K + gk;
        if (gk + 4 <= K) {
            ra[i] = *reinterpret_cast<const float4*>(srcA);
            rb[i] = *reinterpret_cast<const float4*>(srcB);
        } else {
            ra[i].x = (gk + 0 < K) ? srcA[0] : 0.f;
            ra[i].y = (gk + 1 < K) ? srcA[1] : 0.f;
            ra[i].z = (gk + 2 < K) ? srcA[2] : 0.f;
            ra[i].w = (gk + 3 < K) ? srcA[3] : 0.f;
            rb[i].x = (gk + 0 < K) ? srcB[0] : 0.f;
            rb[i].y = (gk + 1 < K) ? srcB[1] : 0.f;
            rb[i].z = (gk + 2 < K) ? srcB[2] : 0.f;
            rb[i].w = (gk + 3 < K) ? srcB[3] : 0.f;
        }
    }
}

__device__ __forceinline__ void gm_store_tiles(
    float* __restrict__ As, float* __restrict__ Bs, int tid,
    const float4 ra[4], const float4 rb[4])
{
#pragma unroll
    for (int i = 0; i < 4; i++) {
        int idx = tid + i * 256;
        int r   = idx >> 3;
        int c4  = (idx & 7) * 4;
        float* da = As + r * GLDS + c4;
        da[0] = wmma::__float_to_tf32(ra[i].x);
        da[1] = wmma::__float_to_tf32(ra[i].y);
        da[2] = wmma::__float_to_tf32(ra[i].z);
        da[3] = wmma::__float_to_tf32(ra[i].w);
        float* db = Bs + r * GLDS + c4;
        db[0] = wmma::__float_to_tf32(rb[i].x);
        db[1] = wmma::__float_to_tf32(rb[i].y);
        db[2] = wmma::__float_to_tf32(rb[i].z);
        db[3] = wmma::__float_to_tf32(rb[i].w);
    }
}

__global__ void __launch_bounds__(256, 1)
gemm_tf32_v2(const float* __restrict__ A, int lda,
             const float* __restrict__ W,
             const float* __restrict__ bias,
             float* __restrict__ C, int ldc,
             int M, int N, int K, int act, int permute_bt)
{
    extern __shared__ float sm[];
    float* Abuf[2] = { sm,               sm + GBUF };
    float* Bbuf[2] = { sm + BM * GLDS,   sm + GBUF + BM * GLDS };
    float* Cs = sm;

    const int bm  = blockIdx.y * BM;
    const int bn  = blockIdx.x * BN;
    const int tid = threadIdx.x;
    const int w   = tid >> 5;
    const int wm  = w & 3;
    const int wn  = w >> 2;

    wmma::fragment<wmma::accumulator, 16, 16, 8, float> c[2][4];
#pragma unroll
    for (int i = 0; i < 2; i++)
#pragma unroll
        for (int j = 0; j < 4; j++)
            wmma::fill_fragment(c[i][j], 0.0f);

    const int niter = (K + BK - 1) / BK;
    float4 ra[4], rb[4];

    gm_load_tiles(A, lda, W, K, bm, bn, 0, tid, ra, rb);
    gm_store_tiles(Abuf[0], Bbuf[0], tid, ra, rb);
    __syncthreads();

    for (int it = 0; it < niter; it++) {
        if (it + 1 < niter)
            gm_load_tiles(A, lda, W, K, bm, bn, (it + 1) * BK, tid, ra, rb);

        const float* As = Abuf[it & 1];
        const float* Bs = Bbuf[it & 1];
#pragma unroll
        for (int ks = 0; ks < 4; ks++) {
            wmma::fragment<wmma::matrix_a, 16, 16, 8, wmma::precision::tf32, wmma::row_major> af[2];
            wmma::fragment<wmma::matrix_b, 16, 16, 8, wmma::precision::tf32, wmma::col_major> bf[4];
#pragma unroll
            for (int i = 0; i < 2; i++)
                wmma::load_matrix_sync(af[i], As + (wm * 32 + i * 16) * GLDS + ks * 8, GLDS);
#pragma unroll
            for (int j = 0; j < 4; j++)
                wmma::load_matrix_sync(bf[j], Bs + (wn * 64 + j * 16) * GLDS + ks * 8, GLDS);
#pragma unroll
            for (int i = 0; i < 2; i++)
#pragma unroll
                for (int j = 0; j < 4; j++)
                    wmma::mma_sync(c[i][j], af[i], bf[j], c[i][j]);
        }

        if (it + 1 < niter)
            gm_store_tiles(Abuf[(it + 1) & 1], Bbuf[(it + 1) & 1], tid, ra, rb);
        __syncthreads();
    }

#pragma unroll
    for (int i = 0; i < 2; i++)
#pragma unroll
        for (int j = 0; j < 4; j++)
            wmma::store_matrix_sync(Cs + (wm * 32 + i * 16) * (BN + 4) + wn * 64 + j * 16,
                                    c[i][j], BN + 4, wmma::mem_row_major);
    __syncthreads();

#pragma unroll
    for (int i = 0; i < 16; i++) {
        int idx4 = tid + i * 256;
        int r    = idx4 >> 5;
        int c4   = (idx4 & 31) * 4;
        float4 v = *reinterpret_cast<const float4*>(Cs + r * (BN + 4) + c4);
        if (bias) {
            float4 bv = *reinterpret_cast<const float4*>(bias + bn + c4);
            v.x += bv.x; v.y += bv.y; v.z += bv.z; v.w += bv.w;
        }
        if (act == 1) {
            v.x = fmaxf(v.x, 0.f); v.y = fmaxf(v.y, 0.f);
            v.z = fmaxf(v.z, 0.f); v.w = fmaxf(v.w, 0.f);
        }
        int gr   = bm + r;
        int orow = permute_bt ? (((gr & 255) << 8) | (gr >> 8)) : gr;
        *reinterpret_cast<float4*>(C + (size_t)orow * ldc + bn + c4) = v;
    }
}

// ----------------------------------------------------------------------------
// tf32 helpers
// ----------------------------------------------------------------------------
__device__ __forceinline__ float sigf(float x) { return 1.f / (1.f + expf(-x)); }

__device__ __forceinline__ uint32_t f2tf32(float x) {
    uint32_t r;
    asm("cvt.rna.tf32.f32 %0, %1;" : "=r"(r) : "f"(x));
    return r;
}

__device__ __forceinline__ void mma_tf32(float d[4], const uint32_t a[4],
                                         uint32_t b0, uint32_t b1) {
    asm volatile(
        "mma.sync.aligned.m16n8k8.row.col.f32.tf32.tf32.f32 "
        "{%0,%1,%2,%3}, {%4,%5,%6,%7}, {%8,%9}, {%0,%1,%2,%3};"
        : "+f"(d[0]), "+f"(d[1]), "+f"(d[2]), "+f"(d[3])
        : "r"(a[0]), "r"(a[1]), "r"(a[2]), "r"(a[3]), "r"(b0), "r"(b1));
}

// ----------------------------------------------------------------------------
// One-time Whh pre-swizzle into mma-fragment order (tf32).
// Layout: wsw[nt][kstep*6 + g*2 + nj][lane*2 + {0,1}] where pair =
//   { W[g*H + nt*16 + nj*8 + (lane>>2)][kstep*8 + (lane&3)],  (same, k+4) }
// ----------------------------------------------------------------------------
__global__ void swizzle_whh(const float* __restrict__ whh, float* __restrict__ wsw)
{
    int nt = blockIdx.x;          // 0..63
    int n0 = nt * 16;
    for (int i = threadIdx.x; i < 128 * 6 * 32; i += blockDim.x) {
        int lane  = i & 31;
        int pos   = i >> 5;       // 0..767
        int kstep = pos / 6;
        int g2    = pos % 6;
        int g  = g2 >> 1;
        int nj = g2 & 1;
        int q = lane >> 2, t = lane & 3;
        const float* src = whh + (size_t)(g * H + n0 + nj * 8 + q) * H + kstep * 8 + t;
        float2 v;
        v.x = __uint_as_float(f2tf32(src[0]));
        v.y = __uint_as_float(f2tf32(src[4]));
        *reinterpret_cast<float2*>(wsw + (size_t)nt * WSW_TILE + (size_t)pos * 64 + lane * 2) = v;
    }
}

// ----------------------------------------------------------------------------
// Fused single GRU step v5: hT operand layout + pre-swizzled weights.
// Grid = 128 CTAs = 2 b-tiles x 64 n-tiles (16 h-cols x 3 gates).
// 512 threads = 16 warps = 4 K-groups (K=256) x 4 m-warps (m32 batch rows).
// A (h) from hT[k][b]: per warp-iter = 8 fully-used 128B lines.
// B (weights): coalesced LDS.64 from fragment-order smem slab.
// h read/write in hT layout; optional row-major h copy for decode GEMM.
// ----------------------------------------------------------------------------
constexpr int RC_LDA     = 20;                    // gate staging ld
constexpr int RC_GFLOATS = 3 * 128 * RC_LDA;      // 7680 floats
constexpr int RC_SMEM_BYTES = (WSW_TILE + RC_GFLOATS) * 4;  // 227328 B

__global__ void __launch_bounds__(512, 1)
gru_step(const float* __restrict__ wsw, const float* __restrict__ bhh,
         const float* __restrict__ gi, size_t gi_bstride,
         const float* __restrict__ hT_read, float* __restrict__ hT_write,
         float* __restrict__ eout_t, size_t eout_bstride,
         float* __restrict__ hrow_write)
{
    extern __shared__ float smem[];
    float* Wsm = smem;                 // 49152 floats, fragment-order tf32
    float* Gsm = smem + WSW_TILE;      // [3][128][20] gate staging

    const int tid  = threadIdx.x;
    const int lane = tid & 31;
    const int w    = tid >> 5;         // 0..15
    const int grp  = w >> 2;           // K group 0..3
    const int wm   = w & 3;            // m32 tile 0..3
    const int nt   = blockIdx.x & 63;
    const int bt   = blockIdx.x >> 6;
    const int b0   = bt * 128;
    const int n0   = nt * 16;
    const int kb   = grp * 256;

    // ---- preload pre-swizzled weight slab (coalesced float4 copy) ----
    {
        const float4* wsrc = reinterpret_cast<const float4*>(wsw + (size_t)nt * WSW_TILE);
        float4* wdst = reinterpret_cast<float4*>(Wsm);
        for (int i = tid; i < WSW_TILE / 4; i += 512)
            wdst[i] = wsrc[i];
    }
    __syncthreads();

    const int q = lane >> 2;
    const int t = lane & 3;
    // hT element (k, b): hT[k*B + b]; this warp's A base:
    const float* hTa = hT_read + (size_t)(kb + t) * B + b0 + wm * 32 + q;

    float acc[2][3][2][4];
#pragma unroll
    for (int mh = 0; mh < 2; mh++)
#pragma unroll
        for (int g = 0; g < 3; g++)
#pragma unroll
            for (int nj = 0; nj < 2; nj++)
#pragma unroll
                for (int e = 0; e < 4; e++) acc[mh][g][nj][e] = 0.f;

    float pf[2][4];
#pragma unroll
    for (int mh = 0; mh < 2; mh++) {
        const float* p = hTa + mh * 16;
        pf[mh][0] = p[0];          // (k=t,   b=q)
        pf[mh][1] = p[8];          // (k=t,   b=q+8)
        pf[mh][2] = p[4 * B];      // (k=t+4, b=q)
        pf[mh][3] = p[4 * B + 8];  // (k=t+4, b=q+8)
    }

    for (int c = 0; c < 32; c++) {
        uint32_t A[2][4];
#pragma unroll
        for (int mh = 0; mh < 2; mh++)
#pragma unroll
            for (int i = 0; i < 4; i++)
                A[mh][i] = f2tf32(pf[mh][i]);

        if (c < 31) {
#pragma unroll
            for (int mh = 0; mh < 2; mh++) {
                const float* p = hTa + (size_t)(c + 1) * 8 * B + mh * 16;
                pf[mh][0] = p[0];
                pf[mh][1] = p[8];
                pf[mh][2] = p[4 * B];
                pf[mh][3] = p[4 * B + 8];
            }
        }

        const int kstep = grp * 32 + c;
        const float2* wrow = reinterpret_cast<const float2*>(Wsm + (size_t)(kstep * 6) * 64);
#pragma unroll
        for (int g = 0; g < 3; g++) {
#pragma unroll
            for (int nj = 0; nj < 2; nj++) {
                float2 bw = wrow[(g * 2 + nj) * 32 + lane];
                uint32_t b0r = __float_as_uint(bw.x);
                uint32_t b1r = __float_as_uint(bw.y);
                mma_tf32(acc[0][g][nj], A[0], b0r, b1r);
                mma_tf32(acc[1][g][nj], A[1], b0r, b1r);
            }
        }
    }

    // ---- combine K-group partials (deterministic sequential passes) ----
    const int ccol = 2 * t;
#pragma unroll
    for (int pass = 3; pass >= 0; pass--) {
        if (grp == pass) {
#pragma unroll
            for (int mh = 0; mh < 2; mh++)
#pragma unroll
                for (int g = 0; g < 3; g++)
#pragma unroll
                    for (int nj = 0; nj < 2; nj++) {
                        int row = wm * 32 + mh * 16 + q;
                        float* b0p = Gsm + (g * 128 + row) * RC_LDA + nj * 8 + ccol;
                        float* b1p = Gsm + (g * 128 + row + 8) * RC_LDA + nj * 8 + ccol;
                        if (pass == 3) {
                            b0p[0] = acc[mh][g][nj][0];
                            b0p[1] = acc[mh][g][nj][1];
                            b1p[0] = acc[mh][g][nj][2];
                            b1p[1] = acc[mh][g][nj][3];
                        } else {
                            b0p[0] += acc[mh][g][nj][0];
                            b0p[1] += acc[mh][g][nj][1];
                            b1p[0] += acc[mh][g][nj][2];
                            b1p[1] += acc[mh][g][nj][3];
                        }
                    }
        }
        __syncthreads();
    }

    // ---- fused gate math: 128 b-rows x 16 n-cols, 4 elems per thread ----
#pragma unroll
    for (int i = 0; i < 4; i++) {
        int e  = tid + i * 512;
        int bl = e >> 4;
        int nl = e & 15;
        int b  = b0 + bl;
        int nc = n0 + nl;
        float hr = Gsm[(0 * 128 + bl) * RC_LDA + nl] + bhh[nc];
        float hz = Gsm[(1 * 128 + bl) * RC_LDA + nl] + bhh[H + nc];
        float hn = Gsm[(2 * 128 + bl) * RC_LDA + nl] + bhh[2 * H + nc];
        const float* gib = gi + (size_t)b * gi_bstride;
        float ir = gib[nc], iz = gib[H + nc], in_ = gib[2 * H + nc];
        float r  = sigf(ir + hr);
        float z  = sigf(iz + hz);
        float nn = tanhf(in_ + r * hn);
        float hv = hT_read[(size_t)nc * B + b];
        float hnew = (1.f - z) * nn + z * hv;
        hT_write[(size_t)nc * B + b] = hnew;
        if (eout_t) eout_t[(size_t)b * eout_bstride + nc] = hnew;
        if (hrow_write) hrow_write[(size_t)b * H + nc] = hnew;
    }
}

// ----------------------------------------------------------------------------
// Small kernels (t-major indices; pool writes hT for decode)
// ----------------------------------------------------------------------------
__global__ void logits_kernel(const float* __restrict__ s1,
                              const float* __restrict__ w2,
                              const float* __restrict__ b2,
                              float* __restrict__ logits)
{
    int row  = blockIdx.x * 8 + (threadIdx.x >> 5);
    int lane = threadIdx.x & 31;
    const float* src = s1 + (size_t)row * HID;
    float acc = 0.f;
    for (int k = lane; k < HID; k += 32) acc += src[k] * w2[k];
#pragma unroll
    for (int o = 16; o > 0; o >>= 1) acc += __shfl_xor_sync(0xffffffffu, acc, o);
    if (lane == 0) logits[row] = acc + b2[0];
}

__global__ void softmax_kernel(const float* __restrict__ logits,
                               float* __restrict__ wts)
{
    __shared__ float sdata[T];
    int b = blockIdx.x, t = threadIdx.x;
    float v = logits[t * B + b];
    sdata[t] = v;
    __syncthreads();
    for (int s = T / 2; s > 0; s >>= 1) {
        if (t < s) sdata[t] = fmaxf(sdata[t], sdata[t + s]);
        __syncthreads();
    }
    float mx = sdata[0];
    __syncthreads();
    float e = expf(v - mx);
    sdata[t] = e;
    __syncthreads();
    for (int s = T / 2; s > 0; s >>= 1) {
        if (t < s) sdata[t] += sdata[t + s];
        __syncthreads();
    }
    wts[t * B + b] = e / sdata[0];
}

// eout is [T, B, H]; writes hsT (hT layout, for decode) + rep_out (row-major)
__global__ void pool_kernel(const float* __restrict__ eout,
                            const float* __restrict__ wts,
                            float* __restrict__ hsT,
                            float* __restrict__ rep_out)
{
    __shared__ float w[T];
    int b = blockIdx.x, tid = threadIdx.x;
    w[tid] = wts[tid * B + b];
    __syncthreads();
    for (int h0 = tid; h0 < H; h0 += blockDim.x) {
        const float* base = eout + (size_t)b * H + h0;
        float acc = 0.f;
#pragma unroll 4
        for (int t = 0; t < T; t++) acc += w[t] * base[(size_t)t * B * H];
        hsT[(size_t)h0 * B + b] = acc;
        if (rep_out) rep_out[b * H + h0] = acc;
    }
}

__global__ void gather_last(const float* __restrict__ x, float* __restrict__ p0)
{
    int idx = blockIdx.x * blockDim.x + threadIdx.x;
    if (idx >= B * D) return;
    int b = idx / D, dd = idx % D;
    p0[idx] = x[((size_t)b * T + (T - 1)) * D + dd];
}

__global__ void pred_kernel(const float* __restrict__ l1,
                            const float* __restrict__ w,
                            const float* __restrict__ bias,
                            float* __restrict__ out, int ldc)
{
    __shared__ float row[HID];
    int m = blockIdx.x;
    for (int k = threadIdx.x; k < HID; k += blockDim.x)
        row[k] = l1[(size_t)m * HID + k];
    __syncthreads();
    int n = threadIdx.x;
    if (n < D) {
        const float* wr = w + (size_t)n * HID;
        float acc = bias[n];
        for (int k = 0; k < HID; k++) acc += row[k] * wr[k];
        out[(size_t)m * ldc + n] = acc;
    }
}

// ----------------------------------------------------------------------------
// Host driver
// ----------------------------------------------------------------------------
static inline void launch_gemm(const float* A, int lda, const float* W,
                               const float* bias, float* C, int ldc,
                               int M, int N, int K, int act, int permute_bt = 0)
{
    dim3 grid(N / BN, M / BM);
    gemm_tf32_v2<<<grid, 256, GM_SMEM_BYTES>>>(A, lda, W, bias, C, ldc, M, N, K,
                                               act, permute_bt);
}

extern "C" void kernel_launch(void* const* d_in, const int* in_sizes, int n_in,
                              void* d_out, int out_size)
{
    const float* x       = (const float*)d_in[0];
    const float* p2l_w1  = (const float*)d_in[2];
    const float* p2l_b1  = (const float*)d_in[3];
    const float* p2l_w2  = (const float*)d_in[4];
    const float* p2l_b2  = (const float*)d_in[5];
    const float* enc_wih = (const float*)d_in[6];
    const float* enc_whh = (const float*)d_in[7];
    const float* enc_bih = (const float*)d_in[8];
    const float* enc_bhh = (const float*)d_in[9];
    const float* dec_wih = (const float*)d_in[10];
    const float* dec_whh = (const float*)d_in[11];
    const float* dec_bih = (const float*)d_in[12];
    const float* dec_bhh = (const float*)d_in[13];
    const float* l2p_w1  = (const float*)d_in[14];
    const float* l2p_b1  = (const float*)d_in[15];
    const float* l2p_w2  = (const float*)d_in[16];
    const float* l2p_b2  = (const float*)d_in[17];
    const float* l2s_w1  = (const float*)d_in[18];
    const float* l2s_b1  = (const float*)d_in[19];
    const float* l2s_w2  = (const float*)d_in[20];
    const float* l2s_b2  = (const float*)d_in[21];

    float* out = (float*)d_out;
    const int PREDS = B * P * D;
    float* rep_out = (out_size >= PREDS + B * H) ? (out + PREDS) : nullptr;

    float *p_buf1, *p_latent, *p_xp, *p_eout, *p_hb0, *p_hb1, *p_logits,
          *p_wts, *p_hs, *p_hs2, *p_hrow, *p_p0, *p_d1, *p_dinp, *p_gi, *p_l1,
          *p_wsw_enc, *p_wsw_dec;
    void* tmp;
#define SYM(dst, sym) cudaGetSymbolAddress(&tmp, sym); dst = (decltype(dst))tmp;
    SYM(p_buf1, g_buf1)   SYM(p_latent, g_latent) SYM(p_xp, g_xp)
    SYM(p_eout, g_eout)   SYM(p_hb0, g_hb0)       SYM(p_hb1, g_hb1)
    SYM(p_logits, g_logits) SYM(p_wts, g_wts)     SYM(p_hs, g_hs)
    SYM(p_hs2, g_hs2)     SYM(p_hrow, g_hrow)     SYM(p_p0, g_p0)
    SYM(p_d1, g_d1)       SYM(p_dinp, g_dinp)     SYM(p_gi, g_gi)
    SYM(p_l1, g_l1)       SYM(p_wsw_enc, g_wsw_enc) SYM(p_wsw_dec, g_wsw_dec)
#undef SYM

    cudaFuncSetAttribute(gru_step, cudaFuncAttributeMaxDynamicSharedMemorySize,
                         RC_SMEM_BYTES);
    cudaFuncSetAttribute(gemm_tf32_v2, cudaFuncAttributeMaxDynamicSharedMemorySize,
                         GM_SMEM_BYTES);

    // ---- one-time weight pre-swizzles (independent; launch early) ----
    swizzle_whh<<<64, 256>>>(enc_whh, p_wsw_enc);
    swizzle_whh<<<64, 256>>>(dec_whh, p_wsw_dec);

    // ---- par2lat(x) ----
    launch_gemm(x, D, p2l_w1, p2l_b1, p_buf1, HID, BT, HID, D, 1);
    launch_gemm(p_buf1, HID, p2l_w2, p2l_b2, p_latent, H, BT, H, HID, 1);

    // ---- xp = latent @ enc_wih^T + enc_bih, stored t-major [T, B, 3H] ----
    launch_gemm(p_latent, H, enc_wih, enc_bih, p_xp, H3, BT, H3, H, 0, 1);

    // ---- encoder recurrence: one fused launch per step (hT ping-pong) ----
    cudaMemsetAsync(p_hb0, 0, (size_t)B * H * sizeof(float));
    {
        float* hr = p_hb0;
        float* hw = p_hb1;
        for (int t = 0; t < T; t++) {
            gru_step<<<128, 512, RC_SMEM_BYTES>>>(
                p_wsw_enc, enc_bhh,
                p_xp + (size_t)t * B * H3, (size_t)H3,
                hr, hw,
                p_eout + (size_t)t * B * H, (size_t)H,
                nullptr);
            float* t2 = hr; hr = hw; hw = t2;
        }
    }

    // ---- attention pooling (rows in (t,b) order) ----
    launch_gemm(p_eout, H, l2s_w1, l2s_b1, p_buf1, HID, BT, HID, H, 1);
    logits_kernel<<<BT / 8, 256>>>(p_buf1, l2s_w2, l2s_b2, p_logits);
    softmax_kernel<<<B, T>>>(p_logits, p_wts);
    pool_kernel<<<B, 256>>>(p_eout, p_wts, p_hs, rep_out);

    // ---- autoregressive decode (hsT ping-pong + row-major copy for GEMM) ----
    gather_last<<<(B * D + 255) / 256, 256>>>(x, p_p0);
    float* hsT_read  = p_hs;
    float* hsT_write = p_hs2;
    for (int s = 0; s < P; s++) {
        const float* pin = (s == 0) ? p_p0 : (out + (size_t)(s - 1) * D);
        int plda = (s == 0) ? D : (P * D);
        launch_gemm(pin, plda, p2l_w1, p2l_b1, p_d1, HID, B, HID, D, 1);
        launch_gemm(p_d1, HID, p2l_w2, p2l_b2, p_dinp, H, B, H, HID, 1);
        launch_gemm(p_dinp, H, dec_wih, dec_bih, p_gi, H3, B, H3, H, 0);
        gru_step<<<128, 512, RC_SMEM_BYTES>>>(
            p_wsw_dec, dec_bhh, p_gi, (size_t)H3,
            hsT_read, hsT_write, nullptr, 0, p_hrow);
        launch_gemm(p_hrow, H, l2p_w1, l2p_b1, p_l1, HID, B, HID, H, 1);
        pred_kernel<<<B, 128>>>(p_l1, l2p_w2, l2p_b2,
                                out + (size_t)s * D, P * D);
        float* t2 = hsT_read; hsT_read = hsT_write; hsT_write = t2;
    }
}

// round 10
// speedup vs baseline: 1.5213x; 1.0775x over previous
#include <cuda_runtime.h>
#include <mma.h>
#include <cstdint>

using namespace nvcuda;

// Problem constants (fixed by the reference)
constexpr int B   = 256;
constexpr int T   = 256;
constexpr int D   = 72;
constexpr int HID = 512;
constexpr int H   = 1024;
constexpr int H3  = 3 * H;
constexpr int P   = 10;       // to_predict
constexpr int BT  = B * T;    // 65536

// ----------------------------------------------------------------------------
// Device scratch
// ----------------------------------------------------------------------------
__device__ float g_buf1  [(size_t)BT * HID];
__device__ float g_latent[(size_t)BT * H];
__device__ float g_xp    [(size_t)BT * H3];   // [T, B, 3H] (t-major)
__device__ float g_eout  [(size_t)BT * H];    // [T, B, H]  (t-major)
__device__ float g_hb0   [B * H];             // hF fragment-order layout
__device__ float g_hb1   [B * H];             // hF fragment-order layout
__device__ float g_logits[BT];                // index t*B + b
__device__ float g_wts   [BT];                // index t*B + b
__device__ float g_hs    [B * H];             // hF layout (decode ping)
__device__ float g_hs2   [B * H];             // hF layout (decode pong)
__device__ float g_hrow  [B * H];             // row-major h for decode l2p GEMM
__device__ float g_p0    [B * D];
__device__ float g_d1    [B * HID];
__device__ float g_dinp  [B * H];
__device__ float g_gi    [B * H3];
__device__ float g_l1    [B * HID];
// Pre-swizzled (fragment-order, tf32) weight slabs: 64 n-tiles x 49152 floats
constexpr int WSW_TILE = 128 * 6 * 64;        // 49152
__device__ float g_wsw_enc[(size_t)64 * WSW_TILE];
__device__ float g_wsw_dec[(size_t)64 * WSW_TILE];

// hF index: fragment-order h. For element (b, k):
//   k8 = k>>3, mb = b>>4, lane = (b&7)*4 + (k&3), reg = ((b>>3)&1) + 2*((k>>2)&1)
//   addr = ((k8*16 + mb)*32 + lane)*4 + reg
__device__ __forceinline__ size_t hf_idx(int b, int k) {
    return ((((size_t)(k >> 3) * 16 + (b >> 4)) * 32 +
             ((b & 7) * 4 + (k & 3))) << 2) +
           (((b >> 3) & 1) + 2 * ((k >> 2) & 1));
}

// ----------------------------------------------------------------------------
// Pipelined tf32 WMMA GEMM v2 (+ optional (b,t)->(t,b) output row permute).
// UNCHANGED (proven, ~118 TF/s).
// ----------------------------------------------------------------------------
#define BM 128
#define BN 128
#define BK 32
constexpr int GLDS = BK + 4;
constexpr int GBUF = (BM + BN) * GLDS;
constexpr int GM_SMEM_BYTES = 2 * GBUF * 4;

__device__ __forceinline__ void gm_load_tiles(
    const float* __restrict__ A, int lda,
    const float* __restrict__ W, int K,
    int bm, int bn, int kk, int tid,
    float4 ra[4], float4 rb[4])
{
#pragma unroll
    for (int i = 0; i < 4; i++) {
        int idx = tid + i * 256;
        int r   = idx >> 3;
        int c4  = (idx & 7) * 4;
        int gk  = kk + c4;
        const float* srcA = A + (size_t)(bm + r) * lda + gk;
        const float* srcB = W + (size_t)(bn + r) * K + gk;
        if (gk + 4 <= K) {
            ra[i] = *reinterpret_cast<const float4*>(srcA);
            rb[i] = *reinterpret_cast<const float4*>(srcB);
        } else {
            ra[i].x = (gk + 0 < K) ? srcA[0] : 0.f;
            ra[i].y = (gk + 1 < K) ? srcA[1] : 0.f;
            ra[i].z = (gk + 2 < K) ? srcA[2] : 0.f;
            ra[i].w = (gk + 3 < K) ? srcA[3] : 0.f;
            rb[i].x = (gk + 0 < K) ? srcB[0] : 0.f;
            rb[i].y = (gk + 1 < K) ? srcB[1] : 0.f;
            rb[i].z = (gk + 2 < K) ? srcB[2] : 0.f;
            rb[i].w = (gk + 3 < K) ? srcB[3] : 0.f;
        }
    }
}

__device__ __forceinline__ void gm_store_tiles(
    float* __restrict__ As, float* __restrict__ Bs, int tid,
    const float4 ra[4], const float4 rb[4])
{
#pragma unroll
    for (int i = 0; i < 4; i++) {
        int idx = tid + i * 256;
        int r   = idx >> 3;
        int c4  = (idx & 7) * 4;
        float* da = As + r * GLDS + c4;
        da[0] = wmma::__float_to_tf32(ra[i].x);
        da[1] = wmma::__float_to_tf32(ra[i].y);
        da[2] = wmma::__float_to_tf32(ra[i].z);
        da[3] = wmma::__float_to_tf32(ra[i].w);
        float* db = Bs + r * GLDS + c4;
        db[0] = wmma::__float_to_tf32(rb[i].x);
        db[1] = wmma::__float_to_tf32(rb[i].y);
        db[2] = wmma::__float_to_tf32(rb[i].z);
        db[3] = wmma::__float_to_tf32(rb[i].w);
    }
}

__global__ void __launch_bounds__(256, 1)
gemm_tf32_v2(const float* __restrict__ A, int lda,
             const float* __restrict__ W,
             const float* __restrict__ bias,
             float* __restrict__ C, int ldc,
             int M, int N, int K, int act, int permute_bt)
{
    extern __shared__ float sm[];
    float* Abuf[2] = { sm,               sm + GBUF };
    float* Bbuf[2] = { sm + BM * GLDS,   sm + GBUF + BM * GLDS };
    float* Cs = sm;

    const int bm  = blockIdx.y * BM;
    const int bn  = blockIdx.x * BN;
    const int tid = threadIdx.x;
    const int w   = tid >> 5;
    const int wm  = w & 3;
    const int wn  = w >> 2;

    wmma::fragment<wmma::accumulator, 16, 16, 8, float> c[2][4];
#pragma unroll
    for (int i = 0; i < 2; i++)
#pragma unroll
        for (int j = 0; j < 4; j++)
            wmma::fill_fragment(c[i][j], 0.0f);

    const int niter = (K + BK - 1) / BK;
    float4 ra[4], rb[4];

    gm_load_tiles(A, lda, W, K, bm, bn, 0, tid, ra, rb);
    gm_store_tiles(Abuf[0], Bbuf[0], tid, ra, rb);
    __syncthreads();

    for (int it = 0; it < niter; it++) {
        if (it + 1 < niter)
            gm_load_tiles(A, lda, W, K, bm, bn, (it + 1) * BK, tid, ra, rb);

        const float* As = Abuf[it & 1];
        const float* Bs = Bbuf[it & 1];
#pragma unroll
        for (int ks = 0; ks < 4; ks++) {
            wmma::fragment<wmma::matrix_a, 16, 16, 8, wmma::precision::tf32, wmma::row_major> af[2];
            wmma::fragment<wmma::matrix_b, 16, 16, 8, wmma::precision::tf32, wmma::col_major> bf[4];
#pragma unroll
            for (int i = 0; i < 2; i++)
                wmma::load_matrix_sync(af[i], As + (wm * 32 + i * 16) * GLDS + ks * 8, GLDS);
#pragma unroll
            for (int j = 0; j < 4; j++)
                wmma::load_matrix_sync(bf[j], Bs + (wn * 64 + j * 16) * GLDS + ks * 8, GLDS);
#pragma unroll
            for (int i = 0; i < 2; i++)
#pragma unroll
                for (int j = 0; j < 4; j++)
                    wmma::mma_sync(c[i][j], af[i], bf[j], c[i][j]);
        }

        if (it + 1 < niter)
            gm_store_tiles(Abuf[(it + 1) & 1], Bbuf[(it + 1) & 1], tid, ra, rb);
        __syncthreads();
    }

#pragma unroll
    for (int i = 0; i < 2; i++)
#pragma unroll
        for (int j = 0; j < 4; j++)
            wmma::store_matrix_sync(Cs + (wm * 32 + i * 16) * (BN + 4) + wn * 64 + j * 16,
                                    c[i][j], BN + 4, wmma::mem_row_major);
    __syncthreads();

#pragma unroll
    for (int i = 0; i < 16; i++) {
        int idx4 = tid + i * 256;
        int r    = idx4 >> 5;
        int c4   = (idx4 & 31) * 4;
        float4 v = *reinterpret_cast<const float4*>(Cs + r * (BN + 4) + c4);
        if (bias) {
            float4 bv = *reinterpret_cast<const float4*>(bias + bn + c4);
            v.x += bv.x; v.y += bv.y; v.z += bv.z; v.w += bv.w;
        }
        if (act == 1) {
            v.x = fmaxf(v.x, 0.f); v.y = fmaxf(v.y, 0.f);
            v.z = fmaxf(v.z, 0.f); v.w = fmaxf(v.w, 0.f);
        }
        int gr   = bm + r;
        int orow = permute_bt ? (((gr & 255) << 8) | (gr >> 8)) : gr;
        *reinterpret_cast<float4*>(C + (size_t)orow * ldc + bn + c4) = v;
    }
}

// ----------------------------------------------------------------------------
// tf32 helpers
// ----------------------------------------------------------------------------
__device__ __forceinline__ float sigf(float x) { return 1.f / (1.f + expf(-x)); }

__device__ __forceinline__ uint32_t f2tf32(float x) {
    uint32_t r;
    asm("cvt.rna.tf32.f32 %0, %1;" : "=r"(r) : "f"(x));
    return r;
}

__device__ __forceinline__ void mma_tf32(float d[4], const uint32_t a[4],
                                         uint32_t b0, uint32_t b1) {
    asm volatile(
        "mma.sync.aligned.m16n8k8.row.col.f32.tf32.tf32.f32 "
        "{%0,%1,%2,%3}, {%4,%5,%6,%7}, {%8,%9}, {%0,%1,%2,%3};"
        : "+f"(d[0]), "+f"(d[1]), "+f"(d[2]), "+f"(d[3])
        : "r"(a[0]), "r"(a[1]), "r"(a[2]), "r"(a[3]), "r"(b0), "r"(b1));
}

// ----------------------------------------------------------------------------
// One-time Whh pre-swizzle into mma-fragment order (tf32). Unchanged.
// ----------------------------------------------------------------------------
__global__ void swizzle_whh(const float* __restrict__ whh, float* __restrict__ wsw)
{
    int nt = blockIdx.x;          // 0..63
    int n0 = nt * 16;
    for (int i = threadIdx.x; i < 128 * 6 * 32; i += blockDim.x) {
        int lane  = i & 31;
        int pos   = i >> 5;       // 0..767
        int kstep = pos / 6;
        int g2    = pos % 6;
        int g  = g2 >> 1;
        int nj = g2 & 1;
        int q = lane >> 2, t = lane & 3;
        const float* src = whh + (size_t)(g * H + n0 + nj * 8 + q) * H + kstep * 8 + t;
        float2 v;
        v.x = __uint_as_float(f2tf32(src[0]));
        v.y = __uint_as_float(f2tf32(src[4]));
        *reinterpret_cast<float2*>(wsw + (size_t)nt * WSW_TILE + (size_t)pos * 64 + lane * 2) = v;
    }
}

// ----------------------------------------------------------------------------
// Fused single GRU step v6: h in fragment-order (hF) + pre-swizzled weights.
// Grid = 128 CTAs = 2 b-tiles x 64 n-tiles. 512 threads = 4 K-groups x 4
// m-warps. A loads: ONE float4 LDG per m16 half per iter (fully coalesced).
// Epilogue: each thread computes the 4 gate outputs of one hF float4 and
// writes it coalesced; h_old comes from the same float4 of hF_read.
// ----------------------------------------------------------------------------
constexpr int RC_LDA     = 20;                    // gate staging ld
constexpr int RC_GFLOATS = 3 * 128 * RC_LDA;      // 7680 floats
constexpr int RC_SMEM_BYTES = (WSW_TILE + RC_GFLOATS) * 4;  // 227328 B

__global__ void __launch_bounds__(512, 1)
gru_step(const float* __restrict__ wsw, const float* __restrict__ bhh,
         const float* __restrict__ gi, size_t gi_bstride,
         const float* __restrict__ hF_read, float* __restrict__ hF_write,
         float* __restrict__ eout_t, size_t eout_bstride,
         float* __restrict__ hrow_write)
{
    extern __shared__ float smem[];
    float* Wsm = smem;                 // 49152 floats, fragment-order tf32
    float* Gsm = smem + WSW_TILE;      // [3][128][20] gate staging

    const int tid  = threadIdx.x;
    const int lane = tid & 31;
    const int w    = tid >> 5;         // 0..15
    const int grp  = w >> 2;           // K group 0..3
    const int wm   = w & 3;            // m32 tile 0..3
    const int nt   = blockIdx.x & 63;
    const int bt   = blockIdx.x >> 6;
    const int b0   = bt * 128;
    const int n0   = nt * 16;

    // ---- preload pre-swizzled weight slab (coalesced float4 copy) ----
    {
        const float4* wsrc = reinterpret_cast<const float4*>(wsw + (size_t)nt * WSW_TILE);
        float4* wdst = reinterpret_cast<float4*>(Wsm);
        for (int i = tid; i < WSW_TILE / 4; i += 512)
            wdst[i] = wsrc[i];
    }
    __syncthreads();

    // ---- barrier-free main loop over this group's 32 k8-steps ----
    const float4* hF4 = reinterpret_cast<const float4*>(hF_read);
    const int k8base = grp * 32;
    const int mbb    = bt * 8 + wm * 2;   // m16 blocks mbb (mh=0), mbb+1 (mh=1)

    float acc[2][3][2][4];
#pragma unroll
    for (int mh = 0; mh < 2; mh++)
#pragma unroll
        for (int g = 0; g < 3; g++)
#pragma unroll
            for (int nj = 0; nj < 2; nj++)
#pragma unroll
                for (int e = 0; e < 4; e++) acc[mh][g][nj][e] = 0.f;

    float4 pf[2];
#pragma unroll
    for (int mh = 0; mh < 2; mh++)
        pf[mh] = hF4[((size_t)k8base * 16 + mbb + mh) * 32 + lane];

    for (int c = 0; c < 32; c++) {
        uint32_t A[2][4];
#pragma unroll
        for (int mh = 0; mh < 2; mh++) {
            A[mh][0] = f2tf32(pf[mh].x);
            A[mh][1] = f2tf32(pf[mh].y);
            A[mh][2] = f2tf32(pf[mh].z);
            A[mh][3] = f2tf32(pf[mh].w);
        }

        if (c < 31) {
#pragma unroll
            for (int mh = 0; mh < 2; mh++)
                pf[mh] = hF4[((size_t)(k8base + c + 1) * 16 + mbb + mh) * 32 + lane];
        }

        const int kstep = k8base + c;
        const float2* wrow = reinterpret_cast<const float2*>(Wsm + (size_t)(kstep * 6) * 64);
#pragma unroll
        for (int g = 0; g < 3; g++) {
#pragma unroll
            for (int nj = 0; nj < 2; nj++) {
                float2 bw = wrow[(g * 2 + nj) * 32 + lane];
                uint32_t b0r = __float_as_uint(bw.x);
                uint32_t b1r = __float_as_uint(bw.y);
                mma_tf32(acc[0][g][nj], A[0], b0r, b1r);
                mma_tf32(acc[1][g][nj], A[1], b0r, b1r);
            }
        }
    }

    // ---- combine K-group partials (deterministic sequential passes) ----
    const int q = lane >> 2;
    const int t = lane & 3;
    const int ccol = 2 * t;
#pragma unroll
    for (int pass = 3; pass >= 0; pass--) {
        if (grp == pass) {
#pragma unroll
            for (int mh = 0; mh < 2; mh++)
#pragma unroll
                for (int g = 0; g < 3; g++)
#pragma unroll
                    for (int nj = 0; nj < 2; nj++) {
                        int row = wm * 32 + mh * 16 + q;
                        float* b0p = Gsm + (g * 128 + row) * RC_LDA + nj * 8 + ccol;
                        float* b1p = Gsm + (g * 128 + row + 8) * RC_LDA + nj * 8 + ccol;
                        if (pass == 3) {
                            b0p[0] = acc[mh][g][nj][0];
                            b0p[1] = acc[mh][g][nj][1];
                            b1p[0] = acc[mh][g][nj][2];
                            b1p[1] = acc[mh][g][nj][3];
                        } else {
                            b0p[0] += acc[mh][g][nj][0];
                            b0p[1] += acc[mh][g][nj][1];
                            b1p[0] += acc[mh][g][nj][2];
                            b1p[1] += acc[mh][g][nj][3];
                        }
                    }
        }
        __syncthreads();
    }

    // ---- fused gate math: one hF float4 per thread ----
    {
        const int k8l  = tid >> 8;          // 0..1 (which k8 block of this n-tile)
        const int mbl  = (tid >> 5) & 7;    // 0..7 (m16 block within b-tile)
        const int ln   = tid & 31;
        const int bq   = ln >> 2;           // b&7
        const int nq   = ln & 3;            // nc&3
        const size_t fidx = ((size_t)(nt * 2 + k8l) * 16 + (bt * 8 + mbl)) * 32 + ln;

        float4 hv4 = hF4[fidx];
        float outv[4];
#pragma unroll
        for (int kh = 0; kh < 2; kh++) {
#pragma unroll
            for (int rh = 0; rh < 2; rh++) {
                int reg = rh + 2 * kh;
                int bl  = mbl * 16 + bq + 8 * rh;
                int nl  = k8l * 8 + nq + 4 * kh;
                int b   = b0 + bl;
                int nc  = n0 + nl;
                float hr = Gsm[(0 * 128 + bl) * RC_LDA + nl] + bhh[nc];
                float hz = Gsm[(1 * 128 + bl) * RC_LDA + nl] + bhh[H + nc];
                float hn = Gsm[(2 * 128 + bl) * RC_LDA + nl] + bhh[2 * H + nc];
                const float* gib = gi + (size_t)b * gi_bstride;
                float ir = gib[nc], iz = gib[H + nc], in_ = gib[2 * H + nc];
                float r  = sigf(ir + hr);
                float z  = sigf(iz + hz);
                float nn = tanhf(in_ + r * hn);
                float hv = (&hv4.x)[reg];
                float hnew = (1.f - z) * nn + z * hv;
                outv[reg] = hnew;
                if (eout_t) eout_t[(size_t)b * eout_bstride + nc] = hnew;
                if (hrow_write) hrow_write[(size_t)b * H + nc] = hnew;
            }
        }
        float4 o4 = make_float4(outv[0], outv[1], outv[2], outv[3]);
        reinterpret_cast<float4*>(hF_write)[fidx] = o4;
    }
}

// ----------------------------------------------------------------------------
// Small kernels (t-major indices; pool writes hF for decode)
// ----------------------------------------------------------------------------
__global__ void logits_kernel(const float* __restrict__ s1,
                              const float* __restrict__ w2,
                              const float* __restrict__ b2,
                              float* __restrict__ logits)
{
    int row  = blockIdx.x * 8 + (threadIdx.x >> 5);
    int lane = threadIdx.x & 31;
    const float* src = s1 + (size_t)row * HID;
    float acc = 0.f;
    for (int k = lane; k < HID; k += 32) acc += src[k] * w2[k];
#pragma unroll
    for (int o = 16; o > 0; o >>= 1) acc += __shfl_xor_sync(0xffffffffu, acc, o);
    if (lane == 0) logits[row] = acc + b2[0];
}

__global__ void softmax_kernel(const float* __restrict__ logits,
                               float* __restrict__ wts)
{
    __shared__ float sdata[T];
    int b = blockIdx.x, t = threadIdx.x;
    float v = logits[t * B + b];
    sdata[t] = v;
    __syncthreads();
    for (int s = T / 2; s > 0; s >>= 1) {
        if (t < s) sdata[t] = fmaxf(sdata[t], sdata[t + s]);
        __syncthreads();
    }
    float mx = sdata[0];
    __syncthreads();
    float e = expf(v - mx);
    sdata[t] = e;
    __syncthreads();
    for (int s = T / 2; s > 0; s >>= 1) {
        if (t < s) sdata[t] += sdata[t + s];
        __syncthreads();
    }
    wts[t * B + b] = e / sdata[0];
}

// eout is [T, B, H]; writes hsF (hF layout, for decode) + rep_out (row-major)
__global__ void pool_kernel(const float* __restrict__ eout,
                            const float* __restrict__ wts,
                            float* __restrict__ hsF,
                            float* __restrict__ rep_out)
{
    __shared__ float w[T];
    int b = blockIdx.x, tid = threadIdx.x;
    w[tid] = wts[tid * B + b];
    __syncthreads();
    for (int h0 = tid; h0 < H; h0 += blockDim.x) {
        const float* base = eout + (size_t)b * H + h0;
        float acc = 0.f;
#pragma unroll 4
        for (int t = 0; t < T; t++) acc += w[t] * base[(size_t)t * B * H];
        hsF[hf_idx(b, h0)] = acc;
        if (rep_out) rep_out[b * H + h0] = acc;
    }
}

__global__ void gather_last(const float* __restrict__ x, float* __restrict__ p0)
{
    int idx = blockIdx.x * blockDim.x + threadIdx.x;
    if (idx >= B * D) return;
    int b = idx / D, dd = idx % D;
    p0[idx] = x[((size_t)b * T + (T - 1)) * D + dd];
}

__global__ void pred_kernel(const float* __restrict__ l1,
                            const float* __restrict__ w,
                            const float* __restrict__ bias,
                            float* __restrict__ out, int ldc)
{
    __shared__ float row[HID];
    int m = blockIdx.x;
    for (int k = threadIdx.x; k < HID; k += blockDim.x)
        row[k] = l1[(size_t)m * HID + k];
    __syncthreads();
    int n = threadIdx.x;
    if (n < D) {
        const float* wr = w + (size_t)n * HID;
        float acc = bias[n];
        for (int k = 0; k < HID; k++) acc += row[k] * wr[k];
        out[(size_t)m * ldc + n] = acc;
    }
}

// ----------------------------------------------------------------------------
// Host driver
// ----------------------------------------------------------------------------
static inline void launch_gemm(const float* A, int lda, const float* W,
                               const float* bias, float* C, int ldc,
                               int M, int N, int K, int act, int permute_bt = 0)
{
    dim3 grid(N / BN, M / BM);
    gemm_tf32_v2<<<grid, 256, GM_SMEM_BYTES>>>(A, lda, W, bias, C, ldc, M, N, K,
                                               act, permute_bt);
}

extern "C" void kernel_launch(void* const* d_in, const int* in_sizes, int n_in,
                              void* d_out, int out_size)
{
    const float* x       = (const float*)d_in[0];
    const float* p2l_w1  = (const float*)d_in[2];
    const float* p2l_b1  = (const float*)d_in[3];
    const float* p2l_w2  = (const float*)d_in[4];
    const float* p2l_b2  = (const float*)d_in[5];
    const float* enc_wih = (const float*)d_in[6];
    const float* enc_whh = (const float*)d_in[7];
    const float* enc_bih = (const float*)d_in[8];
    const float* enc_bhh = (const float*)d_in[9];
    const float* dec_wih = (const float*)d_in[10];
    const float* dec_whh = (const float*)d_in[11];
    const float* dec_bih = (const float*)d_in[12];
    const float* dec_bhh = (const float*)d_in[13];
    const float* l2p_w1  = (const float*)d_in[14];
    const float* l2p_b1  = (const float*)d_in[15];
    const float* l2p_w2  = (const float*)d_in[16];
    const float* l2p_b2  = (const float*)d_in[17];
    const float* l2s_w1  = (const float*)d_in[18];
    const float* l2s_b1  = (const float*)d_in[19];
    const float* l2s_w2  = (const float*)d_in[20];
    const float* l2s_b2  = (const float*)d_in[21];

    float* out = (float*)d_out;
    const int PREDS = B * P * D;
    float* rep_out = (out_size >= PREDS + B * H) ? (out + PREDS) : nullptr;

    float *p_buf1, *p_latent, *p_xp, *p_eout, *p_hb0, *p_hb1, *p_logits,
          *p_wts, *p_hs, *p_hs2, *p_hrow, *p_p0, *p_d1, *p_dinp, *p_gi, *p_l1,
          *p_wsw_enc, *p_wsw_dec;
    void* tmp;
#define SYM(dst, sym) cudaGetSymbolAddress(&tmp, sym); dst = (decltype(dst))tmp;
    SYM(p_buf1, g_buf1)   SYM(p_latent, g_latent) SYM(p_xp, g_xp)
    SYM(p_eout, g_eout)   SYM(p_hb0, g_hb0)       SYM(p_hb1, g_hb1)
    SYM(p_logits, g_logits) SYM(p_wts, g_wts)     SYM(p_hs, g_hs)
    SYM(p_hs2, g_hs2)     SYM(p_hrow, g_hrow)     SYM(p_p0, g_p0)
    SYM(p_d1, g_d1)       SYM(p_dinp, g_dinp)     SYM(p_gi, g_gi)
    SYM(p_l1, g_l1)       SYM(p_wsw_enc, g_wsw_enc) SYM(p_wsw_dec, g_wsw_dec)
#undef SYM

    cudaFuncSetAttribute(gru_step, cudaFuncAttributeMaxDynamicSharedMemorySize,
                         RC_SMEM_BYTES);
    cudaFuncSetAttribute(gemm_tf32_v2, cudaFuncAttributeMaxDynamicSharedMemorySize,
                         GM_SMEM_BYTES);

    // ---- one-time weight pre-swizzles ----
    swizzle_whh<<<64, 256>>>(enc_whh, p_wsw_enc);
    swizzle_whh<<<64, 256>>>(dec_whh, p_wsw_dec);

    // ---- par2lat(x) ----
    launch_gemm(x, D, p2l_w1, p2l_b1, p_buf1, HID, BT, HID, D, 1);
    launch_gemm(p_buf1, HID, p2l_w2, p2l_b2, p_latent, H, BT, H, HID, 1);

    // ---- xp = latent @ enc_wih^T + enc_bih, stored t-major [T, B, 3H] ----
    launch_gemm(p_latent, H, enc_wih, enc_bih, p_xp, H3, BT, H3, H, 0, 1);

    // ---- encoder recurrence: one fused launch per step (hF ping-pong) ----
    cudaMemsetAsync(p_hb0, 0, (size_t)B * H * sizeof(float));
    {
        float* hr = p_hb0;
        float* hw = p_hb1;
        for (int t = 0; t < T; t++) {
            gru_step<<<128, 512, RC_SMEM_BYTES>>>(
                p_wsw_enc, enc_bhh,
                p_xp + (size_t)t * B * H3, (size_t)H3,
                hr, hw,
                p_eout + (size_t)t * B * H, (size_t)H,
                nullptr);
            float* t2 = hr; hr = hw; hw = t2;
        }
    }

    // ---- attention pooling (rows in (t,b) order) ----
    launch_gemm(p_eout, H, l2s_w1, l2s_b1, p_buf1, HID, BT, HID, H, 1);
    logits_kernel<<<BT / 8, 256>>>(p_buf1, l2s_w2, l2s_b2, p_logits);
    softmax_kernel<<<B, T>>>(p_logits, p_wts);
    pool_kernel<<<B, 256>>>(p_eout, p_wts, p_hs, rep_out);

    // ---- autoregressive decode (hF ping-pong + row-major copy for GEMM) ----
    gather_last<<<(B * D + 255) / 256, 256>>>(x, p_p0);
    float* hF_read  = p_hs;
    float* hF_write = p_hs2;
    for (int s = 0; s < P; s++) {
        const float* pin = (s == 0) ? p_p0 : (out + (size_t)(s - 1) * D);
        int plda = (s == 0) ? D : (P * D);
        launch_gemm(pin, plda, p2l_w1, p2l_b1, p_d1, HID, B, HID, D, 1);
        launch_gemm(p_d1, HID, p2l_w2, p2l_b2, p_dinp, H, B, H, HID, 1);
        launch_gemm(p_dinp, H, dec_wih, dec_bih, p_gi, H3, B, H3, H, 0);
        gru_step<<<128, 512, RC_SMEM_BYTES>>>(
            p_wsw_dec, dec_bhh, p_gi, (size_t)H3,
            hF_read, hF_write, nullptr, 0, p_hrow);
        launch_gemm(p_hrow, H, l2p_w1, l2p_b1, p_l1, HID, B, HID, H, 1);
        pred_kernel<<<B, 128>>>(p_l1, l2p_w2, l2p_b2,
                                out + (size_t)s * D, P * D);
        float* t2 = hF_read; hF_read = hF_write; hF_write = t2;
    }
}

// round 11
// speedup vs baseline: 1.6605x; 1.0915x over previous
#include <cuda_runtime.h>
#include <mma.h>
#include <cstdint>

using namespace nvcuda;

// Problem constants (fixed by the reference)
constexpr int B   = 256;
constexpr int T   = 256;
constexpr int D   = 72;
constexpr int HID = 512;
constexpr int H   = 1024;
constexpr int H3  = 3 * H;
constexpr int P   = 10;       // to_predict
constexpr int BT  = B * T;    // 65536

// ----------------------------------------------------------------------------
// Device scratch
// ----------------------------------------------------------------------------
__device__ float g_buf1  [(size_t)BT * HID];
__device__ float g_latent[(size_t)BT * H];
__device__ float g_xp    [(size_t)BT * H3];   // [T, B, 3H] (t-major)
__device__ float g_eout  [(size_t)BT * H];    // [T, B, H]  (t-major)
__device__ float g_hb0   [B * H];             // hF fragment-order layout
__device__ float g_hb1   [B * H];
__device__ float g_logits[BT];                // index t*B + b
__device__ float g_wts   [BT];
__device__ float g_hs    [B * H];             // hF layout (decode ping)
__device__ float g_hs2   [B * H];             // hF layout (decode pong)
__device__ float g_hrow  [B * H];             // row-major h for decode l2p GEMM
__device__ float g_p0    [B * D];
__device__ float g_d1    [B * HID];
__device__ float g_dinp  [B * H];
__device__ float g_gi    [B * H3];
__device__ float g_l1    [B * HID];
// Pre-swizzled (fragment-order, tf32) GRU weight slabs
constexpr int WSW_TILE = 128 * 6 * 64;        // 49152
__device__ float g_wsw_enc[(size_t)64 * WSW_TILE];
__device__ float g_wsw_dec[(size_t)64 * WSW_TILE];
// tf32-pre-rounded GEMM weights (same layout as inputs)
constexpr size_t WT_P2L1   = 0;                              // 512*72
constexpr size_t WT_P2L2   = WT_P2L1 + 512 * 72;             // 1024*512
constexpr size_t WT_ENCWIH = WT_P2L2 + 1024 * 512;           // 3072*1024
constexpr size_t WT_L2S1   = WT_ENCWIH + (size_t)3072 * 1024;// 512*1024
constexpr size_t WT_DECWIH = WT_L2S1 + 512 * 1024;           // 3072*1024
constexpr size_t WT_L2P1   = WT_DECWIH + (size_t)3072 * 1024;// 512*1024
constexpr size_t WT_TOTAL  = WT_L2P1 + 512 * 1024;
__device__ float g_wtf[WT_TOTAL];

__device__ __forceinline__ size_t hf_idx(int b, int k) {
    return ((((size_t)(k >> 3) * 16 + (b >> 4)) * 32 +
             ((b & 7) * 4 + (k & 3))) << 2) +
           (((b >> 3) & 1) + 2 * ((k >> 2) & 1));
}

// ----------------------------------------------------------------------------
// tf32 helpers
// ----------------------------------------------------------------------------
__device__ __forceinline__ float sigf(float x) { return 1.f / (1.f + expf(-x)); }

__device__ __forceinline__ uint32_t f2tf32(float x) {
    uint32_t r;
    asm("cvt.rna.tf32.f32 %0, %1;" : "=r"(r) : "f"(x));
    return r;
}

__device__ __forceinline__ void mma_tf32(float d[4], const uint32_t a[4],
                                         uint32_t b0, uint32_t b1) {
    asm volatile(
        "mma.sync.aligned.m16n8k8.row.col.f32.tf32.tf32.f32 "
        "{%0,%1,%2,%3}, {%4,%5,%6,%7}, {%8,%9}, {%0,%1,%2,%3};"
        : "+f"(d[0]), "+f"(d[1]), "+f"(d[2]), "+f"(d[3])
        : "r"(a[0]), "r"(a[1]), "r"(a[2]), "r"(a[3]), "r"(b0), "r"(b1));
}

__device__ __forceinline__ uint32_t smem_u32(const void* p) {
    return (uint32_t)__cvta_generic_to_shared(p);
}
__device__ __forceinline__ void cp16(uint32_t dst, const void* src) {
    asm volatile("cp.async.ca.shared.global [%0], [%1], 16;" :: "r"(dst), "l"(src));
}

// one-time tf32 rounding of a weight buffer (n multiple of 4)
__global__ void cvt_tf32_buf(const float* __restrict__ src,
                             float* __restrict__ dst, int n4)
{
    int i = blockIdx.x * blockDim.x + threadIdx.x;
    if (i >= n4) return;
    float4 v = reinterpret_cast<const float4*>(src)[i];
    v.x = __uint_as_float(f2tf32(v.x));
    v.y = __uint_as_float(f2tf32(v.y));
    v.z = __uint_as_float(f2tf32(v.z));
    v.w = __uint_as_float(f2tf32(v.w));
    reinterpret_cast<float4*>(dst)[i] = v;
}

// ----------------------------------------------------------------------------
// GEMM v3: cp.async 3-stage pipeline, pre-tf32 weights, fragment-cvt on A.
// C[M,N] = act(A[M,K] * W[N,K]^T + bias); tile 128x128x32; 8 warps (4x2).
// W must be tf32-pre-rounded. Optional (b,t)->(t,b) output row permute.
// ----------------------------------------------------------------------------
#define BM 128
#define BN 128
#define BK 32
constexpr int GLDS = BK + 4;                       // 36 floats (16B-aligned rows)
constexpr int STG  = (BM + BN) * GLDS;             // 9216 floats per stage
constexpr int GM_SMEM_BYTES = 3 * STG * 4;         // 110592 B

__device__ __forceinline__ void cp_stage(
    float* st, const float* __restrict__ A, int lda,
    const float* __restrict__ W, int K,
    int bm, int bn, int kk, int tid)
{
#pragma unroll
    for (int i = 0; i < 4; i++) {
        int idx = tid + i * 256;
        int r   = idx >> 3;
        int c4  = (idx & 7) * 4;
        int gk  = kk + c4;
        float* da = st + r * GLDS + c4;
        float* db = st + (BM + r) * GLDS + c4;
        const float* sa = A + (size_t)(bm + r) * lda + gk;
        const float* sb = W + (size_t)(bn + r) * K + gk;
        if (gk + 4 <= K) {
            cp16(smem_u32(da), sa);
            cp16(smem_u32(db), sb);
        } else {
            float4 va, vb;
            va.x = (gk + 0 < K) ? sa[0] : 0.f;  vb.x = (gk + 0 < K) ? sb[0] : 0.f;
            va.y = (gk + 1 < K) ? sa[1] : 0.f;  vb.y = (gk + 1 < K) ? sb[1] : 0.f;
            va.z = (gk + 2 < K) ? sa[2] : 0.f;  vb.z = (gk + 2 < K) ? sb[2] : 0.f;
            va.w = (gk + 3 < K) ? sa[3] : 0.f;  vb.w = (gk + 3 < K) ? sb[3] : 0.f;
            *reinterpret_cast<float4*>(da) = va;
            *reinterpret_cast<float4*>(db) = vb;
        }
    }
    asm volatile("cp.async.commit_group;");
}

__global__ void __launch_bounds__(256, 2)
gemm_tf32_v3(const float* __restrict__ A, int lda,
             const float* __restrict__ W,
             const float* __restrict__ bias,
             float* __restrict__ C, int ldc,
             int M, int N, int K, int act, int permute_bt)
{
    extern __shared__ float sm[];
    float* Cs = sm;   // epilogue alias (needs 128*132 floats < STG*3)

    const int bm  = blockIdx.y * BM;
    const int bn  = blockIdx.x * BN;
    const int tid = threadIdx.x;
    const int w   = tid >> 5;
    const int wm  = w & 3;
    const int wn  = w >> 2;

    wmma::fragment<wmma::accumulator, 16, 16, 8, float> c[2][4];
#pragma unroll
    for (int i = 0; i < 2; i++)
#pragma unroll
        for (int j = 0; j < 4; j++)
            wmma::fill_fragment(c[i][j], 0.0f);

    const int niter = (K + BK - 1) / BK;

    cp_stage(sm, A, lda, W, K, bm, bn, 0, tid);
    if (niter > 1) cp_stage(sm + STG, A, lda, W, K, bm, bn, BK, tid);

    for (int it = 0; it < niter; it++) {
        if (it + 1 < niter) asm volatile("cp.async.wait_group 1;");
        else                asm volatile("cp.async.wait_group 0;");
        __syncthreads();
        if (it + 2 < niter)
            cp_stage(sm + ((it + 2) % 3) * STG, A, lda, W, K, bm, bn,
                     (it + 2) * BK, tid);

        const float* As = sm + (it % 3) * STG;
        const float* Bs = As + BM * GLDS;
#pragma unroll
        for (int ks = 0; ks < 4; ks++) {
            wmma::fragment<wmma::matrix_a, 16, 16, 8, wmma::precision::tf32, wmma::row_major> af[2];
            wmma::fragment<wmma::matrix_b, 16, 16, 8, wmma::precision::tf32, wmma::col_major> bf[4];
#pragma unroll
            for (int i = 0; i < 2; i++) {
                wmma::load_matrix_sync(af[i], As + (wm * 32 + i * 16) * GLDS + ks * 8, GLDS);
#pragma unroll
                for (int e = 0; e < af[i].num_elements; e++)
                    af[i].x[e] = wmma::__float_to_tf32(af[i].x[e]);
            }
#pragma unroll
            for (int j = 0; j < 4; j++)
                wmma::load_matrix_sync(bf[j], Bs + (wn * 64 + j * 16) * GLDS + ks * 8, GLDS);
#pragma unroll
            for (int i = 0; i < 2; i++)
#pragma unroll
                for (int j = 0; j < 4; j++)
                    wmma::mma_sync(c[i][j], af[i], bf[j], c[i][j]);
        }
    }

    __syncthreads();
#pragma unroll
    for (int i = 0; i < 2; i++)
#pragma unroll
        for (int j = 0; j < 4; j++)
            wmma::store_matrix_sync(Cs + (wm * 32 + i * 16) * (BN + 4) + wn * 64 + j * 16,
                                    c[i][j], BN + 4, wmma::mem_row_major);
    __syncthreads();

#pragma unroll
    for (int i = 0; i < 16; i++) {
        int idx4 = tid + i * 256;
        int r    = idx4 >> 5;
        int c4   = (idx4 & 31) * 4;
        float4 v = *reinterpret_cast<const float4*>(Cs + r * (BN + 4) + c4);
        if (bias) {
            float4 bv = *reinterpret_cast<const float4*>(bias + bn + c4);
            v.x += bv.x; v.y += bv.y; v.z += bv.z; v.w += bv.w;
        }
        if (act == 1) {
            v.x = fmaxf(v.x, 0.f); v.y = fmaxf(v.y, 0.f);
            v.z = fmaxf(v.z, 0.f); v.w = fmaxf(v.w, 0.f);
        }
        int gr   = bm + r;
        int orow = permute_bt ? (((gr & 255) << 8) | (gr >> 8)) : gr;
        *reinterpret_cast<float4*>(C + (size_t)orow * ldc + bn + c4) = v;
    }
}

// ----------------------------------------------------------------------------
// One-time Whh pre-swizzle into mma-fragment order (tf32). Unchanged.
// ----------------------------------------------------------------------------
__global__ void swizzle_whh(const float* __restrict__ whh, float* __restrict__ wsw)
{
    int nt = blockIdx.x;          // 0..63
    int n0 = nt * 16;
    for (int i = threadIdx.x; i < 128 * 6 * 32; i += blockDim.x) {
        int lane  = i & 31;
        int pos   = i >> 5;       // 0..767
        int kstep = pos / 6;
        int g2    = pos % 6;
        int g  = g2 >> 1;
        int nj = g2 & 1;
        int q = lane >> 2, t = lane & 3;
        const float* src = whh + (size_t)(g * H + n0 + nj * 8 + q) * H + kstep * 8 + t;
        float2 v;
        v.x = __uint_as_float(f2tf32(src[0]));
        v.y = __uint_as_float(f2tf32(src[4]));
        *reinterpret_cast<float2*>(wsw + (size_t)nt * WSW_TILE + (size_t)pos * 64 + lane * 2) = v;
    }
}

// ----------------------------------------------------------------------------
// Fused single GRU step v6 (UNCHANGED from round 10 — proven, ~20us)
// ----------------------------------------------------------------------------
constexpr int RC_LDA     = 20;
constexpr int RC_GFLOATS = 3 * 128 * RC_LDA;
constexpr int RC_SMEM_BYTES = (WSW_TILE + RC_GFLOATS) * 4;  // 227328 B

__global__ void __launch_bounds__(512, 1)
gru_step(const float* __restrict__ wsw, const float* __restrict__ bhh,
         const float* __restrict__ gi, size_t gi_bstride,
         const float* __restrict__ hF_read, float* __restrict__ hF_write,
         float* __restrict__ eout_t, size_t eout_bstride,
         float* __restrict__ hrow_write)
{
    extern __shared__ float smem[];
    float* Wsm = smem;
    float* Gsm = smem + WSW_TILE;

    const int tid  = threadIdx.x;
    const int lane = tid & 31;
    const int w    = tid >> 5;
    const int grp  = w >> 2;
    const int wm   = w & 3;
    const int nt   = blockIdx.x & 63;
    const int bt   = blockIdx.x >> 6;
    const int b0   = bt * 128;
    const int n0   = nt * 16;

    {
        const float4* wsrc = reinterpret_cast<const float4*>(wsw + (size_t)nt * WSW_TILE);
        float4* wdst = reinterpret_cast<float4*>(Wsm);
        for (int i = tid; i < WSW_TILE / 4; i += 512)
            wdst[i] = wsrc[i];
    }
    __syncthreads();

    const float4* hF4 = reinterpret_cast<const float4*>(hF_read);
    const int k8base = grp * 32;
    const int mbb    = bt * 8 + wm * 2;

    float acc[2][3][2][4];
#pragma unroll
    for (int mh = 0; mh < 2; mh++)
#pragma unroll
        for (int g = 0; g < 3; g++)
#pragma unroll
            for (int nj = 0; nj < 2; nj++)
#pragma unroll
                for (int e = 0; e < 4; e++) acc[mh][g][nj][e] = 0.f;

    float4 pf[2];
#pragma unroll
    for (int mh = 0; mh < 2; mh++)
        pf[mh] = hF4[((size_t)k8base * 16 + mbb + mh) * 32 + lane];

    for (int c = 0; c < 32; c++) {
        uint32_t A[2][4];
#pragma unroll
        for (int mh = 0; mh < 2; mh++) {
            A[mh][0] = f2tf32(pf[mh].x);
            A[mh][1] = f2tf32(pf[mh].y);
            A[mh][2] = f2tf32(pf[mh].z);
            A[mh][3] = f2tf32(pf[mh].w);
        }

        if (c < 31) {
#pragma unroll
            for (int mh = 0; mh < 2; mh++)
                pf[mh] = hF4[((size_t)(k8base + c + 1) * 16 + mbb + mh) * 32 + lane];
        }

        const int kstep = k8base + c;
        const float2* wrow = reinterpret_cast<const float2*>(Wsm + (size_t)(kstep * 6) * 64);
#pragma unroll
        for (int g = 0; g < 3; g++) {
#pragma unroll
            for (int nj = 0; nj < 2; nj++) {
                float2 bw = wrow[(g * 2 + nj) * 32 + lane];
                uint32_t b0r = __float_as_uint(bw.x);
                uint32_t b1r = __float_as_uint(bw.y);
                mma_tf32(acc[0][g][nj], A[0], b0r, b1r);
                mma_tf32(acc[1][g][nj], A[1], b0r, b1r);
            }
        }
    }

    const int q = lane >> 2;
    const int t = lane & 3;
    const int ccol = 2 * t;
#pragma unroll
    for (int pass = 3; pass >= 0; pass--) {
        if (grp == pass) {
#pragma unroll
            for (int mh = 0; mh < 2; mh++)
#pragma unroll
                for (int g = 0; g < 3; g++)
#pragma unroll
                    for (int nj = 0; nj < 2; nj++) {
                        int row = wm * 32 + mh * 16 + q;
                        float* b0p = Gsm + (g * 128 + row) * RC_LDA + nj * 8 + ccol;
                        float* b1p = Gsm + (g * 128 + row + 8) * RC_LDA + nj * 8 + ccol;
                        if (pass == 3) {
                            b0p[0] = acc[mh][g][nj][0];
                            b0p[1] = acc[mh][g][nj][1];
                            b1p[0] = acc[mh][g][nj][2];
                            b1p[1] = acc[mh][g][nj][3];
                        } else {
                            b0p[0] += acc[mh][g][nj][0];
                            b0p[1] += acc[mh][g][nj][1];
                            b1p[0] += acc[mh][g][nj][2];
                            b1p[1] += acc[mh][g][nj][3];
                        }
                    }
        }
        __syncthreads();
    }

    {
        const int k8l  = tid >> 8;
        const int mbl  = (tid >> 5) & 7;
        const int ln   = tid & 31;
        const int bq   = ln >> 2;
        const int nq   = ln & 3;
        const size_t fidx = ((size_t)(nt * 2 + k8l) * 16 + (bt * 8 + mbl)) * 32 + ln;

        float4 hv4 = hF4[fidx];
        float outv[4];
#pragma unroll
        for (int kh = 0; kh < 2; kh++) {
#pragma unroll
            for (int rh = 0; rh < 2; rh++) {
                int reg = rh + 2 * kh;
                int bl  = mbl * 16 + bq + 8 * rh;
                int nl  = k8l * 8 + nq + 4 * kh;
                int b   = b0 + bl;
                int nc  = n0 + nl;
                float hr = Gsm[(0 * 128 + bl) * RC_LDA + nl] + bhh[nc];
                float hz = Gsm[(1 * 128 + bl) * RC_LDA + nl] + bhh[H + nc];
                float hn = Gsm[(2 * 128 + bl) * RC_LDA + nl] + bhh[2 * H + nc];
                const float* gib = gi + (size_t)b * gi_bstride;
                float ir = gib[nc], iz = gib[H + nc], in_ = gib[2 * H + nc];
                float r  = sigf(ir + hr);
                float z  = sigf(iz + hz);
                float nn = tanhf(in_ + r * hn);
                float hv = (&hv4.x)[reg];
                float hnew = (1.f - z) * nn + z * hv;
                outv[reg] = hnew;
                if (eout_t) eout_t[(size_t)b * eout_bstride + nc] = hnew;
                if (hrow_write) hrow_write[(size_t)b * H + nc] = hnew;
            }
        }
        float4 o4 = make_float4(outv[0], outv[1], outv[2], outv[3]);
        reinterpret_cast<float4*>(hF_write)[fidx] = o4;
    }
}

// ----------------------------------------------------------------------------
// Small kernels (unchanged)
// ----------------------------------------------------------------------------
__global__ void logits_kernel(const float* __restrict__ s1,
                              const float* __restrict__ w2,
                              const float* __restrict__ b2,
                              float* __restrict__ logits)
{
    int row  = blockIdx.x * 8 + (threadIdx.x >> 5);
    int lane = threadIdx.x & 31;
    const float* src = s1 + (size_t)row * HID;
    float acc = 0.f;
    for (int k = lane; k < HID; k += 32) acc += src[k] * w2[k];
#pragma unroll
    for (int o = 16; o > 0; o >>= 1) acc += __shfl_xor_sync(0xffffffffu, acc, o);
    if (lane == 0) logits[row] = acc + b2[0];
}

__global__ void softmax_kernel(const float* __restrict__ logits,
                               float* __restrict__ wts)
{
    __shared__ float sdata[T];
    int b = blockIdx.x, t = threadIdx.x;
    float v = logits[t * B + b];
    sdata[t] = v;
    __syncthreads();
    for (int s = T / 2; s > 0; s >>= 1) {
        if (t < s) sdata[t] = fmaxf(sdata[t], sdata[t + s]);
        __syncthreads();
    }
    float mx = sdata[0];
    __syncthreads();
    float e = expf(v - mx);
    sdata[t] = e;
    __syncthreads();
    for (int s = T / 2; s > 0; s >>= 1) {
        if (t < s) sdata[t] += sdata[t + s];
        __syncthreads();
    }
    wts[t * B + b] = e / sdata[0];
}

__global__ void pool_kernel(const float* __restrict__ eout,
                            const float* __restrict__ wts,
                            float* __restrict__ hsF,
                            float* __restrict__ rep_out)
{
    __shared__ float w[T];
    int b = blockIdx.x, tid = threadIdx.x;
    w[tid] = wts[tid * B + b];
    __syncthreads();
    for (int h0 = tid; h0 < H; h0 += blockDim.x) {
        const float* base = eout + (size_t)b * H + h0;
        float acc = 0.f;
#pragma unroll 4
        for (int t = 0; t < T; t++) acc += w[t] * base[(size_t)t * B * H];
        hsF[hf_idx(b, h0)] = acc;
        if (rep_out) rep_out[b * H + h0] = acc;
    }
}

__global__ void gather_last(const float* __restrict__ x, float* __restrict__ p0)
{
    int idx = blockIdx.x * blockDim.x + threadIdx.x;
    if (idx >= B * D) return;
    int b = idx / D, dd = idx % D;
    p0[idx] = x[((size_t)b * T + (T - 1)) * D + dd];
}

__global__ void pred_kernel(const float* __restrict__ l1,
                            const float* __restrict__ w,
                            const float* __restrict__ bias,
                            float* __restrict__ out, int ldc)
{
    __shared__ float row[HID];
    int m = blockIdx.x;
    for (int k = threadIdx.x; k < HID; k += blockDim.x)
        row[k] = l1[(size_t)m * HID + k];
    __syncthreads();
    int n = threadIdx.x;
    if (n < D) {
        const float* wr = w + (size_t)n * HID;
        float acc = bias[n];
        for (int k = 0; k < HID; k++) acc += row[k] * wr[k];
        out[(size_t)m * ldc + n] = acc;
    }
}

// ----------------------------------------------------------------------------
// Host driver
// ----------------------------------------------------------------------------
static inline void launch_gemm(const float* A, int lda, const float* W,
                               const float* bias, float* C, int ldc,
                               int M, int N, int K, int act, int permute_bt = 0)
{
    dim3 grid(N / BN, M / BM);
    gemm_tf32_v3<<<grid, 256, GM_SMEM_BYTES>>>(A, lda, W, bias, C, ldc, M, N, K,
                                               act, permute_bt);
}

extern "C" void kernel_launch(void* const* d_in, const int* in_sizes, int n_in,
                              void* d_out, int out_size)
{
    const float* x       = (const float*)d_in[0];
    const float* p2l_w1  = (const float*)d_in[2];
    const float* p2l_b1  = (const float*)d_in[3];
    const float* p2l_w2  = (const float*)d_in[4];
    const float* p2l_b2  = (const float*)d_in[5];
    const float* enc_wih = (const float*)d_in[6];
    const float* enc_whh = (const float*)d_in[7];
    const float* enc_bih = (const float*)d_in[8];
    const float* enc_bhh = (const float*)d_in[9];
    const float* dec_wih = (const float*)d_in[10];
    const float* dec_whh = (const float*)d_in[11];
    const float* dec_bih = (const float*)d_in[12];
    const float* dec_bhh = (const float*)d_in[13];
    const float* l2p_w1  = (const float*)d_in[14];
    const float* l2p_b1  = (const float*)d_in[15];
    const float* l2p_w2  = (const float*)d_in[16];
    const float* l2p_b2  = (const float*)d_in[17];
    const float* l2s_w1  = (const float*)d_in[18];
    const float* l2s_b1  = (const float*)d_in[19];
    const float* l2s_w2  = (const float*)d_in[20];
    const float* l2s_b2  = (const float*)d_in[21];

    float* out = (float*)d_out;
    const int PREDS = B * P * D;
    float* rep_out = (out_size >= PREDS + B * H) ? (out + PREDS) : nullptr;

    float *p_buf1, *p_latent, *p_xp, *p_eout, *p_hb0, *p_hb1, *p_logits,
          *p_wts, *p_hs, *p_hs2, *p_hrow, *p_p0, *p_d1, *p_dinp, *p_gi, *p_l1,
          *p_wsw_enc, *p_wsw_dec, *p_wtf;
    void* tmp;
#define SYM(dst, sym) cudaGetSymbolAddress(&tmp, sym); dst = (decltype(dst))tmp;
    SYM(p_buf1, g_buf1)   SYM(p_latent, g_latent) SYM(p_xp, g_xp)
    SYM(p_eout, g_eout)   SYM(p_hb0, g_hb0)       SYM(p_hb1, g_hb1)
    SYM(p_logits, g_logits) SYM(p_wts, g_wts)     SYM(p_hs, g_hs)
    SYM(p_hs2, g_hs2)     SYM(p_hrow, g_hrow)     SYM(p_p0, g_p0)
    SYM(p_d1, g_d1)       SYM(p_dinp, g_dinp)     SYM(p_gi, g_gi)
    SYM(p_l1, g_l1)       SYM(p_wsw_enc, g_wsw_enc) SYM(p_wsw_dec, g_wsw_dec)
    SYM(p_wtf, g_wtf)
#undef SYM

    float* w_p2l1   = p_wtf + WT_P2L1;
    float* w_p2l2   = p_wtf + WT_P2L2;
    float* w_encwih = p_wtf + WT_ENCWIH;
    float* w_l2s1   = p_wtf + WT_L2S1;
    float* w_decwih = p_wtf + WT_DECWIH;
    float* w_l2p1   = p_wtf + WT_L2P1;

    cudaFuncSetAttribute(gru_step, cudaFuncAttributeMaxDynamicSharedMemorySize,
                         RC_SMEM_BYTES);
    cudaFuncSetAttribute(gemm_tf32_v3, cudaFuncAttributeMaxDynamicSharedMemorySize,
                         GM_SMEM_BYTES);

    // ---- one-time weight preprocessing ----
    swizzle_whh<<<64, 256>>>(enc_whh, p_wsw_enc);
    swizzle_whh<<<64, 256>>>(dec_whh, p_wsw_dec);
    {
        auto cvt = [](const float* s, float* d, size_t n) {
            int n4 = (int)(n / 4);
            cvt_tf32_buf<<<(n4 + 255) / 256, 256>>>(s, d, n4);
        };
        cvt(p2l_w1, w_p2l1, 512 * 72);
        cvt(p2l_w2, w_p2l2, 1024 * 512);
        cvt(enc_wih, w_encwih, (size_t)3072 * 1024);
        cvt(l2s_w1, w_l2s1, 512 * 1024);
        cvt(dec_wih, w_decwih, (size_t)3072 * 1024);
        cvt(l2p_w1, w_l2p1, 512 * 1024);
    }

    // ---- par2lat(x) ----
    launch_gemm(x, D, w_p2l1, p2l_b1, p_buf1, HID, BT, HID, D, 1);
    launch_gemm(p_buf1, HID, w_p2l2, p2l_b2, p_latent, H, BT, H, HID, 1);

    // ---- xp = latent @ enc_wih^T + enc_bih, stored t-major [T, B, 3H] ----
    launch_gemm(p_latent, H, w_encwih, enc_bih, p_xp, H3, BT, H3, H, 0, 1);

    // ---- encoder recurrence: one fused launch per step (hF ping-pong) ----
    cudaMemsetAsync(p_hb0, 0, (size_t)B * H * sizeof(float));
    {
        float* hr = p_hb0;
        float* hw = p_hb1;
        for (int t = 0; t < T; t++) {
            gru_step<<<128, 512, RC_SMEM_BYTES>>>(
                p_wsw_enc, enc_bhh,
                p_xp + (size_t)t * B * H3, (size_t)H3,
                hr, hw,
                p_eout + (size_t)t * B * H, (size_t)H,
                nullptr);
            float* t2 = hr; hr = hw; hw = t2;
        }
    }

    // ---- attention pooling (rows in (t,b) order) ----
    launch_gemm(p_eout, H, w_l2s1, l2s_b1, p_buf1, HID, BT, HID, H, 1);
    logits_kernel<<<BT / 8, 256>>>(p_buf1, l2s_w2, l2s_b2, p_logits);
    softmax_kernel<<<B, T>>>(p_logits, p_wts);
    pool_kernel<<<B, 256>>>(p_eout, p_wts, p_hs, rep_out);

    // ---- autoregressive decode (hF ping-pong + row-major copy for GEMM) ----
    gather_last<<<(B * D + 255) / 256, 256>>>(x, p_p0);
    float* hF_read  = p_hs;
    float* hF_write = p_hs2;
    for (int s = 0; s < P; s++) {
        const float* pin = (s == 0) ? p_p0 : (out + (size_t)(s - 1) * D);
        int plda = (s == 0) ? D : (P * D);
        launch_gemm(pin, plda, w_p2l1, p2l_b1, p_d1, HID, B, HID, D, 1);
        launch_gemm(p_d1, HID, w_p2l2, p2l_b2, p_dinp, H, B, H, HID, 1);
        launch_gemm(p_dinp, H, w_decwih, dec_bih, p_gi, H3, B, H3, H, 0);
        gru_step<<<128, 512, RC_SMEM_BYTES>>>(
            p_wsw_dec, dec_bhh, p_gi, (size_t)H3,
            hF_read, hF_write, nullptr, 0, p_hrow);
        launch_gemm(p_hrow, H, w_l2p1, l2p_b1, p_l1, HID, B, HID, H, 1);
        pred_kernel<<<B, 128>>>(p_l1, l2p_w2, l2p_b2,
                                out + (size_t)s * D, P * D);
        float* t2 = hF_read; hF_read = hF_write; hF_write = t2;
    }
}

// round 12
// speedup vs baseline: 1.7071x; 1.0280x over previous
#include <cuda_runtime.h>
#include <mma.h>
#include <cstdint>

using namespace nvcuda;

// Problem constants (fixed by the reference)
constexpr int B   = 256;
constexpr int T   = 256;
constexpr int D   = 72;
constexpr int HID = 512;
constexpr int H   = 1024;
constexpr int H3  = 3 * H;
constexpr int P   = 10;       // to_predict
constexpr int BT  = B * T;    // 65536

// ----------------------------------------------------------------------------
// Device scratch
// ----------------------------------------------------------------------------
__device__ float g_buf1  [(size_t)BT * HID];
__device__ float g_latent[(size_t)BT * H];
__device__ float g_xp    [(size_t)BT * H3];   // [T, B, 3H] (t-major)
__device__ float g_eout  [(size_t)BT * H];    // [T, B, H]  (t-major)
__device__ float g_hb0   [B * H];             // hF fragment-order layout
__device__ float g_hb1   [B * H];
__device__ float g_logits[BT];                // index t*B + b
__device__ float g_lpart [4 * BT];            // fused-logits partials
__device__ float g_wts   [BT];
__device__ float g_hs    [B * H];             // hF layout (decode ping)
__device__ float g_hs2   [B * H];             // hF layout (decode pong)
__device__ float g_hrow  [B * H];             // row-major h for decode l2p GEMM
__device__ float g_p0    [B * D];
__device__ float g_d1    [B * HID];
__device__ float g_dinp  [B * H];
__device__ float g_gi    [B * H3];
__device__ float g_l1    [B * HID];
// Pre-swizzled (fragment-order, tf32) GRU weight slabs
constexpr int WSW_TILE = 128 * 6 * 64;        // 49152
__device__ float g_wsw_enc[(size_t)64 * WSW_TILE];
__device__ float g_wsw_dec[(size_t)64 * WSW_TILE];
// tf32-pre-rounded GEMM weights (same layout as inputs)
constexpr size_t WT_P2L1   = 0;                              // 512*72
constexpr size_t WT_P2L2   = WT_P2L1 + 512 * 72;             // 1024*512
constexpr size_t WT_ENCWIH = WT_P2L2 + 1024 * 512;           // 3072*1024
constexpr size_t WT_L2S1   = WT_ENCWIH + (size_t)3072 * 1024;// 512*1024
constexpr size_t WT_DECWIH = WT_L2S1 + 512 * 1024;           // 3072*1024
constexpr size_t WT_L2P1   = WT_DECWIH + (size_t)3072 * 1024;// 512*1024
constexpr size_t WT_TOTAL  = WT_L2P1 + 512 * 1024;
__device__ float g_wtf[WT_TOTAL];

__device__ __forceinline__ size_t hf_idx(int b, int k) {
    return ((((size_t)(k >> 3) * 16 + (b >> 4)) * 32 +
             ((b & 7) * 4 + (k & 3))) << 2) +
           (((b >> 3) & 1) + 2 * ((k >> 2) & 1));
}

// ----------------------------------------------------------------------------
// tf32 helpers
// ----------------------------------------------------------------------------
__device__ __forceinline__ float sigf(float x) { return 1.f / (1.f + expf(-x)); }

__device__ __forceinline__ uint32_t f2tf32(float x) {
    uint32_t r;
    asm("cvt.rna.tf32.f32 %0, %1;" : "=r"(r) : "f"(x));
    return r;
}

__device__ __forceinline__ void mma_tf32(float d[4], const uint32_t a[4],
                                         uint32_t b0, uint32_t b1) {
    asm volatile(
        "mma.sync.aligned.m16n8k8.row.col.f32.tf32.tf32.f32 "
        "{%0,%1,%2,%3}, {%4,%5,%6,%7}, {%8,%9}, {%0,%1,%2,%3};"
        : "+f"(d[0]), "+f"(d[1]), "+f"(d[2]), "+f"(d[3])
        : "r"(a[0]), "r"(a[1]), "r"(a[2]), "r"(a[3]), "r"(b0), "r"(b1));
}

__device__ __forceinline__ uint32_t smem_u32(const void* p) {
    return (uint32_t)__cvta_generic_to_shared(p);
}
__device__ __forceinline__ void cp16(uint32_t dst, const void* src) {
    asm volatile("cp.async.ca.shared.global [%0], [%1], 16;" :: "r"(dst), "l"(src));
}

// one-time tf32 rounding of a weight buffer (n multiple of 4)
__global__ void cvt_tf32_buf(const float* __restrict__ src,
                             float* __restrict__ dst, int n4)
{
    int i = blockIdx.x * blockDim.x + threadIdx.x;
    if (i >= n4) return;
    float4 v = reinterpret_cast<const float4*>(src)[i];
    v.x = __uint_as_float(f2tf32(v.x));
    v.y = __uint_as_float(f2tf32(v.y));
    v.z = __uint_as_float(f2tf32(v.z));
    v.w = __uint_as_float(f2tf32(v.w));
    reinterpret_cast<float4*>(dst)[i] = v;
}

// ----------------------------------------------------------------------------
// GEMM v3: cp.async 3-stage pipeline, pre-tf32 weights, fragment-cvt on A.
// Optional fused-logits mode: with lpart != nullptr, skips the C store and
// writes per-n-tile partial dots of act(C) with lw into lpart[(bn/128)*M + row].
// ----------------------------------------------------------------------------
#define BM 128
#define BN 128
#define BK 32
constexpr int GLDS = BK + 4;
constexpr int STG  = (BM + BN) * GLDS;
constexpr int GM_SMEM_BYTES = 3 * STG * 4;         // 110592 B

__device__ __forceinline__ void cp_stage(
    float* st, const float* __restrict__ A, int lda,
    const float* __restrict__ W, int K,
    int bm, int bn, int kk, int tid)
{
#pragma unroll
    for (int i = 0; i < 4; i++) {
        int idx = tid + i * 256;
        int r   = idx >> 3;
        int c4  = (idx & 7) * 4;
        int gk  = kk + c4;
        float* da = st + r * GLDS + c4;
        float* db = st + (BM + r) * GLDS + c4;
        const float* sa = A + (size_t)(bm + r) * lda + gk;
        const float* sb = W + (size_t)(bn + r) * K + gk;
        if (gk + 4 <= K) {
            cp16(smem_u32(da), sa);
            cp16(smem_u32(db), sb);
        } else {
            float4 va, vb;
            va.x = (gk + 0 < K) ? sa[0] : 0.f;  vb.x = (gk + 0 < K) ? sb[0] : 0.f;
            va.y = (gk + 1 < K) ? sa[1] : 0.f;  vb.y = (gk + 1 < K) ? sb[1] : 0.f;
            va.z = (gk + 2 < K) ? sa[2] : 0.f;  vb.z = (gk + 2 < K) ? sb[2] : 0.f;
            va.w = (gk + 3 < K) ? sa[3] : 0.f;  vb.w = (gk + 3 < K) ? sb[3] : 0.f;
            *reinterpret_cast<float4*>(da) = va;
            *reinterpret_cast<float4*>(db) = vb;
        }
    }
    asm volatile("cp.async.commit_group;");
}

__global__ void __launch_bounds__(256, 2)
gemm_tf32_v3(const float* __restrict__ A, int lda,
             const float* __restrict__ W,
             const float* __restrict__ bias,
             float* __restrict__ C, int ldc,
             int M, int N, int K, int act, int permute_bt,
             const float* __restrict__ lw, float* __restrict__ lpart)
{
    extern __shared__ float sm[];
    float* Cs = sm;

    const int bm  = blockIdx.y * BM;
    const int bn  = blockIdx.x * BN;
    const int tid = threadIdx.x;
    const int w   = tid >> 5;
    const int wm  = w & 3;
    const int wn  = w >> 2;

    wmma::fragment<wmma::accumulator, 16, 16, 8, float> c[2][4];
#pragma unroll
    for (int i = 0; i < 2; i++)
#pragma unroll
        for (int j = 0; j < 4; j++)
            wmma::fill_fragment(c[i][j], 0.0f);

    const int niter = (K + BK - 1) / BK;

    cp_stage(sm, A, lda, W, K, bm, bn, 0, tid);
    if (niter > 1) cp_stage(sm + STG, A, lda, W, K, bm, bn, BK, tid);

    for (int it = 0; it < niter; it++) {
        if (it + 1 < niter) asm volatile("cp.async.wait_group 1;");
        else                asm volatile("cp.async.wait_group 0;");
        __syncthreads();
        if (it + 2 < niter)
            cp_stage(sm + ((it + 2) % 3) * STG, A, lda, W, K, bm, bn,
                     (it + 2) * BK, tid);

        const float* As = sm + (it % 3) * STG;
        const float* Bs = As + BM * GLDS;
#pragma unroll
        for (int ks = 0; ks < 4; ks++) {
            wmma::fragment<wmma::matrix_a, 16, 16, 8, wmma::precision::tf32, wmma::row_major> af[2];
            wmma::fragment<wmma::matrix_b, 16, 16, 8, wmma::precision::tf32, wmma::col_major> bf[4];
#pragma unroll
            for (int i = 0; i < 2; i++) {
                wmma::load_matrix_sync(af[i], As + (wm * 32 + i * 16) * GLDS + ks * 8, GLDS);
#pragma unroll
                for (int e = 0; e < af[i].num_elements; e++)
                    af[i].x[e] = wmma::__float_to_tf32(af[i].x[e]);
            }
#pragma unroll
            for (int j = 0; j < 4; j++)
                wmma::load_matrix_sync(bf[j], Bs + (wn * 64 + j * 16) * GLDS + ks * 8, GLDS);
#pragma unroll
            for (int i = 0; i < 2; i++)
#pragma unroll
                for (int j = 0; j < 4; j++)
                    wmma::mma_sync(c[i][j], af[i], bf[j], c[i][j]);
        }
    }

    __syncthreads();
#pragma unroll
    for (int i = 0; i < 2; i++)
#pragma unroll
        for (int j = 0; j < 4; j++)
            wmma::store_matrix_sync(Cs + (wm * 32 + i * 16) * (BN + 4) + wn * 64 + j * 16,
                                    c[i][j], BN + 4, wmma::mem_row_major);
    __syncthreads();

#pragma unroll
    for (int i = 0; i < 16; i++) {
        int idx4 = tid + i * 256;
        int r    = idx4 >> 5;
        int c4   = (idx4 & 31) * 4;
        float4 v = *reinterpret_cast<const float4*>(Cs + r * (BN + 4) + c4);
        if (bias) {
            float4 bv = *reinterpret_cast<const float4*>(bias + bn + c4);
            v.x += bv.x; v.y += bv.y; v.z += bv.z; v.w += bv.w;
        }
        if (act == 1) {
            v.x = fmaxf(v.x, 0.f); v.y = fmaxf(v.y, 0.f);
            v.z = fmaxf(v.z, 0.f); v.w = fmaxf(v.w, 0.f);
        }
        int gr   = bm + r;
        int orow = permute_bt ? (((gr & 255) << 8) | (gr >> 8)) : gr;
        if (!lpart) {
            *reinterpret_cast<float4*>(C + (size_t)orow * ldc + bn + c4) = v;
        } else {
            // fused logits: dot row fragment with lw, warp-reduce (lanes cover
            // the full 128-col tile for this row), lane 0 writes the partial.
            float4 wv4 = *reinterpret_cast<const float4*>(lw + bn + c4);
            float d = v.x * wv4.x + v.y * wv4.y + v.z * wv4.z + v.w * wv4.w;
#pragma unroll
            for (int o = 16; o > 0; o >>= 1)
                d += __shfl_xor_sync(0xffffffffu, d, o);
            if ((tid & 31) == 0)
                lpart[(size_t)(bn >> 7) * M + orow] = d;
        }
    }
}

__global__ void logits_reduce(const float* __restrict__ lpart,
                              const float* __restrict__ b2,
                              float* __restrict__ logits)
{
    int i = blockIdx.x * blockDim.x + threadIdx.x;
    if (i >= BT) return;
    logits[i] = lpart[i] + lpart[BT + i] + lpart[2 * BT + i] +
                lpart[3 * BT + i] + b2[0];
}

// ----------------------------------------------------------------------------
// One-time Whh pre-swizzle into mma-fragment order (tf32). Unchanged.
// ----------------------------------------------------------------------------
__global__ void swizzle_whh(const float* __restrict__ whh, float* __restrict__ wsw)
{
    int nt = blockIdx.x;          // 0..63
    int n0 = nt * 16;
    for (int i = threadIdx.x; i < 128 * 6 * 32; i += blockDim.x) {
        int lane  = i & 31;
        int pos   = i >> 5;       // 0..767
        int kstep = pos / 6;
        int g2    = pos % 6;
        int g  = g2 >> 1;
        int nj = g2 & 1;
        int q = lane >> 2, t = lane & 3;
        const float* src = whh + (size_t)(g * H + n0 + nj * 8 + q) * H + kstep * 8 + t;
        float2 v;
        v.x = __uint_as_float(f2tf32(src[0]));
        v.y = __uint_as_float(f2tf32(src[4]));
        *reinterpret_cast<float2*>(wsw + (size_t)nt * WSW_TILE + (size_t)pos * 64 + lane * 2) = v;
    }
}

// ----------------------------------------------------------------------------
// Fused single GRU step v7: weights streamed DIRECTLY from L2-resident
// pre-swizzled global (no smem staging, no prologue barrier), 1-iter register
// prefetch on both operands. Smem = gate staging only (30 KB).
// ----------------------------------------------------------------------------
constexpr int RC_LDA     = 20;
constexpr int RC_GFLOATS = 3 * 128 * RC_LDA;      // 7680 floats
constexpr int RC_SMEM_BYTES = RC_GFLOATS * 4;     // 30720 B

__global__ void __launch_bounds__(512, 1)
gru_step(const float* __restrict__ wsw, const float* __restrict__ bhh,
         const float* __restrict__ gi, size_t gi_bstride,
         const float* __restrict__ hF_read, float* __restrict__ hF_write,
         float* __restrict__ eout_t, size_t eout_bstride,
         float* __restrict__ hrow_write)
{
    extern __shared__ float Gsm[];     // [3][128][20] gate staging

    const int tid  = threadIdx.x;
    const int lane = tid & 31;
    const int w    = tid >> 5;
    const int grp  = w >> 2;
    const int wm   = w & 3;
    const int nt   = blockIdx.x & 63;
    const int bt   = blockIdx.x >> 6;
    const int b0   = bt * 128;
    const int n0   = nt * 16;

    const float2* wg  = reinterpret_cast<const float2*>(wsw + (size_t)nt * WSW_TILE);
    const float4* hF4 = reinterpret_cast<const float4*>(hF_read);
    const int k8base  = grp * 32;
    const int mbb     = bt * 8 + wm * 2;

    float acc[2][3][2][4];
#pragma unroll
    for (int mh = 0; mh < 2; mh++)
#pragma unroll
        for (int g = 0; g < 3; g++)
#pragma unroll
            for (int nj = 0; nj < 2; nj++)
#pragma unroll
                for (int e = 0; e < 4; e++) acc[mh][g][nj][e] = 0.f;

    float4 pf[2];
    float2 wv[6];
#pragma unroll
    for (int mh = 0; mh < 2; mh++)
        pf[mh] = hF4[((size_t)k8base * 16 + mbb + mh) * 32 + lane];
#pragma unroll
    for (int j = 0; j < 6; j++)
        wv[j] = wg[((size_t)(k8base * 6) + j) * 32 + lane];

    for (int c = 0; c < 32; c++) {
        uint32_t A[2][4];
#pragma unroll
        for (int mh = 0; mh < 2; mh++) {
            A[mh][0] = f2tf32(pf[mh].x);
            A[mh][1] = f2tf32(pf[mh].y);
            A[mh][2] = f2tf32(pf[mh].z);
            A[mh][3] = f2tf32(pf[mh].w);
        }
        uint32_t bw0[6], bw1[6];
#pragma unroll
        for (int j = 0; j < 6; j++) {
            bw0[j] = __float_as_uint(wv[j].x);
            bw1[j] = __float_as_uint(wv[j].y);
        }

        if (c < 31) {
#pragma unroll
            for (int mh = 0; mh < 2; mh++)
                pf[mh] = hF4[((size_t)(k8base + c + 1) * 16 + mbb + mh) * 32 + lane];
#pragma unroll
            for (int j = 0; j < 6; j++)
                wv[j] = wg[((size_t)((k8base + c + 1) * 6) + j) * 32 + lane];
        }

#pragma unroll
        for (int g = 0; g < 3; g++) {
#pragma unroll
            for (int nj = 0; nj < 2; nj++) {
                int j = g * 2 + nj;
                mma_tf32(acc[0][g][nj], A[0], bw0[j], bw1[j]);
                mma_tf32(acc[1][g][nj], A[1], bw0[j], bw1[j]);
            }
        }
    }

    // ---- combine K-group partials (deterministic sequential passes) ----
    const int q = lane >> 2;
    const int t = lane & 3;
    const int ccol = 2 * t;
#pragma unroll
    for (int pass = 3; pass >= 0; pass--) {
        if (grp == pass) {
#pragma unroll
            for (int mh = 0; mh < 2; mh++)
#pragma unroll
                for (int g = 0; g < 3; g++)
#pragma unroll
                    for (int nj = 0; nj < 2; nj++) {
                        int row = wm * 32 + mh * 16 + q;
                        float* b0p = Gsm + (g * 128 + row) * RC_LDA + nj * 8 + ccol;
                        float* b1p = Gsm + (g * 128 + row + 8) * RC_LDA + nj * 8 + ccol;
                        if (pass == 3) {
                            b0p[0] = acc[mh][g][nj][0];
                            b0p[1] = acc[mh][g][nj][1];
                            b1p[0] = acc[mh][g][nj][2];
                            b1p[1] = acc[mh][g][nj][3];
                        } else {
                            b0p[0] += acc[mh][g][nj][0];
                            b0p[1] += acc[mh][g][nj][1];
                            b1p[0] += acc[mh][g][nj][2];
                            b1p[1] += acc[mh][g][nj][3];
                        }
                    }
        }
        __syncthreads();
    }

    // ---- fused gate math: one hF float4 per thread ----
    {
        const int k8l  = tid >> 8;
        const int mbl  = (tid >> 5) & 7;
        const int ln   = tid & 31;
        const int bq   = ln >> 2;
        const int nq   = ln & 3;
        const size_t fidx = ((size_t)(nt * 2 + k8l) * 16 + (bt * 8 + mbl)) * 32 + ln;

        float4 hv4 = hF4[fidx];
        float outv[4];
#pragma unroll
        for (int kh = 0; kh < 2; kh++) {
#pragma unroll
            for (int rh = 0; rh < 2; rh++) {
                int reg = rh + 2 * kh;
                int bl  = mbl * 16 + bq + 8 * rh;
                int nl  = k8l * 8 + nq + 4 * kh;
                int b   = b0 + bl;
                int nc  = n0 + nl;
                float hr = Gsm[(0 * 128 + bl) * RC_LDA + nl] + bhh[nc];
                float hz = Gsm[(1 * 128 + bl) * RC_LDA + nl] + bhh[H + nc];
                float hn = Gsm[(2 * 128 + bl) * RC_LDA + nl] + bhh[2 * H + nc];
                const float* gib = gi + (size_t)b * gi_bstride;
                float ir = gib[nc], iz = gib[H + nc], in_ = gib[2 * H + nc];
                float r  = sigf(ir + hr);
                float z  = sigf(iz + hz);
                float nn = tanhf(in_ + r * hn);
                float hv = (&hv4.x)[reg];
                float hnew = (1.f - z) * nn + z * hv;
                outv[reg] = hnew;
                if (eout_t) eout_t[(size_t)b * eout_bstride + nc] = hnew;
                if (hrow_write) hrow_write[(size_t)b * H + nc] = hnew;
            }
        }
        float4 o4 = make_float4(outv[0], outv[1], outv[2], outv[3]);
        reinterpret_cast<float4*>(hF_write)[fidx] = o4;
    }
}

// ----------------------------------------------------------------------------
// Small kernels
// ----------------------------------------------------------------------------
__global__ void softmax_kernel(const float* __restrict__ logits,
                               float* __restrict__ wts)
{
    __shared__ float sdata[T];
    int b = blockIdx.x, t = threadIdx.x;
    float v = logits[t * B + b];
    sdata[t] = v;
    __syncthreads();
    for (int s = T / 2; s > 0; s >>= 1) {
        if (t < s) sdata[t] = fmaxf(sdata[t], sdata[t + s]);
        __syncthreads();
    }
    float mx = sdata[0];
    __syncthreads();
    float e = expf(v - mx);
    sdata[t] = e;
    __syncthreads();
    for (int s = T / 2; s > 0; s >>= 1) {
        if (t < s) sdata[t] += sdata[t + s];
        __syncthreads();
    }
    wts[t * B + b] = e / sdata[0];
}

__global__ void pool_kernel(const float* __restrict__ eout,
                            const float* __restrict__ wts,
                            float* __restrict__ hsF,
                            float* __restrict__ rep_out)
{
    __shared__ float w[T];
    int b = blockIdx.x, tid = threadIdx.x;
    w[tid] = wts[tid * B + b];
    __syncthreads();
    for (int h0 = tid; h0 < H; h0 += blockDim.x) {
        const float* base = eout + (size_t)b * H + h0;
        float acc = 0.f;
#pragma unroll 4
        for (int t = 0; t < T; t++) acc += w[t] * base[(size_t)t * B * H];
        hsF[hf_idx(b, h0)] = acc;
        if (rep_out) rep_out[b * H + h0] = acc;
    }
}

__global__ void gather_last(const float* __restrict__ x, float* __restrict__ p0)
{
    int idx = blockIdx.x * blockDim.x + threadIdx.x;
    if (idx >= B * D) return;
    int b = idx / D, dd = idx % D;
    p0[idx] = x[((size_t)b * T + (T - 1)) * D + dd];
}

__global__ void pred_kernel(const float* __restrict__ l1,
                            const float* __restrict__ w,
                            const float* __restrict__ bias,
                            float* __restrict__ out, int ldc)
{
    __shared__ float row[HID];
    int m = blockIdx.x;
    for (int k = threadIdx.x; k < HID; k += blockDim.x)
        row[k] = l1[(size_t)m * HID + k];
    __syncthreads();
    int n = threadIdx.x;
    if (n < D) {
        const float* wr = w + (size_t)n * HID;
        float acc = bias[n];
        for (int k = 0; k < HID; k++) acc += row[k] * wr[k];
        out[(size_t)m * ldc + n] = acc;
    }
}

// ----------------------------------------------------------------------------
// Host driver
// ----------------------------------------------------------------------------
static inline void launch_gemm(const float* A, int lda, const float* W,
                               const float* bias, float* C, int ldc,
                               int M, int N, int K, int act, int permute_bt = 0,
                               const float* lw = nullptr, float* lpart = nullptr)
{
    dim3 grid(N / BN, M / BM);
    gemm_tf32_v3<<<grid, 256, GM_SMEM_BYTES>>>(A, lda, W, bias, C, ldc, M, N, K,
                                               act, permute_bt, lw, lpart);
}

extern "C" void kernel_launch(void* const* d_in, const int* in_sizes, int n_in,
                              void* d_out, int out_size)
{
    const float* x       = (const float*)d_in[0];
    const float* p2l_w1  = (const float*)d_in[2];
    const float* p2l_b1  = (const float*)d_in[3];
    const float* p2l_w2  = (const float*)d_in[4];
    const float* p2l_b2  = (const float*)d_in[5];
    const float* enc_wih = (const float*)d_in[6];
    const float* enc_whh = (const float*)d_in[7];
    const float* enc_bih = (const float*)d_in[8];
    const float* enc_bhh = (const float*)d_in[9];
    const float* dec_wih = (const float*)d_in[10];
    const float* dec_whh = (const float*)d_in[11];
    const float* dec_bih = (const float*)d_in[12];
    const float* dec_bhh = (const float*)d_in[13];
    const float* l2p_w1  = (const float*)d_in[14];
    const float* l2p_b1  = (const float*)d_in[15];
    const float* l2p_w2  = (const float*)d_in[16];
    const float* l2p_b2  = (const float*)d_in[17];
    const float* l2s_w1  = (const float*)d_in[18];
    const float* l2s_b1  = (const float*)d_in[19];
    const float* l2s_w2  = (const float*)d_in[20];
    const float* l2s_b2  = (const float*)d_in[21];

    float* out = (float*)d_out;
    const int PREDS = B * P * D;
    float* rep_out = (out_size >= PREDS + B * H) ? (out + PREDS) : nullptr;

    float *p_buf1, *p_latent, *p_xp, *p_eout, *p_hb0, *p_hb1, *p_logits,
          *p_lpart, *p_wts, *p_hs, *p_hs2, *p_hrow, *p_p0, *p_d1, *p_dinp,
          *p_gi, *p_l1, *p_wsw_enc, *p_wsw_dec, *p_wtf;
    void* tmp;
#define SYM(dst, sym) cudaGetSymbolAddress(&tmp, sym); dst = (decltype(dst))tmp;
    SYM(p_buf1, g_buf1)   SYM(p_latent, g_latent) SYM(p_xp, g_xp)
    SYM(p_eout, g_eout)   SYM(p_hb0, g_hb0)       SYM(p_hb1, g_hb1)
    SYM(p_logits, g_logits) SYM(p_lpart, g_lpart) SYM(p_wts, g_wts)
    SYM(p_hs, g_hs)       SYM(p_hs2, g_hs2)       SYM(p_hrow, g_hrow)
    SYM(p_p0, g_p0)       SYM(p_d1, g_d1)         SYM(p_dinp, g_dinp)
    SYM(p_gi, g_gi)       SYM(p_l1, g_l1)         SYM(p_wsw_enc, g_wsw_enc)
    SYM(p_wsw_dec, g_wsw_dec) SYM(p_wtf, g_wtf)
#undef SYM

    float* w_p2l1   = p_wtf + WT_P2L1;
    float* w_p2l2   = p_wtf + WT_P2L2;
    float* w_encwih = p_wtf + WT_ENCWIH;
    float* w_l2s1   = p_wtf + WT_L2S1;
    float* w_decwih = p_wtf + WT_DECWIH;
    float* w_l2p1   = p_wtf + WT_L2P1;

    cudaFuncSetAttribute(gru_step, cudaFuncAttributeMaxDynamicSharedMemorySize,
                         RC_SMEM_BYTES);
    cudaFuncSetAttribute(gemm_tf32_v3, cudaFuncAttributeMaxDynamicSharedMemorySize,
                         GM_SMEM_BYTES);

    // ---- one-time weight preprocessing ----
    swizzle_whh<<<64, 256>>>(enc_whh, p_wsw_enc);
    swizzle_whh<<<64, 256>>>(dec_whh, p_wsw_dec);
    {
        auto cvt = [](const float* s, float* d, size_t n) {
            int n4 = (int)(n / 4);
            cvt_tf32_buf<<<(n4 + 255) / 256, 256>>>(s, d, n4);
        };
        cvt(p2l_w1, w_p2l1, 512 * 72);
        cvt(p2l_w2, w_p2l2, 1024 * 512);
        cvt(enc_wih, w_encwih, (size_t)3072 * 1024);
        cvt(l2s_w1, w_l2s1, 512 * 1024);
        cvt(dec_wih, w_decwih, (size_t)3072 * 1024);
        cvt(l2p_w1, w_l2p1, 512 * 1024);
    }

    // ---- par2lat(x) ----
    launch_gemm(x, D, w_p2l1, p2l_b1, p_buf1, HID, BT, HID, D, 1);
    launch_gemm(p_buf1, HID, w_p2l2, p2l_b2, p_latent, H, BT, H, HID, 1);

    // ---- xp = latent @ enc_wih^T + enc_bih, stored t-major [T, B, 3H] ----
    launch_gemm(p_latent, H, w_encwih, enc_bih, p_xp, H3, BT, H3, H, 0, 1);

    // ---- encoder recurrence: one fused launch per step (hF ping-pong) ----
    cudaMemsetAsync(p_hb0, 0, (size_t)B * H * sizeof(float));
    {
        float* hr = p_hb0;
        float* hw = p_hb1;
        for (int t = 0; t < T; t++) {
            gru_step<<<128, 512, RC_SMEM_BYTES>>>(
                p_wsw_enc, enc_bhh,
                p_xp + (size_t)t * B * H3, (size_t)H3,
                hr, hw,
                p_eout + (size_t)t * B * H, (size_t)H,
                nullptr);
            float* t2 = hr; hr = hw; hw = t2;
        }
    }

    // ---- attention pooling: fused s1-GEMM + logits dot ----
    launch_gemm(p_eout, H, w_l2s1, l2s_b1, nullptr, HID, BT, HID, H, 1, 0,
                l2s_w2, p_lpart);
    logits_reduce<<<BT / 256, 256>>>(p_lpart, l2s_b2, p_logits);
    softmax_kernel<<<B, T>>>(p_logits, p_wts);
    pool_kernel<<<B, 256>>>(p_eout, p_wts, p_hs, rep_out);

    // ---- autoregressive decode (hF ping-pong + row-major copy for GEMM) ----
    gather_last<<<(B * D + 255) / 256, 256>>>(x, p_p0);
    float* hF_read  = p_hs;
    float* hF_write = p_hs2;
    for (int s = 0; s < P; s++) {
        const float* pin = (s == 0) ? p_p0 : (out + (size_t)(s - 1) * D);
        int plda = (s == 0) ? D : (P * D);
        launch_gemm(pin, plda, w_p2l1, p2l_b1, p_d1, HID, B, HID, D, 1);
        launch_gemm(p_d1, HID, w_p2l2, p2l_b2, p_dinp, H, B, H, HID, 1);
        launch_gemm(p_dinp, H, w_decwih, dec_bih, p_gi, H3, B, H3, H, 0);
        gru_step<<<128, 512, RC_SMEM_BYTES>>>(
            p_wsw_dec, dec_bhh, p_gi, (size_t)H3,
            hF_read, hF_write, nullptr, 0, p_hrow);
        launch_gemm(p_hrow, H, w_l2p1, l2p_b1, p_l1, HID, B, HID, H, 1);
        pred_kernel<<<B, 128>>>(p_l1, l2p_w2, l2p_b2,
                                out + (size_t)s * D, P * D);
        float* t2 = hF_read; hF_read = hF_write; hF_write = t2;
    }
}